// round 6
// baseline (speedup 1.0000x reference)
#include <cuda_runtime.h>
#include <cuda_bf16.h>
#include <cstdint>

// ---------------------------------------------------------------------------
// Problem constants
// ---------------------------------------------------------------------------
#define BS_ROWS 4096      // B*S
#define NHEAD   8
#define DIM     64        // d == D_head
#define NLAND   2048      // landmarks per head
#define DOUT    512
#define EPS_C   1e-12f

// ---------------------------------------------------------------------------
// Device-global scratch (no allocation allowed)
// ---------------------------------------------------------------------------
__device__ float g_R2[NHEAD * NLAND];
__device__ float g_qa[NHEAD * NLAND];
__device__ __nv_bfloat16 g_RH[NHEAD * NLAND * DIM];     // R hi  [h][n][d]
__device__ __nv_bfloat16 g_RL[NHEAD * NLAND * DIM];     // R lo
__device__ __nv_bfloat16 g_WH[NHEAD * DIM * NLAND];     // W^T hi [h][dh][n]
__device__ __nv_bfloat16 g_WL[NHEAD * DIM * NLAND];     // W^T lo
__device__ __nv_bfloat16 g_YH[BS_ROWS * DOUT];          // y hi [row][col]
__device__ __nv_bfloat16 g_YL[BS_ROWS * DOUT];          // y lo
__device__ __nv_bfloat16 g_WOH[DOUT * DOUT];            // W_O^T hi [col][k]
__device__ __nv_bfloat16 g_WOL[DOUT * DOUT];            // W_O^T lo

// ---------------------------------------------------------------------------
// PTX helpers (sm_80-era, valid on sm_100 base)
// ---------------------------------------------------------------------------
__device__ __forceinline__ uint32_t smem_u32(const void* p) {
    return (uint32_t)__cvta_generic_to_shared(p);
}

__device__ __forceinline__ void cp16(uint32_t s, const void* g) {
    asm volatile("cp.async.cg.shared.global [%0], [%1], 16;" :: "r"(s), "l"(g));
}
#define CP_COMMIT() asm volatile("cp.async.commit_group;" ::: "memory")
#define CP_WAIT1()  asm volatile("cp.async.wait_group 1;" ::: "memory")
#define CP_WAIT0()  asm volatile("cp.async.wait_group 0;" ::: "memory")

__device__ __forceinline__ void ldm_x4(uint32_t* f, uint32_t addr) {
    asm volatile("ldmatrix.sync.aligned.m8n8.x4.shared.b16 {%0,%1,%2,%3}, [%4];"
        : "=r"(f[0]), "=r"(f[1]), "=r"(f[2]), "=r"(f[3]) : "r"(addr));
}

__device__ __forceinline__ void mma_bf16(float* c, const uint32_t* a,
                                         uint32_t b0, uint32_t b1) {
    asm volatile(
        "mma.sync.aligned.m16n8k16.row.col.f32.bf16.bf16.f32 "
        "{%0,%1,%2,%3}, {%4,%5,%6,%7}, {%8,%9}, {%0,%1,%2,%3};"
        : "+f"(c[0]), "+f"(c[1]), "+f"(c[2]), "+f"(c[3])
        : "r"(a[0]), "r"(a[1]), "r"(a[2]), "r"(a[3]), "r"(b0), "r"(b1));
}

// (f32,f32) -> packed bf16x2 hi + lo (residual)
__device__ __forceinline__ void split_pack(float e0, float e1,
                                           uint32_t& hi, uint32_t& lo)
{
    __nv_bfloat162 h2 = __float22bfloat162_rn(make_float2(e0, e1));
    float r0 = e0 - __bfloat162float(h2.x);
    float r1 = e1 - __bfloat162float(h2.y);
    __nv_bfloat162 l2 = __float22bfloat162_rn(make_float2(r0, r1));
    hi = *reinterpret_cast<uint32_t*>(&h2);
    lo = *reinterpret_cast<uint32_t*>(&l2);
}

// ---------------------------------------------------------------------------
// Fused-kernel SMEM layout
// ---------------------------------------------------------------------------
#define SR_B     144u
#define SW_B     272u
#define OFF_RH   0u
#define OFF_RL   18432u
#define OFF_WH   36864u
#define OFF_WL   54272u
#define OFF_R2   71680u
#define OFF_QA   72192u
#define BUF_B    72704u
// persistent Z hi/lo stage + reduction scratch beyond the two buffers
#define ZH_OFF   145408u     // [128 rows][64 k] halves, stride 144 B
#define ZL_OFF   163840u
#define Z2_OFF   182272u     // float[128]
#define P1_OFF   182784u     // float[2][128]
#define P2_OFF   183808u     // float[2][128]
#define SMEM_BYTES 184832u
// y-exchange buffer aliased onto tile buffers after mainloop: [128][66] fp32

// ---------------------------------------------------------------------------
// Prep 1: per-landmark R2, qa, bf16 hi/lo split of R. warp per landmark.
// ---------------------------------------------------------------------------
__global__ void __launch_bounds__(256)
prep_land(const float* __restrict__ R, const float* __restrict__ q)
{
    int wid  = threadIdx.x >> 5, lane = threadIdx.x & 31;
    int idx  = blockIdx.x * 8 + wid;            // h*NLAND + n
    const float* r = R + (size_t)idx * DIM;
    float v0 = r[lane], v1 = r[lane + 32];
    __nv_bfloat16 h0 = __float2bfloat16_rn(v0);
    __nv_bfloat16 h1 = __float2bfloat16_rn(v1);
    g_RH[(size_t)idx * DIM + lane]      = h0;
    g_RH[(size_t)idx * DIM + lane + 32] = h1;
    g_RL[(size_t)idx * DIM + lane]      = __float2bfloat16_rn(v0 - __bfloat162float(h0));
    g_RL[(size_t)idx * DIM + lane + 32] = __float2bfloat16_rn(v1 - __bfloat162float(h1));
    float s = v0 * v0 + v1 * v1;
    #pragma unroll
    for (int m = 16; m >= 1; m >>= 1) s += __shfl_xor_sync(0xffffffffu, s, m);
    if (lane == 0) {
        g_R2[idx] = s;
        float qq = q[idx];
        qq = (qq > 0.f ? qq : 0.f) + EPS_C;
        g_qa[idx] = rsqrtf(qq);
    }
}

// ---------------------------------------------------------------------------
// Prep 2: W^T bf16 hi/lo [h][dh][n] via SMEM transpose
// ---------------------------------------------------------------------------
__global__ void __launch_bounds__(256)
prep_w(const float* __restrict__ W)
{
    __shared__ float sm[64][65];
    int h  = blockIdx.x >> 5;
    int n0 = (blockIdx.x & 31) * 64;
    for (int t = threadIdx.x; t < 4096; t += 256) {
        int i = t >> 6, d = t & 63;
        sm[i][d] = W[((size_t)(h * NLAND + n0 + i)) * DIM + d];
    }
    __syncthreads();
    for (int t = threadIdx.x; t < 4096; t += 256) {
        int d = t >> 6, i = t & 63;
        float v = sm[i][d];
        __nv_bfloat16 hh = __float2bfloat16_rn(v);
        size_t o = ((size_t)h * DIM + d) * NLAND + n0 + i;
        g_WH[o] = hh;
        g_WL[o] = __float2bfloat16_rn(v - __bfloat162float(hh));
    }
}

// ---------------------------------------------------------------------------
// Prep 3: W_O^T bf16 hi/lo [col][k] via SMEM transpose (512x512)
// ---------------------------------------------------------------------------
__global__ void __launch_bounds__(256)
prep_wo(const float* __restrict__ WO)
{
    __shared__ float sm[64][65];
    int kb = blockIdx.x >> 3;
    int cb = blockIdx.x & 7;
    int k0 = kb * 64, c0 = cb * 64;
    for (int t = threadIdx.x; t < 4096; t += 256) {
        int i = t >> 6, d = t & 63;
        sm[i][d] = WO[(size_t)(k0 + i) * DOUT + c0 + d];
    }
    __syncthreads();
    for (int t = threadIdx.x; t < 4096; t += 256) {
        int d = t >> 6, i = t & 63;
        float v = sm[i][d];
        __nv_bfloat16 hh = __float2bfloat16_rn(v);
        size_t o = (size_t)(c0 + d) * DOUT + k0 + i;
        g_WOH[o] = hh;
        g_WOL[o] = __float2bfloat16_rn(v - __bfloat162float(hh));
    }
}

// ---------------------------------------------------------------------------
// Fused kernel: one CTA per (head, 128-row block), 512 threads (16 warps).
// warp = (rg = warp>>1: 16-row group, ch = warp&1: 64-landmark half).
// ---------------------------------------------------------------------------
__device__ __forceinline__ void issue_tile_loads(char* smem, int buf, int h, int n0,
                                                 int tid)
{
    uint32_t sb = smem_u32(smem) + (uint32_t)buf * BUF_B;
    const __nv_bfloat16* rh = g_RH + ((size_t)h * NLAND + n0) * DIM;
    const __nv_bfloat16* rl = g_RL + ((size_t)h * NLAND + n0) * DIM;
    #pragma unroll
    for (int i = tid; i < 1024; i += 512) {
        int row = i >> 3, u = i & 7;
        cp16(sb + OFF_RH + row * SR_B + u * 16, rh + row * DIM + u * 8);
        cp16(sb + OFF_RL + row * SR_B + u * 16, rl + row * DIM + u * 8);
    }
    const __nv_bfloat16* wh = g_WH + (size_t)h * DIM * NLAND + n0;
    const __nv_bfloat16* wl = g_WL + (size_t)h * DIM * NLAND + n0;
    #pragma unroll
    for (int i = tid; i < 1024; i += 512) {
        int row = i >> 4, u = i & 15;
        cp16(sb + OFF_WH + row * SW_B + u * 16, wh + (size_t)row * NLAND + u * 8);
        cp16(sb + OFF_WL + row * SW_B + u * 16, wl + (size_t)row * NLAND + u * 8);
    }
    if (tid < 32) {
        cp16(sb + OFF_R2 + tid * 16, g_R2 + h * NLAND + n0 + tid * 4);
        cp16(sb + OFF_QA + tid * 16, g_qa + h * NLAND + n0 + tid * 4);
    }
}

__global__ void __launch_bounds__(512, 1)
fused_mma(const float* __restrict__ z)
{
    extern __shared__ __align__(16) char smem[];
    const int tid  = threadIdx.x;
    const int warp = tid >> 5;
    const int lane = tid & 31;
    const int rg   = warp >> 1;          // row group 0..7 (16 rows each)
    const int ch   = warp & 1;           // landmark half 0/1 (64 cols)
    const int h    = blockIdx.y;
    const int row0 = blockIdx.x * 128;
    const int g    = lane >> 2;          // 0..7
    const int t4   = lane & 3;           // 0..3
    const int wrow = rg * 16;
    const uint32_t sbase = smem_u32(smem);

    const int n_add = ((lane >> 4) & 1) * 8 + (lane & 7);
    const int k_add = ((lane >> 3) & 1) * 8;
    const uint32_t laneR = (uint32_t)(n_add * SR_B + k_add * 2);
    const uint32_t laneW = (uint32_t)(n_add * SW_B + k_add * 2);

    // ---- prologue: kick cp.async for tile 0 into buf 0 ----
    issue_tile_loads(smem, 0, h, 0, tid);
    CP_COMMIT();

    // ---- stage z rows as bf16 hi/lo into persistent SMEM (ldmatrix layout) ----
    {
        #pragma unroll
        for (int i = tid; i < 4096; i += 512) {       // 128 rows x 32 pairs
            int r = i >> 5, p = i & 31;
            float2 v = *reinterpret_cast<const float2*>(
                z + ((size_t)(row0 + r) * NHEAD + h) * DIM + 2 * p);
            uint32_t hi, lo;
            split_pack(v.x, v.y, hi, lo);
            *reinterpret_cast<uint32_t*>(smem + ZH_OFF + r * SR_B + p * 4) = hi;
            *reinterpret_cast<uint32_t*>(smem + ZL_OFF + r * SR_B + p * 4) = lo;
        }
        if (tid < 128) {                              // fp32 row norms
            const float* zr = z + ((size_t)(row0 + tid) * NHEAD + h) * DIM;
            float s = 0.f;
            #pragma unroll 16
            for (int k = 0; k < DIM; k++) s += zr[k] * zr[k];
            *reinterpret_cast<float*>(smem + Z2_OFF + tid * 4) = s;
        }
    }
    __syncthreads();

    const int r0 = wrow + g, r1 = r0 + 8;             // this thread's 2 rows
    const float z2a = *reinterpret_cast<const float*>(smem + Z2_OFF + r0 * 4);
    const float z2b = *reinterpret_cast<const float*>(smem + Z2_OFF + r1 * 4);

    // A-frag ldmatrix base for Z (persistent)
    const uint32_t zHa = sbase + ZH_OFF + (uint32_t)(wrow + n_add) * SR_B + k_add * 2;
    const uint32_t zLa = sbase + ZL_OFF + (uint32_t)(wrow + n_add) * SR_B + k_add * 2;

    float y[8][4];
    #pragma unroll
    for (int nt = 0; nt < 8; nt++)
        #pragma unroll
        for (int e = 0; e < 4; e++) y[nt][e] = 0.f;

    float p1a = 0.f, p1b = 0.f, p2a = 0.f, p2b = 0.f;

    for (int t = 0; t < 16; t++) {
        const int cur = t & 1;
        if (t < 15) {
            issue_tile_loads(smem, cur ^ 1, h, (t + 1) * 128, tid);
            CP_COMMIT();
            CP_WAIT1();
        } else {
            CP_WAIT0();
        }
        __syncthreads();

        const uint32_t sb  = sbase + (uint32_t)cur * BUF_B;
        const uint32_t rbH = sb + OFF_RH + (uint32_t)(ch * 64) * SR_B + laneR;
        const uint32_t rbL = sb + OFF_RL + (uint32_t)(ch * 64) * SR_B + laneR;
        const float* r2p = (const float*)(smem + cur * BUF_B + OFF_R2) + ch * 64;
        const float* qap = (const float*)(smem + cur * BUF_B + OFF_QA) + ch * 64;

        // ---- GEMM1: 16 rows x 64 landmark cols ----
        float c[8][4];
        #pragma unroll
        for (int nt = 0; nt < 8; nt++)
            #pragma unroll
            for (int e = 0; e < 4; e++) c[nt][e] = 0.f;

        #pragma unroll
        for (int kc = 0; kc < 4; kc++) {
            uint32_t ta[4], tb[4];
            ldm_x4(ta, zHa + kc * 32);
            ldm_x4(tb, zLa + kc * 32);
            uint32_t azh[4] = {ta[0], ta[2], ta[1], ta[3]};
            uint32_t azl[4] = {tb[0], tb[2], tb[1], tb[3]};
            #pragma unroll
            for (int ntp = 0; ntp < 4; ntp++) {
                uint32_t off = (uint32_t)(ntp * 16) * SR_B + (uint32_t)kc * 32;
                uint32_t rh[4], rl[4];
                ldm_x4(rh, rbH + off);
                ldm_x4(rl, rbL + off);
                mma_bf16(c[2 * ntp],     azh, rh[0], rh[1]);
                mma_bf16(c[2 * ntp],     azh, rl[0], rl[1]);
                mma_bf16(c[2 * ntp],     azl, rh[0], rh[1]);
                mma_bf16(c[2 * ntp + 1], azh, rh[2], rh[3]);
                mma_bf16(c[2 * ntp + 1], azh, rl[2], rl[3]);
                mma_bf16(c[2 * ntp + 1], azl, rh[2], rh[3]);
            }
        }

        // ---- epilogue + GEMM2 interleaved (k = this warp's 64 landmarks) ----
        const uint32_t wbH = sb + OFF_WH + laneW + (uint32_t)(ch * 128);
        const uint32_t wbL = sb + OFF_WL + laneW + (uint32_t)(ch * 128);
        #pragma unroll
        for (int kch = 0; kch < 4; kch++) {
            const int ct0 = 2 * kch, ct1 = 2 * kch + 1;
            const int col0 = ct0 * 8 + 2 * t4;
            const int col1 = ct1 * 8 + 2 * t4;
            float r2_0 = r2p[col0], r2_1 = r2p[col0 + 1];
            float r2_2 = r2p[col1], r2_3 = r2p[col1 + 1];
            float qa_0 = qap[col0], qa_1 = qap[col0 + 1];
            float qa_2 = qap[col1], qa_3 = qap[col1 + 1];

            float K00 = __expf(-0.5f * fmaxf(fmaf(-2.f, c[ct0][0], z2a) + r2_0, 0.f));
            float K01 = __expf(-0.5f * fmaxf(fmaf(-2.f, c[ct0][1], z2a) + r2_1, 0.f));
            float K02 = __expf(-0.5f * fmaxf(fmaf(-2.f, c[ct0][2], z2b) + r2_0, 0.f));
            float K03 = __expf(-0.5f * fmaxf(fmaf(-2.f, c[ct0][3], z2b) + r2_1, 0.f));
            float K10 = __expf(-0.5f * fmaxf(fmaf(-2.f, c[ct1][0], z2a) + r2_2, 0.f));
            float K11 = __expf(-0.5f * fmaxf(fmaf(-2.f, c[ct1][1], z2a) + r2_3, 0.f));
            float K12 = __expf(-0.5f * fmaxf(fmaf(-2.f, c[ct1][2], z2b) + r2_2, 0.f));
            float K13 = __expf(-0.5f * fmaxf(fmaf(-2.f, c[ct1][3], z2b) + r2_3, 0.f));

            p1a += K00 + K01 + K10 + K11;
            p1b += K02 + K03 + K12 + K13;

            float kt00 = K00 * qa_0, kt01 = K01 * qa_1;
            float kt02 = K02 * qa_0, kt03 = K03 * qa_1;
            float kt10 = K10 * qa_2, kt11 = K11 * qa_3;
            float kt12 = K12 * qa_2, kt13 = K13 * qa_3;

            p2a += kt00 + kt01 + kt10 + kt11;
            p2b += kt02 + kt03 + kt12 + kt13;

            uint32_t ah[4], al[4];
            split_pack(kt00, kt01, ah[0], al[0]);
            split_pack(kt02, kt03, ah[1], al[1]);
            split_pack(kt10, kt11, ah[2], al[2]);
            split_pack(kt12, kt13, ah[3], al[3]);

            #pragma unroll
            for (int ntp = 0; ntp < 4; ntp++) {
                uint32_t off = (uint32_t)(ntp * 16) * SW_B + (uint32_t)kch * 32;
                uint32_t wh[4], wl[4];
                ldm_x4(wh, wbH + off);
                ldm_x4(wl, wbL + off);
                mma_bf16(y[2 * ntp],     ah, wh[0], wh[1]);
                mma_bf16(y[2 * ntp],     ah, wl[0], wl[1]);
                mma_bf16(y[2 * ntp],     al, wh[0], wh[1]);
                mma_bf16(y[2 * ntp + 1], ah, wh[2], wh[3]);
                mma_bf16(y[2 * ntp + 1], ah, wl[2], wl[3]);
                mma_bf16(y[2 * ntp + 1], al, wh[2], wh[3]);
            }
        }
        __syncthreads();
    }

    // ---- cross-lane row sums within this warp's half ----
    #pragma unroll
    for (int m = 1; m <= 2; m <<= 1) {
        p1a += __shfl_xor_sync(0xffffffffu, p1a, m);
        p1b += __shfl_xor_sync(0xffffffffu, p1b, m);
        p2a += __shfl_xor_sync(0xffffffffu, p2a, m);
        p2b += __shfl_xor_sync(0xffffffffu, p2b, m);
    }
    float* p1s = (float*)(smem + P1_OFF);
    float* p2s = (float*)(smem + P2_OFF);
    if (t4 == 0) {
        p1s[ch * 128 + r0] = p1a;  p1s[ch * 128 + r1] = p1b;
        p2s[ch * 128 + r0] = p2a;  p2s[ch * 128 + r1] = p2b;
    }

    // ---- y partial exchange: half-1 warps dump to SMEM (aliased tile bufs) ----
    float* yx = (float*)smem;                         // [128][66] fp32
    if (ch == 1) {
        #pragma unroll
        for (int nt = 0; nt < 8; nt++) {
            int col = nt * 8 + 2 * t4;
            yx[r0 * 66 + col]     = y[nt][0];
            yx[r0 * 66 + col + 1] = y[nt][1];
            yx[r1 * 66 + col]     = y[nt][2];
            yx[r1 * 66 + col + 1] = y[nt][3];
        }
    }
    __syncthreads();

    // ---- half-0 warps combine, scale, write bf16 hi/lo y ----
    if (ch == 0) {
        float P1a = p1s[r0] + p1s[128 + r0];
        float P1b = p1s[r1] + p1s[128 + r1];
        float P2a = p2s[r0] + p2s[128 + r0];
        float P2b = p2s[r1] + p2s[128 + r1];
        float cc0 = rsqrtf(fmaxf(P1a, EPS_C));
        float cc1 = rsqrtf(fmaxf(P1b, EPS_C));
        float sc0 = cc0 / fmaxf(cc0 * P2a, EPS_C);
        float sc1 = cc1 / fmaxf(cc1 * P2b, EPS_C);

        size_t o0 = (size_t)(row0 + r0) * DOUT + h * DIM + 2 * t4;
        size_t o1 = (size_t)(row0 + r1) * DOUT + h * DIM + 2 * t4;
        #pragma unroll
        for (int nt = 0; nt < 8; nt++) {
            int col = nt * 8 + 2 * t4;
            float v0 = (y[nt][0] + yx[r0 * 66 + col])     * sc0;
            float v1 = (y[nt][1] + yx[r0 * 66 + col + 1]) * sc0;
            float v2 = (y[nt][2] + yx[r1 * 66 + col])     * sc1;
            float v3 = (y[nt][3] + yx[r1 * 66 + col + 1]) * sc1;
            uint32_t hi, lo;
            split_pack(v0, v1, hi, lo);
            *reinterpret_cast<uint32_t*>(g_YH + o0 + nt * 8) = hi;
            *reinterpret_cast<uint32_t*>(g_YL + o0 + nt * 8) = lo;
            split_pack(v2, v3, hi, lo);
            *reinterpret_cast<uint32_t*>(g_YH + o1 + nt * 8) = hi;
            *reinterpret_cast<uint32_t*>(g_YL + o1 + nt * 8) = lo;
        }
    }
}

// ---------------------------------------------------------------------------
// out = y @ W_O + b_O  via bf16 mma hi/lo. Tile 128x128, K=512 in 64-blocks.
// ---------------------------------------------------------------------------
#define OB_STRIDE 144u
#define OB_AH     0u
#define OB_AL     18432u
#define OB_BH     36864u
#define OB_BL     55296u
#define OB_BUF    73728u
#define OUT_SMEM  (2u * OB_BUF)          // 147456

__device__ __forceinline__ void issue_out_loads(char* smem, int buf, int row0,
                                                int col0, int k0, int tid)
{
    uint32_t sb = smem_u32(smem) + (uint32_t)buf * OB_BUF;
    #pragma unroll
    for (int i = tid; i < 1024; i += 256) {
        int row = i >> 3, u = i & 7;
        size_t ga = (size_t)(row0 + row) * DOUT + k0 + u * 8;
        cp16(sb + OB_AH + row * OB_STRIDE + u * 16, g_YH + ga);
        cp16(sb + OB_AL + row * OB_STRIDE + u * 16, g_YL + ga);
        size_t gb = (size_t)(col0 + row) * DOUT + k0 + u * 8;
        cp16(sb + OB_BH + row * OB_STRIDE + u * 16, g_WOH + gb);
        cp16(sb + OB_BL + row * OB_STRIDE + u * 16, g_WOL + gb);
    }
}

__global__ void __launch_bounds__(256, 1)
out_tc(const float* __restrict__ bO, float* __restrict__ out)
{
    extern __shared__ __align__(16) char smem[];
    const int tid  = threadIdx.x;
    const int warp = tid >> 5;
    const int lane = tid & 31;
    const int row0 = blockIdx.x * 128;
    const int col0 = blockIdx.y * 128;
    const int g    = lane >> 2;
    const int t4   = lane & 3;
    const int wrow = warp * 16;
    const uint32_t sbase = smem_u32(smem);

    const int n_add = ((lane >> 4) & 1) * 8 + (lane & 7);
    const int k_add = ((lane >> 3) & 1) * 8;
    const uint32_t laneO = (uint32_t)(n_add * OB_STRIDE + k_add * 2);

    issue_out_loads(smem, 0, row0, col0, 0, tid);
    CP_COMMIT();

    float y[16][4];
    #pragma unroll
    for (int nt = 0; nt < 16; nt++)
        #pragma unroll
        for (int e = 0; e < 4; e++) y[nt][e] = 0.f;

    for (int kb = 0; kb < 8; kb++) {
        const int cur = kb & 1;
        if (kb < 7) {
            issue_out_loads(smem, cur ^ 1, row0, col0, (kb + 1) * 64, tid);
            CP_COMMIT();
            CP_WAIT1();
        } else {
            CP_WAIT0();
        }
        __syncthreads();

        const uint32_t sb  = sbase + (uint32_t)cur * OB_BUF;
        const uint32_t aH  = sb + OB_AH + (uint32_t)wrow * OB_STRIDE + laneO;
        const uint32_t aL  = sb + OB_AL + (uint32_t)wrow * OB_STRIDE + laneO;
        const uint32_t bH  = sb + OB_BH + laneO;
        const uint32_t bL  = sb + OB_BL + laneO;

        #pragma unroll
        for (int kc = 0; kc < 4; kc++) {
            uint32_t ta[4], tb[4];
            ldm_x4(ta, aH + kc * 32);
            ldm_x4(tb, aL + kc * 32);
            uint32_t ah[4] = {ta[0], ta[2], ta[1], ta[3]};
            uint32_t al[4] = {tb[0], tb[2], tb[1], tb[3]};

            #pragma unroll
            for (int ntp = 0; ntp < 8; ntp++) {
                uint32_t off = (uint32_t)(ntp * 16) * OB_STRIDE + (uint32_t)kc * 32;
                uint32_t wh[4], wl[4];
                ldm_x4(wh, bH + off);
                ldm_x4(wl, bL + off);
                mma_bf16(y[2 * ntp],     ah, wh[0], wh[1]);
                mma_bf16(y[2 * ntp],     ah, wl[0], wl[1]);
                mma_bf16(y[2 * ntp],     al, wh[0], wh[1]);
                mma_bf16(y[2 * ntp + 1], ah, wh[2], wh[3]);
                mma_bf16(y[2 * ntp + 1], ah, wl[2], wl[3]);
                mma_bf16(y[2 * ntp + 1], al, wh[2], wh[3]);
            }
        }
        __syncthreads();
    }

    const int r0 = row0 + wrow + g, r1 = r0 + 8;
    #pragma unroll
    for (int nt = 0; nt < 16; nt++) {
        int col = col0 + nt * 8 + 2 * t4;
        float b0 = bO[col], b1 = bO[col + 1];
        *reinterpret_cast<float2*>(out + (size_t)r0 * DOUT + col) =
            make_float2(y[nt][0] + b0, y[nt][1] + b1);
        *reinterpret_cast<float2*>(out + (size_t)r1 * DOUT + col) =
            make_float2(y[nt][2] + b0, y[nt][3] + b1);
    }
}

// ---------------------------------------------------------------------------
extern "C" void kernel_launch(void* const* d_in, const int* in_sizes, int n_in,
                              void* d_out, int out_size)
{
    const float* z  = (const float*)d_in[0];   // (4,1024,8,64)
    const float* R  = (const float*)d_in[1];   // (8,2048,64)
    const float* q  = (const float*)d_in[2];   // (8,2048)
    const float* W  = (const float*)d_in[3];   // (8,2048,64)
    const float* WO = (const float*)d_in[4];   // (512,512)
    const float* bO = (const float*)d_in[5];   // (512)
    float* out = (float*)d_out;                // (4,1024,512)
    (void)in_sizes; (void)n_in; (void)out_size;

    cudaFuncSetAttribute(fused_mma, cudaFuncAttributeMaxDynamicSharedMemorySize,
                         SMEM_BYTES);
    cudaFuncSetAttribute(out_tc, cudaFuncAttributeMaxDynamicSharedMemorySize,
                         OUT_SMEM);

    prep_land<<<NHEAD * NLAND / 8, 256>>>(R, q);
    prep_w<<<NHEAD * (NLAND / 64), 256>>>(W);
    prep_wo<<<64, 256>>>(WO);

    dim3 gridF(BS_ROWS / 128, NHEAD);          // (32, 8)
    fused_mma<<<gridF, 512, SMEM_BYTES>>>(z);

    dim3 gridO(BS_ROWS / 128, DOUT / 128);     // (32, 4)
    out_tc<<<gridO, 256, OUT_SMEM>>>(bO, out);
}

// round 7
// speedup vs baseline: 1.0525x; 1.0525x over previous
#include <cuda_runtime.h>
#include <cuda_bf16.h>
#include <cstdint>

// ---------------------------------------------------------------------------
// Problem constants
// ---------------------------------------------------------------------------
#define BS_ROWS 4096      // B*S
#define NHEAD   8
#define DIM     64        // d == D_head
#define NLAND   2048      // landmarks per head
#define DOUT    512
#define EPS_C   1e-12f

// ---------------------------------------------------------------------------
// Device-global scratch (no allocation allowed)
// ---------------------------------------------------------------------------
__device__ float g_R2[NHEAD * NLAND];
__device__ float g_qa[NHEAD * NLAND];
__device__ __nv_bfloat16 g_RH[NHEAD * NLAND * DIM];     // R hi  [h][n][d]
__device__ __nv_bfloat16 g_RL[NHEAD * NLAND * DIM];     // R lo
__device__ __nv_bfloat16 g_WH[NHEAD * DIM * NLAND];     // W^T hi [h][dh][n]
__device__ __nv_bfloat16 g_WL[NHEAD * DIM * NLAND];     // W^T lo
__device__ __nv_bfloat16 g_YH[BS_ROWS * DOUT];          // y hi [row][col]
__device__ __nv_bfloat16 g_YL[BS_ROWS * DOUT];          // y lo
__device__ __nv_bfloat16 g_WOH[DOUT * DOUT];            // W_O^T hi [col][k]
__device__ __nv_bfloat16 g_WOL[DOUT * DOUT];            // W_O^T lo

// ---------------------------------------------------------------------------
// PTX helpers (sm_80-era, valid on sm_100 base)
// ---------------------------------------------------------------------------
__device__ __forceinline__ uint32_t smem_u32(const void* p) {
    return (uint32_t)__cvta_generic_to_shared(p);
}

__device__ __forceinline__ void cp16(uint32_t s, const void* g) {
    asm volatile("cp.async.cg.shared.global [%0], [%1], 16;" :: "r"(s), "l"(g));
}
#define CP_COMMIT() asm volatile("cp.async.commit_group;" ::: "memory")
#define CP_WAIT1()  asm volatile("cp.async.wait_group 1;" ::: "memory")
#define CP_WAIT0()  asm volatile("cp.async.wait_group 0;" ::: "memory")

__device__ __forceinline__ void ldm_x4(uint32_t* f, uint32_t addr) {
    asm volatile("ldmatrix.sync.aligned.m8n8.x4.shared.b16 {%0,%1,%2,%3}, [%4];"
        : "=r"(f[0]), "=r"(f[1]), "=r"(f[2]), "=r"(f[3]) : "r"(addr));
}

__device__ __forceinline__ void mma_bf16(float* c, const uint32_t* a,
                                         uint32_t b0, uint32_t b1) {
    asm volatile(
        "mma.sync.aligned.m16n8k16.row.col.f32.bf16.bf16.f32 "
        "{%0,%1,%2,%3}, {%4,%5,%6,%7}, {%8,%9}, {%0,%1,%2,%3};"
        : "+f"(c[0]), "+f"(c[1]), "+f"(c[2]), "+f"(c[3])
        : "r"(a[0]), "r"(a[1]), "r"(a[2]), "r"(a[3]), "r"(b0), "r"(b1));
}

// (f32,f32) -> packed bf16x2 hi + lo (residual)
__device__ __forceinline__ void split_pack(float e0, float e1,
                                           uint32_t& hi, uint32_t& lo)
{
    __nv_bfloat162 h2 = __float22bfloat162_rn(make_float2(e0, e1));
    float r0 = e0 - __bfloat162float(h2.x);
    float r1 = e1 - __bfloat162float(h2.y);
    __nv_bfloat162 l2 = __float22bfloat162_rn(make_float2(r0, r1));
    hi = *reinterpret_cast<uint32_t*>(&h2);
    lo = *reinterpret_cast<uint32_t*>(&l2);
}

// ---------------------------------------------------------------------------
// Fused-kernel SMEM layout (BN = 64 landmarks per tile, 32 tiles)
// Tiles: R [64 n][64 k] halves stride 144 B; W^T [64 dh][64 n] stride 144 B.
// ---------------------------------------------------------------------------
#define SR_B     144u
#define OFF_RH   0u
#define OFF_RL   9216u
#define OFF_WH   18432u
#define OFF_WL   27648u
#define OFF_R2   36864u   // float[64]
#define OFF_QA   37120u   // float[64]
#define BUF_B    37376u
#define ZH_OFF   74752u   // persistent Z hi [128 rows][64 k] halves stride 144
#define ZL_OFF   93184u
#define Z2_OFF   111616u  // float[128]
#define SMEM_BYTES 112128u

// ---------------------------------------------------------------------------
// Prep 1: per-landmark R2, qa, bf16 hi/lo split of R. warp per landmark.
// ---------------------------------------------------------------------------
__global__ void __launch_bounds__(256)
prep_land(const float* __restrict__ R, const float* __restrict__ q)
{
    int wid  = threadIdx.x >> 5, lane = threadIdx.x & 31;
    int idx  = blockIdx.x * 8 + wid;            // h*NLAND + n
    const float* r = R + (size_t)idx * DIM;
    float v0 = r[lane], v1 = r[lane + 32];
    __nv_bfloat16 h0 = __float2bfloat16_rn(v0);
    __nv_bfloat16 h1 = __float2bfloat16_rn(v1);
    g_RH[(size_t)idx * DIM + lane]      = h0;
    g_RH[(size_t)idx * DIM + lane + 32] = h1;
    g_RL[(size_t)idx * DIM + lane]      = __float2bfloat16_rn(v0 - __bfloat162float(h0));
    g_RL[(size_t)idx * DIM + lane + 32] = __float2bfloat16_rn(v1 - __bfloat162float(h1));
    float s = v0 * v0 + v1 * v1;
    #pragma unroll
    for (int m = 16; m >= 1; m >>= 1) s += __shfl_xor_sync(0xffffffffu, s, m);
    if (lane == 0) {
        g_R2[idx] = s;
        float qq = q[idx];
        qq = (qq > 0.f ? qq : 0.f) + EPS_C;
        g_qa[idx] = rsqrtf(qq);
    }
}

// ---------------------------------------------------------------------------
// Prep 2: W^T bf16 hi/lo [h][dh][n] via SMEM transpose
// ---------------------------------------------------------------------------
__global__ void __launch_bounds__(256)
prep_w(const float* __restrict__ W)
{
    __shared__ float sm[64][65];
    int h  = blockIdx.x >> 5;
    int n0 = (blockIdx.x & 31) * 64;
    for (int t = threadIdx.x; t < 4096; t += 256) {
        int i = t >> 6, d = t & 63;
        sm[i][d] = W[((size_t)(h * NLAND + n0 + i)) * DIM + d];
    }
    __syncthreads();
    for (int t = threadIdx.x; t < 4096; t += 256) {
        int d = t >> 6, i = t & 63;
        float v = sm[i][d];
        __nv_bfloat16 hh = __float2bfloat16_rn(v);
        size_t o = ((size_t)h * DIM + d) * NLAND + n0 + i;
        g_WH[o] = hh;
        g_WL[o] = __float2bfloat16_rn(v - __bfloat162float(hh));
    }
}

// ---------------------------------------------------------------------------
// Prep 3: W_O^T bf16 hi/lo [col][k] via SMEM transpose (512x512)
// ---------------------------------------------------------------------------
__global__ void __launch_bounds__(256)
prep_wo(const float* __restrict__ WO)
{
    __shared__ float sm[64][65];
    int kb = blockIdx.x >> 3;
    int cb = blockIdx.x & 7;
    int k0 = kb * 64, c0 = cb * 64;
    for (int t = threadIdx.x; t < 4096; t += 256) {
        int i = t >> 6, d = t & 63;
        sm[i][d] = WO[(size_t)(k0 + i) * DOUT + c0 + d];
    }
    __syncthreads();
    for (int t = threadIdx.x; t < 4096; t += 256) {
        int d = t >> 6, i = t & 63;
        float v = sm[i][d];
        __nv_bfloat16 hh = __float2bfloat16_rn(v);
        size_t o = (size_t)(c0 + d) * DOUT + k0 + i;
        g_WOH[o] = hh;
        g_WOL[o] = __float2bfloat16_rn(v - __bfloat162float(hh));
    }
}

// ---------------------------------------------------------------------------
// Fused kernel: one CTA per (head, 128-row block), 256 threads, 2 CTAs/SM.
// Warp owns 16 rows x all 64 landmark cols of each tile (R4 partitioning).
// ---------------------------------------------------------------------------
__device__ __forceinline__ void issue_tile_loads(char* smem, int buf, int h, int n0,
                                                 int tid)
{
    uint32_t sb = smem_u32(smem) + (uint32_t)buf * BUF_B;
    const __nv_bfloat16* rh = g_RH + ((size_t)h * NLAND + n0) * DIM;
    const __nv_bfloat16* rl = g_RL + ((size_t)h * NLAND + n0) * DIM;
    #pragma unroll
    for (int i = tid; i < 512; i += 256) {
        int row = i >> 3, u = i & 7;
        cp16(sb + OFF_RH + row * SR_B + u * 16, rh + row * DIM + u * 8);
        cp16(sb + OFF_RL + row * SR_B + u * 16, rl + row * DIM + u * 8);
    }
    const __nv_bfloat16* wh = g_WH + (size_t)h * DIM * NLAND + n0;
    const __nv_bfloat16* wl = g_WL + (size_t)h * DIM * NLAND + n0;
    #pragma unroll
    for (int i = tid; i < 512; i += 256) {
        int row = i >> 3, u = i & 7;
        cp16(sb + OFF_WH + row * SR_B + u * 16, wh + (size_t)row * NLAND + u * 8);
        cp16(sb + OFF_WL + row * SR_B + u * 16, wl + (size_t)row * NLAND + u * 8);
    }
    if (tid < 16) {
        cp16(sb + OFF_R2 + tid * 16, g_R2 + h * NLAND + n0 + tid * 4);
        cp16(sb + OFF_QA + tid * 16, g_qa + h * NLAND + n0 + tid * 4);
    }
}

__global__ void __launch_bounds__(256, 2)
fused_mma(const float* __restrict__ z)
{
    extern __shared__ __align__(16) char smem[];
    const int tid  = threadIdx.x;
    const int warp = tid >> 5;
    const int lane = tid & 31;
    const int h    = blockIdx.y;
    const int row0 = blockIdx.x * 128;
    const int g    = lane >> 2;          // 0..7
    const int t4   = lane & 3;           // 0..3
    const int wrow = warp * 16;
    const uint32_t sbase = smem_u32(smem);

    const int n_add = ((lane >> 4) & 1) * 8 + (lane & 7);
    const int k_add = ((lane >> 3) & 1) * 8;
    const uint32_t laneR = (uint32_t)(n_add * SR_B + k_add * 2);

    // ---- prologue: kick cp.async for tile 0 into buf 0 ----
    issue_tile_loads(smem, 0, h, 0, tid);
    CP_COMMIT();

    // ---- stage Z rows as bf16 hi/lo into persistent SMEM ----
    #pragma unroll
    for (int i = tid; i < 4096; i += 256) {       // 128 rows x 32 pairs
        int r = i >> 5, p = i & 31;
        float2 v = *reinterpret_cast<const float2*>(
            z + ((size_t)(row0 + r) * NHEAD + h) * DIM + 2 * p);
        uint32_t hi, lo;
        split_pack(v.x, v.y, hi, lo);
        *reinterpret_cast<uint32_t*>(smem + ZH_OFF + r * SR_B + p * 4) = hi;
        *reinterpret_cast<uint32_t*>(smem + ZL_OFF + r * SR_B + p * 4) = lo;
    }
    if (tid < 128) {                              // fp32 row norms
        const float* zr = z + ((size_t)(row0 + tid) * NHEAD + h) * DIM;
        float s = 0.f;
        #pragma unroll 16
        for (int k = 0; k < DIM; k++) s += zr[k] * zr[k];
        *reinterpret_cast<float*>(smem + Z2_OFF + tid * 4) = s;
    }
    __syncthreads();

    const int r0 = wrow + g, r1 = r0 + 8;         // this thread's 2 rows
    const float z2a = *reinterpret_cast<const float*>(smem + Z2_OFF + r0 * 4);
    const float z2b = *reinterpret_cast<const float*>(smem + Z2_OFF + r1 * 4);

    const uint32_t zHa = sbase + ZH_OFF + (uint32_t)(wrow + n_add) * SR_B + k_add * 2;
    const uint32_t zLa = sbase + ZL_OFF + (uint32_t)(wrow + n_add) * SR_B + k_add * 2;

    float y[8][4];
    #pragma unroll
    for (int nt = 0; nt < 8; nt++)
        #pragma unroll
        for (int e = 0; e < 4; e++) y[nt][e] = 0.f;

    float p1a = 0.f, p1b = 0.f, p2a = 0.f, p2b = 0.f;

    for (int t = 0; t < 32; t++) {
        const int cur = t & 1;
        if (t < 31) {
            issue_tile_loads(smem, cur ^ 1, h, (t + 1) * 64, tid);
            CP_COMMIT();
            CP_WAIT1();
        } else {
            CP_WAIT0();
        }
        __syncthreads();

        const uint32_t sb  = sbase + (uint32_t)cur * BUF_B;
        const uint32_t rbH = sb + OFF_RH + laneR;
        const uint32_t rbL = sb + OFF_RL + laneR;
        const float* r2p = (const float*)(smem + cur * BUF_B + OFF_R2);
        const float* qap = (const float*)(smem + cur * BUF_B + OFF_QA);

        // ---- GEMM1: 16 rows x 64 landmark cols, chain-spaced passes ----
        float c[8][4];
        #pragma unroll
        for (int nt = 0; nt < 8; nt++)
            #pragma unroll
            for (int e = 0; e < 4; e++) c[nt][e] = 0.f;

        #pragma unroll
        for (int kc = 0; kc < 4; kc++) {
            uint32_t ta[4], tb[4];
            ldm_x4(ta, zHa + kc * 32);
            ldm_x4(tb, zLa + kc * 32);
            uint32_t azh[4] = {ta[0], ta[2], ta[1], ta[3]};
            uint32_t azl[4] = {tb[0], tb[2], tb[1], tb[3]};
            #pragma unroll
            for (int np = 0; np < 2; np++) {
                uint32_t oA = (uint32_t)((2 * np) * 16) * SR_B + (uint32_t)kc * 32;
                uint32_t oB = (uint32_t)((2 * np + 1) * 16) * SR_B + (uint32_t)kc * 32;
                uint32_t rhA[4], rlA[4], rhB[4], rlB[4];
                ldm_x4(rhA, rbH + oA);
                ldm_x4(rlA, rbL + oA);
                ldm_x4(rhB, rbH + oB);
                ldm_x4(rlB, rbL + oB);
                float* c0 = c[4 * np + 0];
                float* c1 = c[4 * np + 1];
                float* c2 = c[4 * np + 2];
                float* c3 = c[4 * np + 3];
                // pass hh (4 independent accumulators)
                mma_bf16(c0, azh, rhA[0], rhA[1]);
                mma_bf16(c1, azh, rhA[2], rhA[3]);
                mma_bf16(c2, azh, rhB[0], rhB[1]);
                mma_bf16(c3, azh, rhB[2], rhB[3]);
                // pass hl
                mma_bf16(c0, azh, rlA[0], rlA[1]);
                mma_bf16(c1, azh, rlA[2], rlA[3]);
                mma_bf16(c2, azh, rlB[0], rlB[1]);
                mma_bf16(c3, azh, rlB[2], rlB[3]);
                // pass lh
                mma_bf16(c0, azl, rhA[0], rhA[1]);
                mma_bf16(c1, azl, rhA[2], rhA[3]);
                mma_bf16(c2, azl, rhB[0], rhB[1]);
                mma_bf16(c3, azl, rhB[2], rhB[3]);
            }
        }

        // ---- epilogue + GEMM2, interleaved per 16-landmark chunk ----
        const uint32_t wbH = sb + OFF_WH + laneR;
        const uint32_t wbL = sb + OFF_WL + laneR;
        #pragma unroll
        for (int kch = 0; kch < 4; kch++) {
            const int ct0 = 2 * kch, ct1 = 2 * kch + 1;
            const int col0 = ct0 * 8 + 2 * t4;
            const int col1 = ct1 * 8 + 2 * t4;
            float r2_0 = r2p[col0], r2_1 = r2p[col0 + 1];
            float r2_2 = r2p[col1], r2_3 = r2p[col1 + 1];
            float qa_0 = qap[col0], qa_1 = qap[col0 + 1];
            float qa_2 = qap[col1], qa_3 = qap[col1 + 1];

            float K00 = __expf(-0.5f * fmaxf(fmaf(-2.f, c[ct0][0], z2a) + r2_0, 0.f));
            float K01 = __expf(-0.5f * fmaxf(fmaf(-2.f, c[ct0][1], z2a) + r2_1, 0.f));
            float K02 = __expf(-0.5f * fmaxf(fmaf(-2.f, c[ct0][2], z2b) + r2_0, 0.f));
            float K03 = __expf(-0.5f * fmaxf(fmaf(-2.f, c[ct0][3], z2b) + r2_1, 0.f));
            float K10 = __expf(-0.5f * fmaxf(fmaf(-2.f, c[ct1][0], z2a) + r2_2, 0.f));
            float K11 = __expf(-0.5f * fmaxf(fmaf(-2.f, c[ct1][1], z2a) + r2_3, 0.f));
            float K12 = __expf(-0.5f * fmaxf(fmaf(-2.f, c[ct1][2], z2b) + r2_2, 0.f));
            float K13 = __expf(-0.5f * fmaxf(fmaf(-2.f, c[ct1][3], z2b) + r2_3, 0.f));

            p1a += K00 + K01 + K10 + K11;
            p1b += K02 + K03 + K12 + K13;

            float kt00 = K00 * qa_0, kt01 = K01 * qa_1;
            float kt02 = K02 * qa_0, kt03 = K03 * qa_1;
            float kt10 = K10 * qa_2, kt11 = K11 * qa_3;
            float kt12 = K12 * qa_2, kt13 = K13 * qa_3;

            p2a += kt00 + kt01 + kt10 + kt11;
            p2b += kt02 + kt03 + kt12 + kt13;

            uint32_t ah[4], al[4];
            split_pack(kt00, kt01, ah[0], al[0]);
            split_pack(kt02, kt03, ah[1], al[1]);
            split_pack(kt10, kt11, ah[2], al[2]);
            split_pack(kt12, kt13, ah[3], al[3]);

            #pragma unroll
            for (int np = 0; np < 2; np++) {
                uint32_t oA = (uint32_t)((2 * np) * 16) * SR_B + (uint32_t)kch * 32;
                uint32_t oB = (uint32_t)((2 * np + 1) * 16) * SR_B + (uint32_t)kch * 32;
                uint32_t whA[4], wlA[4], whB[4], wlB[4];
                ldm_x4(whA, wbH + oA);
                ldm_x4(wlA, wbL + oA);
                ldm_x4(whB, wbH + oB);
                ldm_x4(wlB, wbL + oB);
                float* y0 = y[4 * np + 0];
                float* y1 = y[4 * np + 1];
                float* y2 = y[4 * np + 2];
                float* y3 = y[4 * np + 3];
                mma_bf16(y0, ah, whA[0], whA[1]);
                mma_bf16(y1, ah, whA[2], whA[3]);
                mma_bf16(y2, ah, whB[0], whB[1]);
                mma_bf16(y3, ah, whB[2], whB[3]);
                mma_bf16(y0, ah, wlA[0], wlA[1]);
                mma_bf16(y1, ah, wlA[2], wlA[3]);
                mma_bf16(y2, ah, wlB[0], wlB[1]);
                mma_bf16(y3, ah, wlB[2], wlB[3]);
                mma_bf16(y0, al, whA[0], whA[1]);
                mma_bf16(y1, al, whA[2], whA[3]);
                mma_bf16(y2, al, whB[0], whB[1]);
                mma_bf16(y3, al, whB[2], whB[3]);
            }
        }
        __syncthreads();
    }

    // ---- row-sum reduction across the 4 lanes sharing each row ----
    #pragma unroll
    for (int m = 1; m <= 2; m <<= 1) {
        p1a += __shfl_xor_sync(0xffffffffu, p1a, m);
        p1b += __shfl_xor_sync(0xffffffffu, p1b, m);
        p2a += __shfl_xor_sync(0xffffffffu, p2a, m);
        p2b += __shfl_xor_sync(0xffffffffu, p2b, m);
    }
    float cc0 = rsqrtf(fmaxf(p1a, EPS_C));
    float cc1 = rsqrtf(fmaxf(p1b, EPS_C));
    float sc0 = cc0 / fmaxf(cc0 * p2a, EPS_C);
    float sc1 = cc1 / fmaxf(cc1 * p2b, EPS_C);

    // ---- write y as bf16 hi/lo (ldmatrix-ready for out_tc) ----
    size_t o0 = (size_t)(row0 + r0) * DOUT + h * DIM + 2 * t4;
    size_t o1 = (size_t)(row0 + r1) * DOUT + h * DIM + 2 * t4;
    #pragma unroll
    for (int nt = 0; nt < 8; nt++) {
        uint32_t hi, lo;
        split_pack(y[nt][0] * sc0, y[nt][1] * sc0, hi, lo);
        *reinterpret_cast<uint32_t*>(g_YH + o0 + nt * 8) = hi;
        *reinterpret_cast<uint32_t*>(g_YL + o0 + nt * 8) = lo;
        split_pack(y[nt][2] * sc1, y[nt][3] * sc1, hi, lo);
        *reinterpret_cast<uint32_t*>(g_YH + o1 + nt * 8) = hi;
        *reinterpret_cast<uint32_t*>(g_YL + o1 + nt * 8) = lo;
    }
}

// ---------------------------------------------------------------------------
// out = y @ W_O + b_O  via bf16 mma hi/lo. Tile 128x128, K=512 in 64-blocks.
// ---------------------------------------------------------------------------
#define OB_STRIDE 144u
#define OB_AH     0u
#define OB_AL     18432u
#define OB_BH     36864u
#define OB_BL     55296u
#define OB_BUF    73728u
#define OUT_SMEM  (2u * OB_BUF)          // 147456

__device__ __forceinline__ void issue_out_loads(char* smem, int buf, int row0,
                                                int col0, int k0, int tid)
{
    uint32_t sb = smem_u32(smem) + (uint32_t)buf * OB_BUF;
    #pragma unroll
    for (int i = tid; i < 1024; i += 256) {
        int row = i >> 3, u = i & 7;
        size_t ga = (size_t)(row0 + row) * DOUT + k0 + u * 8;
        cp16(sb + OB_AH + row * OB_STRIDE + u * 16, g_YH + ga);
        cp16(sb + OB_AL + row * OB_STRIDE + u * 16, g_YL + ga);
        size_t gb = (size_t)(col0 + row) * DOUT + k0 + u * 8;
        cp16(sb + OB_BH + row * OB_STRIDE + u * 16, g_WOH + gb);
        cp16(sb + OB_BL + row * OB_STRIDE + u * 16, g_WOL + gb);
    }
}

__global__ void __launch_bounds__(256, 1)
out_tc(const float* __restrict__ bO, float* __restrict__ out)
{
    extern __shared__ __align__(16) char smem[];
    const int tid  = threadIdx.x;
    const int warp = tid >> 5;
    const int lane = tid & 31;
    const int row0 = blockIdx.x * 128;
    const int col0 = blockIdx.y * 128;
    const int g    = lane >> 2;
    const int t4   = lane & 3;
    const int wrow = warp * 16;
    const uint32_t sbase = smem_u32(smem);

    const int n_add = ((lane >> 4) & 1) * 8 + (lane & 7);
    const int k_add = ((lane >> 3) & 1) * 8;
    const uint32_t laneO = (uint32_t)(n_add * OB_STRIDE + k_add * 2);

    issue_out_loads(smem, 0, row0, col0, 0, tid);
    CP_COMMIT();

    float y[16][4];
    #pragma unroll
    for (int nt = 0; nt < 16; nt++)
        #pragma unroll
        for (int e = 0; e < 4; e++) y[nt][e] = 0.f;

    for (int kb = 0; kb < 8; kb++) {
        const int cur = kb & 1;
        if (kb < 7) {
            issue_out_loads(smem, cur ^ 1, row0, col0, (kb + 1) * 64, tid);
            CP_COMMIT();
            CP_WAIT1();
        } else {
            CP_WAIT0();
        }
        __syncthreads();

        const uint32_t sb  = sbase + (uint32_t)cur * OB_BUF;
        const uint32_t aH  = sb + OB_AH + (uint32_t)wrow * OB_STRIDE + laneO;
        const uint32_t aL  = sb + OB_AL + (uint32_t)wrow * OB_STRIDE + laneO;
        const uint32_t bH  = sb + OB_BH + laneO;
        const uint32_t bL  = sb + OB_BL + laneO;

        #pragma unroll
        for (int kc = 0; kc < 4; kc++) {
            uint32_t ta[4], tb[4];
            ldm_x4(ta, aH + kc * 32);
            ldm_x4(tb, aL + kc * 32);
            uint32_t ah[4] = {ta[0], ta[2], ta[1], ta[3]};
            uint32_t al[4] = {tb[0], tb[2], tb[1], tb[3]};

            #pragma unroll
            for (int np = 0; np < 4; np++) {
                uint32_t oA = (uint32_t)((2 * np) * 16) * OB_STRIDE + (uint32_t)kc * 32;
                uint32_t oB = (uint32_t)((2 * np + 1) * 16) * OB_STRIDE + (uint32_t)kc * 32;
                uint32_t whA[4], wlA[4], whB[4], wlB[4];
                ldm_x4(whA, bH + oA);
                ldm_x4(wlA, bL + oA);
                ldm_x4(whB, bH + oB);
                ldm_x4(wlB, bL + oB);
                float* y0 = y[4 * np + 0];
                float* y1 = y[4 * np + 1];
                float* y2 = y[4 * np + 2];
                float* y3 = y[4 * np + 3];
                mma_bf16(y0, ah, whA[0], whA[1]);
                mma_bf16(y1, ah, whA[2], whA[3]);
                mma_bf16(y2, ah, whB[0], whB[1]);
                mma_bf16(y3, ah, whB[2], whB[3]);
                mma_bf16(y0, ah, wlA[0], wlA[1]);
                mma_bf16(y1, ah, wlA[2], wlA[3]);
                mma_bf16(y2, ah, wlB[0], wlB[1]);
                mma_bf16(y3, ah, wlB[2], wlB[3]);
                mma_bf16(y0, al, whA[0], whA[1]);
                mma_bf16(y1, al, whA[2], whA[3]);
                mma_bf16(y2, al, whB[0], whB[1]);
                mma_bf16(y3, al, whB[2], whB[3]);
            }
        }
        __syncthreads();
    }

    const int r0 = row0 + wrow + g, r1 = r0 + 8;
    #pragma unroll
    for (int nt = 0; nt < 16; nt++) {
        int col = col0 + nt * 8 + 2 * t4;
        float b0 = bO[col], b1 = bO[col + 1];
        *reinterpret_cast<float2*>(out + (size_t)r0 * DOUT + col) =
            make_float2(y[nt][0] + b0, y[nt][1] + b1);
        *reinterpret_cast<float2*>(out + (size_t)r1 * DOUT + col) =
            make_float2(y[nt][2] + b0, y[nt][3] + b1);
    }
}

// ---------------------------------------------------------------------------
extern "C" void kernel_launch(void* const* d_in, const int* in_sizes, int n_in,
                              void* d_out, int out_size)
{
    const float* z  = (const float*)d_in[0];   // (4,1024,8,64)
    const float* R  = (const float*)d_in[1];   // (8,2048,64)
    const float* q  = (const float*)d_in[2];   // (8,2048)
    const float* W  = (const float*)d_in[3];   // (8,2048,64)
    const float* WO = (const float*)d_in[4];   // (512,512)
    const float* bO = (const float*)d_in[5];   // (512)
    float* out = (float*)d_out;                // (4,1024,512)
    (void)in_sizes; (void)n_in; (void)out_size;

    cudaFuncSetAttribute(fused_mma, cudaFuncAttributeMaxDynamicSharedMemorySize,
                         SMEM_BYTES);
    cudaFuncSetAttribute(out_tc, cudaFuncAttributeMaxDynamicSharedMemorySize,
                         OUT_SMEM);

    prep_land<<<NHEAD * NLAND / 8, 256>>>(R, q);
    prep_w<<<NHEAD * (NLAND / 64), 256>>>(W);
    prep_wo<<<64, 256>>>(WO);

    dim3 gridF(BS_ROWS / 128, NHEAD);          // (32, 8)
    fused_mma<<<gridF, 256, SMEM_BYTES>>>(z);

    dim3 gridO(BS_ROWS / 128, DOUT / 128);     // (32, 4)
    out_tc<<<gridO, 256, OUT_SMEM>>>(bO, out);
}

// round 9
// speedup vs baseline: 1.2632x; 1.2002x over previous
#include <cuda_runtime.h>
#include <cuda_fp16.h>
#include <cuda_bf16.h>
#include <cstdint>

// ---------------------------------------------------------------------------
// Problem constants
// ---------------------------------------------------------------------------
#define BS_ROWS 4096      // B*S
#define NHEAD   8
#define DIM     64        // d == D_head
#define NLAND   2048      // landmarks per head
#define DOUT    512
#define EPS_C   1e-12f

// ---------------------------------------------------------------------------
// Device-global scratch
// g_RH/RL: fp16 (z/R values are O(1) — fp16-safe, 11-bit mantissa)
// g_WH/WL: bf16 (multiplied against bf16 Kt which needs fp32-range exponent)
// ---------------------------------------------------------------------------
__device__ float g_R2[NHEAD * NLAND];
__device__ float g_qa[NHEAD * NLAND];
__device__ __half         g_RH[NHEAD * NLAND * DIM];    // R hi [h][n][d] fp16
__device__ __half         g_RL[NHEAD * NLAND * DIM];    // R lo fp16
__device__ __nv_bfloat16  g_WH[NHEAD * DIM * NLAND];    // W^T hi [h][dh][n] bf16
__device__ __nv_bfloat16  g_WL[NHEAD * DIM * NLAND];    // W^T lo bf16
__device__ __half         g_Y [BS_ROWS * DOUT];         // y fp16 [row][col]
__device__ __half         g_WOH[DOUT * DOUT];           // W_O^T hi [col][k] fp16
__device__ __half         g_WOL[DOUT * DOUT];           // W_O^T lo fp16

// ---------------------------------------------------------------------------
// PTX helpers
// ---------------------------------------------------------------------------
__device__ __forceinline__ uint32_t smem_u32(const void* p) {
    return (uint32_t)__cvta_generic_to_shared(p);
}
__device__ __forceinline__ void cp16(uint32_t s, const void* g) {
    asm volatile("cp.async.cg.shared.global [%0], [%1], 16;" :: "r"(s), "l"(g));
}
#define CP_COMMIT() asm volatile("cp.async.commit_group;" ::: "memory")
#define CP_WAIT1()  asm volatile("cp.async.wait_group 1;" ::: "memory")
#define CP_WAIT0()  asm volatile("cp.async.wait_group 0;" ::: "memory")

__device__ __forceinline__ void ldm_x4(uint32_t* f, uint32_t addr) {
    asm volatile("ldmatrix.sync.aligned.m8n8.x4.shared.b16 {%0,%1,%2,%3}, [%4];"
        : "=r"(f[0]), "=r"(f[1]), "=r"(f[2]), "=r"(f[3]) : "r"(addr));
}
__device__ __forceinline__ void mma_f16(float* c, const uint32_t* a,
                                        uint32_t b0, uint32_t b1) {
    asm volatile(
        "mma.sync.aligned.m16n8k16.row.col.f32.f16.f16.f32 "
        "{%0,%1,%2,%3}, {%4,%5,%6,%7}, {%8,%9}, {%0,%1,%2,%3};"
        : "+f"(c[0]), "+f"(c[1]), "+f"(c[2]), "+f"(c[3])
        : "r"(a[0]), "r"(a[1]), "r"(a[2]), "r"(a[3]), "r"(b0), "r"(b1));
}
__device__ __forceinline__ void mma_bf16(float* c, const uint32_t* a,
                                         uint32_t b0, uint32_t b1) {
    asm volatile(
        "mma.sync.aligned.m16n8k16.row.col.f32.bf16.bf16.f32 "
        "{%0,%1,%2,%3}, {%4,%5,%6,%7}, {%8,%9}, {%0,%1,%2,%3};"
        : "+f"(c[0]), "+f"(c[1]), "+f"(c[2]), "+f"(c[3])
        : "r"(a[0]), "r"(a[1]), "r"(a[2]), "r"(a[3]), "r"(b0), "r"(b1));
}
__device__ __forceinline__ uint32_t pack_h2(float a, float b) {
    __half2 h = __float22half2_rn(make_float2(a, b));
    return *reinterpret_cast<uint32_t*>(&h);
}
// (f32,f32) -> packed bf16x2 hi + lo (fp32-range exponent — required for Kt)
__device__ __forceinline__ void split_pack_bf(float e0, float e1,
                                              uint32_t& hi, uint32_t& lo)
{
    __nv_bfloat162 h2 = __float22bfloat162_rn(make_float2(e0, e1));
    float r0 = e0 - __bfloat162float(h2.x);
    float r1 = e1 - __bfloat162float(h2.y);
    __nv_bfloat162 l2 = __float22bfloat162_rn(make_float2(r0, r1));
    hi = *reinterpret_cast<uint32_t*>(&h2);
    lo = *reinterpret_cast<uint32_t*>(&l2);
}

// ---------------------------------------------------------------------------
// Fused-kernel SMEM layout (R4 exact)
// ---------------------------------------------------------------------------
#define SR_B     144u
#define SW_B     272u
#define OFF_RH   0u
#define OFF_RL   18432u
#define OFF_WH   36864u
#define OFF_WL   54272u
#define OFF_R2   71680u
#define OFF_QA   72192u
#define BUF_B    72704u
#define SMEM_BYTES (2u * BUF_B)       // 145408

// ---------------------------------------------------------------------------
// Prep 1: per-landmark R2, qa, fp16 hi/lo split of R. warp per landmark.
// ---------------------------------------------------------------------------
__global__ void __launch_bounds__(256)
prep_land(const float* __restrict__ R, const float* __restrict__ q)
{
    int wid  = threadIdx.x >> 5, lane = threadIdx.x & 31;
    int idx  = blockIdx.x * 8 + wid;            // h*NLAND + n
    const float* r = R + (size_t)idx * DIM;
    float v0 = r[lane], v1 = r[lane + 32];
    __half h0 = __float2half_rn(v0);
    __half h1 = __float2half_rn(v1);
    g_RH[(size_t)idx * DIM + lane]      = h0;
    g_RH[(size_t)idx * DIM + lane + 32] = h1;
    g_RL[(size_t)idx * DIM + lane]      = __float2half_rn(v0 - __half2float(h0));
    g_RL[(size_t)idx * DIM + lane + 32] = __float2half_rn(v1 - __half2float(h1));
    float s = v0 * v0 + v1 * v1;
    #pragma unroll
    for (int m = 16; m >= 1; m >>= 1) s += __shfl_xor_sync(0xffffffffu, s, m);
    if (lane == 0) {
        g_R2[idx] = s;
        float qq = q[idx];
        qq = (qq > 0.f ? qq : 0.f) + EPS_C;
        g_qa[idx] = rsqrtf(qq);
    }
}

// ---------------------------------------------------------------------------
// Prep 2: W^T bf16 hi/lo [h][dh][n] via SMEM transpose (R4 exact)
// ---------------------------------------------------------------------------
__global__ void __launch_bounds__(256)
prep_w(const float* __restrict__ W)
{
    __shared__ float sm[64][65];
    int h  = blockIdx.x >> 5;
    int n0 = (blockIdx.x & 31) * 64;
    for (int t = threadIdx.x; t < 4096; t += 256) {
        int i = t >> 6, d = t & 63;
        sm[i][d] = W[((size_t)(h * NLAND + n0 + i)) * DIM + d];
    }
    __syncthreads();
    for (int t = threadIdx.x; t < 4096; t += 256) {
        int d = t >> 6, i = t & 63;
        float v = sm[i][d];
        __nv_bfloat16 hh = __float2bfloat16_rn(v);
        size_t o = ((size_t)h * DIM + d) * NLAND + n0 + i;
        g_WH[o] = hh;
        g_WL[o] = __float2bfloat16_rn(v - __bfloat162float(hh));
    }
}

// ---------------------------------------------------------------------------
// Prep 3: W_O^T fp16 hi/lo [col][k] via SMEM transpose (512x512)
// ---------------------------------------------------------------------------
__global__ void __launch_bounds__(256)
prep_wo(const float* __restrict__ WO)
{
    __shared__ float sm[64][65];
    int kb = blockIdx.x >> 3, cb = blockIdx.x & 7;
    int k0 = kb * 64, c0 = cb * 64;
    for (int t = threadIdx.x; t < 4096; t += 256) {
        int i = t >> 6, d = t & 63;
        sm[i][d] = WO[(size_t)(k0 + i) * DOUT + c0 + d];
    }
    __syncthreads();
    for (int t = threadIdx.x; t < 4096; t += 256) {
        int d = t >> 6, i = t & 63;
        float v = sm[i][d];
        __half hh = __float2half_rn(v);
        size_t o = (size_t)(c0 + d) * DOUT + k0 + i;
        g_WOH[o] = hh;
        g_WOL[o] = __float2half_rn(v - __half2float(hh));
    }
}

// ---------------------------------------------------------------------------
// Fused kernel: one CTA per (head, 128-row block), 256 threads (R4 schedule).
// ---------------------------------------------------------------------------
__device__ __forceinline__ void issue_tile_loads(char* smem, int buf, int h, int n0,
                                                 int tid)
{
    uint32_t sb = smem_u32(smem) + (uint32_t)buf * BUF_B;
    const __half* rh = g_RH + ((size_t)h * NLAND + n0) * DIM;
    const __half* rl = g_RL + ((size_t)h * NLAND + n0) * DIM;
    #pragma unroll
    for (int i = tid; i < 1024; i += 256) {
        int row = i >> 3, u = i & 7;
        cp16(sb + OFF_RH + row * SR_B + u * 16, rh + row * DIM + u * 8);
        cp16(sb + OFF_RL + row * SR_B + u * 16, rl + row * DIM + u * 8);
    }
    const __nv_bfloat16* wh = g_WH + (size_t)h * DIM * NLAND + n0;
    const __nv_bfloat16* wl = g_WL + (size_t)h * DIM * NLAND + n0;
    #pragma unroll
    for (int i = tid; i < 1024; i += 256) {
        int row = i >> 4, u = i & 15;
        cp16(sb + OFF_WH + row * SW_B + u * 16, wh + (size_t)row * NLAND + u * 8);
        cp16(sb + OFF_WL + row * SW_B + u * 16, wl + (size_t)row * NLAND + u * 8);
    }
    if (tid < 32) {
        cp16(sb + OFF_R2 + tid * 16, g_R2 + h * NLAND + n0 + tid * 4);
        cp16(sb + OFF_QA + tid * 16, g_qa + h * NLAND + n0 + tid * 4);
    }
}

__global__ void __launch_bounds__(256, 1)
fused_mma(const float* __restrict__ z)
{
    extern __shared__ __align__(16) char smem[];
    const int tid  = threadIdx.x;
    const int warp = tid >> 5;
    const int lane = tid & 31;
    const int h    = blockIdx.y;
    const int row0 = blockIdx.x * 128;
    const int g    = lane >> 2;
    const int t4   = lane & 3;
    const int wrow = warp * 16;
    const uint32_t sbase = smem_u32(smem);

    const int n_add = ((lane >> 4) & 1) * 8 + (lane & 7);
    const int k_add = ((lane >> 3) & 1) * 8;
    const uint32_t laneR = (uint32_t)(n_add * SR_B + k_add * 2);
    const uint32_t laneW = (uint32_t)(n_add * SW_B + k_add * 2);

    issue_tile_loads(smem, 0, h, 0, tid);
    CP_COMMIT();

    // ---- stage z fp32 into buf1 region; build fp16 A-frags (single) ----
    float* zstage = (float*)(smem + BUF_B);     // [128][68]
    {
        const float4* zsrc = reinterpret_cast<const float4*>(z);
        #pragma unroll
        for (int i = tid; i < 2048; i += 256) {
            int r = i >> 4, c4 = i & 15;
            float4 v = zsrc[(((size_t)(row0 + r) * NHEAD + h) * DIM >> 2) + c4];
            *reinterpret_cast<float4*>(zstage + r * 68 + c4 * 4) = v;
        }
    }
    __syncthreads();

    const int r0 = wrow + g, r1 = r0 + 8;
    float z2a = 0.f, z2b = 0.f;
    #pragma unroll
    for (int k = 0; k < DIM; k++) {
        float va = zstage[r0 * 68 + k];
        float vb = zstage[r1 * 68 + k];
        z2a += va * va; z2b += vb * vb;
    }

    uint32_t zh[4][4];
    #pragma unroll
    for (int kc = 0; kc < 4; kc++) {
        int k0 = kc * 16 + 2 * t4;
        zh[kc][0] = pack_h2(zstage[r0 * 68 + k0],     zstage[r0 * 68 + k0 + 1]);
        zh[kc][1] = pack_h2(zstage[r1 * 68 + k0],     zstage[r1 * 68 + k0 + 1]);
        zh[kc][2] = pack_h2(zstage[r0 * 68 + k0 + 8], zstage[r0 * 68 + k0 + 9]);
        zh[kc][3] = pack_h2(zstage[r1 * 68 + k0 + 8], zstage[r1 * 68 + k0 + 9]);
    }
    __syncthreads();   // buf1 free before tile-1 cp.async

    float y[8][4];
    #pragma unroll
    for (int nt = 0; nt < 8; nt++)
        #pragma unroll
        for (int e = 0; e < 4; e++) y[nt][e] = 0.f;

    float p1a = 0.f, p1b = 0.f, p2a = 0.f, p2b = 0.f;

    for (int t = 0; t < 16; t++) {
        const int cur = t & 1;
        if (t < 15) {
            issue_tile_loads(smem, cur ^ 1, h, (t + 1) * 128, tid);
            CP_COMMIT();
            CP_WAIT1();
        } else {
            CP_WAIT0();
        }
        __syncthreads();

        const uint32_t sb  = sbase + (uint32_t)cur * BUF_B;
        const uint32_t rbH = sb + OFF_RH + laneR;
        const uint32_t rbL = sb + OFF_RL + laneR;
        const float* r2p = (const float*)(smem + cur * BUF_B + OFF_R2);
        const float* qap = (const float*)(smem + cur * BUF_B + OFF_QA);

        // ---- GEMM1: fp16, z single x R hi/lo (2-pass) ----
        float c[16][4];
        #pragma unroll
        for (int nt = 0; nt < 16; nt++)
            #pragma unroll
            for (int e = 0; e < 4; e++) c[nt][e] = 0.f;

        #pragma unroll
        for (int kc = 0; kc < 4; kc++) {
            #pragma unroll
            for (int ntp = 0; ntp < 8; ntp++) {
                uint32_t off = (uint32_t)(ntp * 16) * SR_B + (uint32_t)kc * 32;
                uint32_t rh[4], rl[4];
                ldm_x4(rh, rbH + off);
                ldm_x4(rl, rbL + off);
                mma_f16(c[2 * ntp],     zh[kc], rh[0], rh[1]);
                mma_f16(c[2 * ntp + 1], zh[kc], rh[2], rh[3]);
                mma_f16(c[2 * ntp],     zh[kc], rl[0], rl[1]);
                mma_f16(c[2 * ntp + 1], zh[kc], rl[2], rl[3]);
            }
        }

        // ---- epilogue + GEMM2 (bf16 3-pass, R4 exact) ----
        const uint32_t wbH = sb + OFF_WH + laneW;
        const uint32_t wbL = sb + OFF_WL + laneW;
        #pragma unroll
        for (int kch = 0; kch < 8; kch++) {
            const int ct0 = 2 * kch, ct1 = 2 * kch + 1;
            const int col0 = ct0 * 8 + 2 * t4;
            const int col1 = ct1 * 8 + 2 * t4;
            float r2_0 = r2p[col0], r2_1 = r2p[col0 + 1];
            float r2_2 = r2p[col1], r2_3 = r2p[col1 + 1];
            float qa_0 = qap[col0], qa_1 = qap[col0 + 1];
            float qa_2 = qap[col1], qa_3 = qap[col1 + 1];

            float K00 = __expf(-0.5f * fmaxf(fmaf(-2.f, c[ct0][0], z2a) + r2_0, 0.f));
            float K01 = __expf(-0.5f * fmaxf(fmaf(-2.f, c[ct0][1], z2a) + r2_1, 0.f));
            float K02 = __expf(-0.5f * fmaxf(fmaf(-2.f, c[ct0][2], z2b) + r2_0, 0.f));
            float K03 = __expf(-0.5f * fmaxf(fmaf(-2.f, c[ct0][3], z2b) + r2_1, 0.f));
            float K10 = __expf(-0.5f * fmaxf(fmaf(-2.f, c[ct1][0], z2a) + r2_2, 0.f));
            float K11 = __expf(-0.5f * fmaxf(fmaf(-2.f, c[ct1][1], z2a) + r2_3, 0.f));
            float K12 = __expf(-0.5f * fmaxf(fmaf(-2.f, c[ct1][2], z2b) + r2_2, 0.f));
            float K13 = __expf(-0.5f * fmaxf(fmaf(-2.f, c[ct1][3], z2b) + r2_3, 0.f));

            p1a += K00 + K01 + K10 + K11;
            p1b += K02 + K03 + K12 + K13;

            float kt00 = K00 * qa_0, kt01 = K01 * qa_1;
            float kt02 = K02 * qa_0, kt03 = K03 * qa_1;
            float kt10 = K10 * qa_2, kt11 = K11 * qa_3;
            float kt12 = K12 * qa_2, kt13 = K13 * qa_3;

            p2a += kt00 + kt01 + kt10 + kt11;
            p2b += kt02 + kt03 + kt12 + kt13;

            uint32_t ah[4], al[4];
            split_pack_bf(kt00, kt01, ah[0], al[0]);
            split_pack_bf(kt02, kt03, ah[1], al[1]);
            split_pack_bf(kt10, kt11, ah[2], al[2]);
            split_pack_bf(kt12, kt13, ah[3], al[3]);

            #pragma unroll
            for (int ntp = 0; ntp < 4; ntp++) {
                uint32_t off = (uint32_t)(ntp * 16) * SW_B + (uint32_t)kch * 32;
                uint32_t wh[4], wl[4];
                ldm_x4(wh, wbH + off);
                ldm_x4(wl, wbL + off);
                mma_bf16(y[2 * ntp],     ah, wh[0], wh[1]);
                mma_bf16(y[2 * ntp + 1], ah, wh[2], wh[3]);
                mma_bf16(y[2 * ntp],     ah, wl[0], wl[1]);
                mma_bf16(y[2 * ntp + 1], ah, wl[2], wl[3]);
                mma_bf16(y[2 * ntp],     al, wh[0], wh[1]);
                mma_bf16(y[2 * ntp + 1], al, wh[2], wh[3]);
            }
        }
        __syncthreads();
    }

    // ---- row-sum reduction across the 4 lanes sharing each row ----
    #pragma unroll
    for (int m = 1; m <= 2; m <<= 1) {
        p1a += __shfl_xor_sync(0xffffffffu, p1a, m);
        p1b += __shfl_xor_sync(0xffffffffu, p1b, m);
        p2a += __shfl_xor_sync(0xffffffffu, p2a, m);
        p2b += __shfl_xor_sync(0xffffffffu, p2b, m);
    }
    float cc0 = rsqrtf(fmaxf(p1a, EPS_C));
    float cc1 = rsqrtf(fmaxf(p1b, EPS_C));
    float sc0 = cc0 / fmaxf(cc0 * p2a, EPS_C);
    float sc1 = cc1 / fmaxf(cc1 * p2b, EPS_C);

    // ---- write y as single fp16 (range-safe: y is O(0.02)) ----
    size_t o0 = (size_t)(row0 + r0) * DOUT + h * DIM + 2 * t4;
    size_t o1 = (size_t)(row0 + r1) * DOUT + h * DIM + 2 * t4;
    #pragma unroll
    for (int nt = 0; nt < 8; nt++) {
        *reinterpret_cast<uint32_t*>(g_Y + o0 + nt * 8) =
            pack_h2(y[nt][0] * sc0, y[nt][1] * sc0);
        *reinterpret_cast<uint32_t*>(g_Y + o1 + nt * 8) =
            pack_h2(y[nt][2] * sc1, y[nt][3] * sc1);
    }
}

// ---------------------------------------------------------------------------
// out = y @ W_O + b_O : fp16, A single, B hi/lo 2-pass. 128x128 tiles.
// ---------------------------------------------------------------------------
#define OB_STRIDE 144u
#define OB_A      0u
#define OB_BH     18432u
#define OB_BL     36864u
#define OB_BUF    55296u
#define OUT_SMEM  (2u * OB_BUF)          // 110592

__device__ __forceinline__ void issue_out_loads(char* smem, int buf, int row0,
                                                int col0, int k0, int tid)
{
    uint32_t sb = smem_u32(smem) + (uint32_t)buf * OB_BUF;
    #pragma unroll
    for (int i = tid; i < 1024; i += 256) {
        int row = i >> 3, u = i & 7;
        cp16(sb + OB_A  + row * OB_STRIDE + u * 16,
             g_Y + (size_t)(row0 + row) * DOUT + k0 + u * 8);
        size_t gb = (size_t)(col0 + row) * DOUT + k0 + u * 8;
        cp16(sb + OB_BH + row * OB_STRIDE + u * 16, g_WOH + gb);
        cp16(sb + OB_BL + row * OB_STRIDE + u * 16, g_WOL + gb);
    }
}

__global__ void __launch_bounds__(256, 1)
out_tc(const float* __restrict__ bO, float* __restrict__ out)
{
    extern __shared__ __align__(16) char smem[];
    const int tid  = threadIdx.x;
    const int warp = tid >> 5;
    const int lane = tid & 31;
    const int row0 = blockIdx.x * 128;
    const int col0 = blockIdx.y * 128;
    const int g    = lane >> 2;
    const int t4   = lane & 3;
    const int wrow = warp * 16;
    const uint32_t sbase = smem_u32(smem);

    const int n_add = ((lane >> 4) & 1) * 8 + (lane & 7);
    const int k_add = ((lane >> 3) & 1) * 8;
    const uint32_t laneO = (uint32_t)(n_add * OB_STRIDE + k_add * 2);

    issue_out_loads(smem, 0, row0, col0, 0, tid);
    CP_COMMIT();

    float y[16][4];
    #pragma unroll
    for (int nt = 0; nt < 16; nt++)
        #pragma unroll
        for (int e = 0; e < 4; e++) y[nt][e] = 0.f;

    for (int kb = 0; kb < 8; kb++) {
        const int cur = kb & 1;
        if (kb < 7) {
            issue_out_loads(smem, cur ^ 1, row0, col0, (kb + 1) * 64, tid);
            CP_COMMIT();
            CP_WAIT1();
        } else {
            CP_WAIT0();
        }
        __syncthreads();

        const uint32_t sb = sbase + (uint32_t)cur * OB_BUF;
        const uint32_t aA = sb + OB_A  + (uint32_t)wrow * OB_STRIDE + laneO;
        const uint32_t bH = sb + OB_BH + laneO;
        const uint32_t bL = sb + OB_BL + laneO;

        #pragma unroll
        for (int kc = 0; kc < 4; kc++) {
            uint32_t ta[4];
            ldm_x4(ta, aA + kc * 32);
            uint32_t a[4] = {ta[0], ta[2], ta[1], ta[3]};   // validated permute

            #pragma unroll
            for (int np = 0; np < 4; np++) {
                uint32_t oA = (uint32_t)((2 * np) * 16) * OB_STRIDE + (uint32_t)kc * 32;
                uint32_t oB = (uint32_t)((2 * np + 1) * 16) * OB_STRIDE + (uint32_t)kc * 32;
                uint32_t whA[4], wlA[4], whB[4], wlB[4];
                ldm_x4(whA, bH + oA);
                ldm_x4(wlA, bL + oA);
                ldm_x4(whB, bH + oB);
                ldm_x4(wlB, bL + oB);
                float* y0 = y[4 * np + 0];
                float* y1 = y[4 * np + 1];
                float* y2 = y[4 * np + 2];
                float* y3 = y[4 * np + 3];
                mma_f16(y0, a, whA[0], whA[1]);
                mma_f16(y1, a, whA[2], whA[3]);
                mma_f16(y2, a, whB[0], whB[1]);
                mma_f16(y3, a, whB[2], whB[3]);
                mma_f16(y0, a, wlA[0], wlA[1]);
                mma_f16(y1, a, wlA[2], wlA[3]);
                mma_f16(y2, a, wlB[0], wlB[1]);
                mma_f16(y3, a, wlB[2], wlB[3]);
            }
        }
        __syncthreads();
    }

    const int r0 = row0 + wrow + g, r1 = r0 + 8;
    #pragma unroll
    for (int nt = 0; nt < 16; nt++) {
        int col = col0 + nt * 8 + 2 * t4;
        float b0 = bO[col], b1 = bO[col + 1];
        *reinterpret_cast<float2*>(out + (size_t)r0 * DOUT + col) =
            make_float2(y[nt][0] + b0, y[nt][1] + b1);
        *reinterpret_cast<float2*>(out + (size_t)r1 * DOUT + col) =
            make_float2(y[nt][2] + b0, y[nt][3] + b1);
    }
}

// ---------------------------------------------------------------------------
extern "C" void kernel_launch(void* const* d_in, const int* in_sizes, int n_in,
                              void* d_out, int out_size)
{
    const float* z  = (const float*)d_in[0];   // (4,1024,8,64)
    const float* R  = (const float*)d_in[1];   // (8,2048,64)
    const float* q  = (const float*)d_in[2];   // (8,2048)
    const float* W  = (const float*)d_in[3];   // (8,2048,64)
    const float* WO = (const float*)d_in[4];   // (512,512)
    const float* bO = (const float*)d_in[5];   // (512)
    float* out = (float*)d_out;                // (4,1024,512)
    (void)in_sizes; (void)n_in; (void)out_size;

    cudaFuncSetAttribute(fused_mma, cudaFuncAttributeMaxDynamicSharedMemorySize,
                         SMEM_BYTES);
    cudaFuncSetAttribute(out_tc, cudaFuncAttributeMaxDynamicSharedMemorySize,
                         OUT_SMEM);

    prep_land<<<NHEAD * NLAND / 8, 256>>>(R, q);
    prep_w<<<NHEAD * (NLAND / 64), 256>>>(W);
    prep_wo<<<64, 256>>>(WO);

    dim3 gridF(BS_ROWS / 128, NHEAD);          // (32, 8)
    fused_mma<<<gridF, 256, SMEM_BYTES>>>(z);

    dim3 gridO(BS_ROWS / 128, DOUT / 128);     // (32, 4)
    out_tc<<<gridO, 256, OUT_SMEM>>>(bO, out);
}

// round 10
// speedup vs baseline: 1.5281x; 1.2097x over previous
#include <cuda_runtime.h>
#include <cuda_fp16.h>
#include <cstdint>

// ---------------------------------------------------------------------------
// Problem constants
// ---------------------------------------------------------------------------
#define BS_ROWS 4096      // B*S
#define NHEAD   8
#define DIM     64        // d == D_head
#define NLAND   2048      // landmarks per head
#define DOUT    512
#define EPS_C   1e-12f
#define C2EXP   (-0.72134752044448f)    // -0.5 * log2(e)
#define LOG2E   (1.44269504088896f)

// ---------------------------------------------------------------------------
// Device-global scratch
// Trick: GEMM2 operand is K' = K * e^{+z^2/2} (per-row uniform shift), which
// lives in [~e-6, ~e5] -> fp16-safe. The shift is undone in fp32 at the end,
// with the reference's eps-clamps applied to the UNSCALED p1/p2.
// ---------------------------------------------------------------------------
__device__ float  g_cR2[NHEAD * NLAND];                 // C2EXP * ||R_n||^2
__device__ float  g_qa [NHEAD * NLAND];                 // (relu(q)+eps)^(-1/2)
__device__ __half g_RH[NHEAD * NLAND * DIM];            // R hi [h][n][d] fp16
__device__ __half g_RL[NHEAD * NLAND * DIM];            // R lo fp16
__device__ __half g_WPH[NHEAD * 72 * NLAND];            // W' hi [h][72][n] fp16
__device__ __half g_WPL[NHEAD * 72 * NLAND];            // rows 0-63: qa*W^T; 64: 1; 65: qa; 66-71: 0
__device__ __half g_Y [BS_ROWS * DOUT];                 // y fp16 [row][col]
__device__ __half g_WOH[DOUT * DOUT];                   // W_O^T hi [col][k] fp16
__device__ __half g_WOL[DOUT * DOUT];                   // W_O^T lo fp16

// ---------------------------------------------------------------------------
// PTX helpers
// ---------------------------------------------------------------------------
__device__ __forceinline__ uint32_t smem_u32(const void* p) {
    return (uint32_t)__cvta_generic_to_shared(p);
}
__device__ __forceinline__ void cp16(uint32_t s, const void* g) {
    asm volatile("cp.async.cg.shared.global [%0], [%1], 16;" :: "r"(s), "l"(g));
}
#define CP_COMMIT() asm volatile("cp.async.commit_group;" ::: "memory")
#define CP_WAIT1()  asm volatile("cp.async.wait_group 1;" ::: "memory")
#define CP_WAIT0()  asm volatile("cp.async.wait_group 0;" ::: "memory")

__device__ __forceinline__ void ldm_x4(uint32_t* f, uint32_t addr) {
    asm volatile("ldmatrix.sync.aligned.m8n8.x4.shared.b16 {%0,%1,%2,%3}, [%4];"
        : "=r"(f[0]), "=r"(f[1]), "=r"(f[2]), "=r"(f[3]) : "r"(addr));
}
__device__ __forceinline__ void ldm_x2(uint32_t* f, uint32_t addr) {
    asm volatile("ldmatrix.sync.aligned.m8n8.x2.shared.b16 {%0,%1}, [%2];"
        : "=r"(f[0]), "=r"(f[1]) : "r"(addr));
}
__device__ __forceinline__ void mma_f16(float* c, const uint32_t* a,
                                        uint32_t b0, uint32_t b1) {
    asm volatile(
        "mma.sync.aligned.m16n8k16.row.col.f32.f16.f16.f32 "
        "{%0,%1,%2,%3}, {%4,%5,%6,%7}, {%8,%9}, {%0,%1,%2,%3};"
        : "+f"(c[0]), "+f"(c[1]), "+f"(c[2]), "+f"(c[3])
        : "r"(a[0]), "r"(a[1]), "r"(a[2]), "r"(a[3]), "r"(b0), "r"(b1));
}
__device__ __forceinline__ uint32_t pack_h2(float a, float b) {
    __half2 h = __float22half2_rn(make_float2(a, b));
    return *reinterpret_cast<uint32_t*>(&h);
}
__device__ __forceinline__ float ex2f(float x) {
    float r; asm("ex2.approx.ftz.f32 %0, %1;" : "=f"(r) : "f"(x)); return r;
}

// ---------------------------------------------------------------------------
// Fused SMEM layout (per buffer)
// ---------------------------------------------------------------------------
#define SR_B     144u     // R tile [128 n][64 k] fp16
#define SW_B     272u     // W' tile [72 dh][128 n] fp16
#define OFF_RH   0u
#define OFF_RL   18432u
#define OFF_WH   36864u
#define OFF_WL   56448u
#define OFF_CR2  76032u   // float[128]
#define BUF_B    76544u
#define SMEM_BYTES (2u * BUF_B)    // 153088

// ---------------------------------------------------------------------------
// Prep 1: cR2, qa, fp16 hi/lo split of R. warp per landmark.
// ---------------------------------------------------------------------------
__global__ void __launch_bounds__(256)
prep_land(const float* __restrict__ R, const float* __restrict__ q)
{
    int wid  = threadIdx.x >> 5, lane = threadIdx.x & 31;
    int idx  = blockIdx.x * 8 + wid;
    const float* r = R + (size_t)idx * DIM;
    float v0 = r[lane], v1 = r[lane + 32];
    __half h0 = __float2half_rn(v0);
    __half h1 = __float2half_rn(v1);
    g_RH[(size_t)idx * DIM + lane]      = h0;
    g_RH[(size_t)idx * DIM + lane + 32] = h1;
    g_RL[(size_t)idx * DIM + lane]      = __float2half_rn(v0 - __half2float(h0));
    g_RL[(size_t)idx * DIM + lane + 32] = __float2half_rn(v1 - __half2float(h1));
    float s = v0 * v0 + v1 * v1;
    #pragma unroll
    for (int m = 16; m >= 1; m >>= 1) s += __shfl_xor_sync(0xffffffffu, s, m);
    if (lane == 0) {
        g_cR2[idx] = C2EXP * s;
        float qq = q[idx];
        qq = (qq > 0.f ? qq : 0.f) + EPS_C;
        g_qa[idx] = rsqrtf(qq);
    }
}

// ---------------------------------------------------------------------------
// Prep 2: W' = [qa*W^T ; ones ; qa ; zeros] fp16 hi/lo [h][72][n]
// Must run AFTER prep_land (reads g_qa).
// ---------------------------------------------------------------------------
__global__ void __launch_bounds__(256)
prep_wp(const float* __restrict__ W)
{
    __shared__ float sm[64][65];
    __shared__ float sqa[64];
    int h  = blockIdx.x >> 5;
    int n0 = (blockIdx.x & 31) * 64;
    for (int t = threadIdx.x; t < 4096; t += 256) {
        int i = t >> 6, d = t & 63;
        sm[i][d] = W[((size_t)(h * NLAND + n0 + i)) * DIM + d];
    }
    if (threadIdx.x < 64) sqa[threadIdx.x] = g_qa[h * NLAND + n0 + threadIdx.x];
    __syncthreads();
    for (int t = threadIdx.x; t < 4096; t += 256) {
        int d = t >> 6, i = t & 63;
        float v = sm[i][d] * sqa[i];
        __half hh = __float2half_rn(v);
        size_t o = ((size_t)h * 72 + d) * NLAND + n0 + i;
        g_WPH[o] = hh;
        g_WPL[o] = __float2half_rn(v - __half2float(hh));
    }
    for (int t = threadIdx.x; t < 64 * 8; t += 256) {
        int rr = 64 + (t >> 6), i = t & 63;
        float v = (rr == 64) ? 1.0f : (rr == 65 ? sqa[i] : 0.0f);
        __half hh = __float2half_rn(v);
        size_t o = ((size_t)h * 72 + rr) * NLAND + n0 + i;
        g_WPH[o] = hh;
        g_WPL[o] = __float2half_rn(v - __half2float(hh));
    }
}

// ---------------------------------------------------------------------------
// Prep 3: W_O^T fp16 hi/lo [col][k]
// ---------------------------------------------------------------------------
__global__ void __launch_bounds__(256)
prep_wo(const float* __restrict__ WO)
{
    __shared__ float sm[64][65];
    int kb = blockIdx.x >> 3, cb = blockIdx.x & 7;
    int k0 = kb * 64, c0 = cb * 64;
    for (int t = threadIdx.x; t < 4096; t += 256) {
        int i = t >> 6, d = t & 63;
        sm[i][d] = WO[(size_t)(k0 + i) * DOUT + c0 + d];
    }
    __syncthreads();
    for (int t = threadIdx.x; t < 4096; t += 256) {
        int d = t >> 6, i = t & 63;
        float v = sm[i][d];
        __half hh = __float2half_rn(v);
        size_t o = (size_t)(c0 + d) * DOUT + k0 + i;
        g_WOH[o] = hh;
        g_WOL[o] = __float2half_rn(v - __half2float(hh));
    }
}

// ---------------------------------------------------------------------------
// Fused kernel: one CTA per (head, 128-row block), 256 threads (R4 schedule).
// ---------------------------------------------------------------------------
__device__ __forceinline__ void issue_tile_loads(char* smem, int buf, int h, int n0,
                                                 int tid)
{
    uint32_t sb = smem_u32(smem) + (uint32_t)buf * BUF_B;
    const __half* rh = g_RH + ((size_t)h * NLAND + n0) * DIM;
    const __half* rl = g_RL + ((size_t)h * NLAND + n0) * DIM;
    #pragma unroll
    for (int i = tid; i < 1024; i += 256) {
        int row = i >> 3, u = i & 7;
        cp16(sb + OFF_RH + row * SR_B + u * 16, rh + row * DIM + u * 8);
        cp16(sb + OFF_RL + row * SR_B + u * 16, rl + row * DIM + u * 8);
    }
    const __half* wh = g_WPH + (size_t)h * 72 * NLAND + n0;
    const __half* wl = g_WPL + (size_t)h * 72 * NLAND + n0;
    for (int i = tid; i < 1152; i += 256) {
        int row = i >> 4, u = i & 15;
        cp16(sb + OFF_WH + row * SW_B + u * 16, wh + (size_t)row * NLAND + u * 8);
        cp16(sb + OFF_WL + row * SW_B + u * 16, wl + (size_t)row * NLAND + u * 8);
    }
    if (tid < 32)
        cp16(sb + OFF_CR2 + tid * 16, g_cR2 + h * NLAND + n0 + tid * 4);
}

__global__ void __launch_bounds__(256, 1)
fused_mma(const float* __restrict__ z)
{
    extern __shared__ __align__(16) char smem[];
    const int tid  = threadIdx.x;
    const int warp = tid >> 5;
    const int lane = tid & 31;
    const int h    = blockIdx.y;
    const int row0 = blockIdx.x * 128;
    const int g    = lane >> 2;
    const int t4   = lane & 3;
    const int wrow = warp * 16;
    const uint32_t sbase = smem_u32(smem);

    const int n_add = ((lane >> 4) & 1) * 8 + (lane & 7);
    const int k_add = ((lane >> 3) & 1) * 8;
    const uint32_t laneR = (uint32_t)(n_add * SR_B + k_add * 2);
    const uint32_t laneW = (uint32_t)(n_add * SW_B + k_add * 2);

    issue_tile_loads(smem, 0, h, 0, tid);
    CP_COMMIT();

    // ---- stage z fp32 into buf1 region; build fp16 A-frags (single) ----
    float* zstage = (float*)(smem + BUF_B);     // [128][68]
    {
        const float4* zsrc = reinterpret_cast<const float4*>(z);
        #pragma unroll
        for (int i = tid; i < 2048; i += 256) {
            int r = i >> 4, c4 = i & 15;
            float4 v = zsrc[(((size_t)(row0 + r) * NHEAD + h) * DIM >> 2) + c4];
            *reinterpret_cast<float4*>(zstage + r * 68 + c4 * 4) = v;
        }
    }
    __syncthreads();

    const int r0 = wrow + g, r1 = r0 + 8;
    float z2a = 0.f, z2b = 0.f;
    #pragma unroll
    for (int k = 0; k < DIM; k++) {
        float va = zstage[r0 * 68 + k];
        float vb = zstage[r1 * 68 + k];
        z2a += va * va; z2b += vb * vb;
    }
    // per-row deflation factor e^{-z^2/2} (fp32; ~1e-24 worst case, safe)
    const float esca = ex2f(C2EXP * z2a);
    const float escb = ex2f(C2EXP * z2b);

    uint32_t zh[4][4];
    #pragma unroll
    for (int kc = 0; kc < 4; kc++) {
        int k0 = kc * 16 + 2 * t4;
        zh[kc][0] = pack_h2(zstage[r0 * 68 + k0],     zstage[r0 * 68 + k0 + 1]);
        zh[kc][1] = pack_h2(zstage[r1 * 68 + k0],     zstage[r1 * 68 + k0 + 1]);
        zh[kc][2] = pack_h2(zstage[r0 * 68 + k0 + 8], zstage[r0 * 68 + k0 + 9]);
        zh[kc][3] = pack_h2(zstage[r1 * 68 + k0 + 8], zstage[r1 * 68 + k0 + 9]);
    }
    __syncthreads();   // buf1 free before tile-1 cp.async

    float y[8][4];     // y accumulators (64 dh)
    float yp[4];       // p-columns accumulator (cols 64-71 block)
    #pragma unroll
    for (int nt = 0; nt < 8; nt++)
        #pragma unroll
        for (int e = 0; e < 4; e++) y[nt][e] = 0.f;
    #pragma unroll
    for (int e = 0; e < 4; e++) yp[e] = 0.f;

    for (int t = 0; t < 16; t++) {
        const int cur = t & 1;
        if (t < 15) {
            issue_tile_loads(smem, cur ^ 1, h, (t + 1) * 128, tid);
            CP_COMMIT();
            CP_WAIT1();
        } else {
            CP_WAIT0();
        }
        __syncthreads();

        const uint32_t sb  = sbase + (uint32_t)cur * BUF_B;
        const uint32_t rbH = sb + OFF_RH + laneR;
        const uint32_t rbL = sb + OFF_RL + laneR;
        const float* crp = (const float*)(smem + cur * BUF_B + OFF_CR2);

        // ---- GEMM1: fp16, z single x R hi/lo (2-pass) ----
        float c[16][4];
        #pragma unroll
        for (int nt = 0; nt < 16; nt++)
            #pragma unroll
            for (int e = 0; e < 4; e++) c[nt][e] = 0.f;

        #pragma unroll
        for (int kc = 0; kc < 4; kc++) {
            #pragma unroll
            for (int ntp = 0; ntp < 8; ntp++) {
                uint32_t off = (uint32_t)(ntp * 16) * SR_B + (uint32_t)kc * 32;
                uint32_t rh[4], rl[4];
                ldm_x4(rh, rbH + off);
                ldm_x4(rl, rbL + off);
                mma_f16(c[2 * ntp],     zh[kc], rh[0], rh[1]);
                mma_f16(c[2 * ntp + 1], zh[kc], rh[2], rh[3]);
                mma_f16(c[2 * ntp],     zh[kc], rl[0], rl[1]);
                mma_f16(c[2 * ntp + 1], zh[kc], rl[2], rl[3]);
            }
        }

        // ---- epilogue: K' = 2^min(s*log2e + cR2, 15)  (row-shifted kernel) ----
        const uint32_t wbH = sb + OFF_WH + laneW;
        const uint32_t wbL = sb + OFF_WL + laneW;
        #pragma unroll
        for (int kch = 0; kch < 8; kch++) {
            const int ct0 = 2 * kch, ct1 = 2 * kch + 1;
            const int col0 = ct0 * 8 + 2 * t4;
            const int col1 = ct1 * 8 + 2 * t4;
            float cr0 = crp[col0], cr1 = crp[col0 + 1];
            float cr2 = crp[col1], cr3 = crp[col1 + 1];

            float K00 = ex2f(fminf(fmaf(c[ct0][0], LOG2E, cr0), 15.f));
            float K01 = ex2f(fminf(fmaf(c[ct0][1], LOG2E, cr1), 15.f));
            float K02 = ex2f(fminf(fmaf(c[ct0][2], LOG2E, cr0), 15.f));
            float K03 = ex2f(fminf(fmaf(c[ct0][3], LOG2E, cr1), 15.f));
            float K10 = ex2f(fminf(fmaf(c[ct1][0], LOG2E, cr2), 15.f));
            float K11 = ex2f(fminf(fmaf(c[ct1][1], LOG2E, cr3), 15.f));
            float K12 = ex2f(fminf(fmaf(c[ct1][2], LOG2E, cr2), 15.f));
            float K13 = ex2f(fminf(fmaf(c[ct1][3], LOG2E, cr3), 15.f));

            uint32_t a[4];
            a[0] = pack_h2(K00, K01);
            a[1] = pack_h2(K02, K03);
            a[2] = pack_h2(K10, K11);
            a[3] = pack_h2(K12, K13);

            uint32_t kcOff = (uint32_t)kch * 32;
            uint32_t w0[4], w1[4], w2[4], w3[4], wp[2];
            // hi pass
            ldm_x4(w0, wbH + kcOff);
            ldm_x4(w1, wbH + 16 * SW_B + kcOff);
            ldm_x4(w2, wbH + 32 * SW_B + kcOff);
            ldm_x4(w3, wbH + 48 * SW_B + kcOff);
            ldm_x2(wp, wbH + 64 * SW_B + kcOff);
            mma_f16(y[0], a, w0[0], w0[1]);
            mma_f16(y[1], a, w0[2], w0[3]);
            mma_f16(y[2], a, w1[0], w1[1]);
            mma_f16(y[3], a, w1[2], w1[3]);
            mma_f16(y[4], a, w2[0], w2[1]);
            mma_f16(y[5], a, w2[2], w2[3]);
            mma_f16(y[6], a, w3[0], w3[1]);
            mma_f16(y[7], a, w3[2], w3[3]);
            mma_f16(yp,   a, wp[0], wp[1]);
            // lo pass
            ldm_x4(w0, wbL + kcOff);
            ldm_x4(w1, wbL + 16 * SW_B + kcOff);
            ldm_x4(w2, wbL + 32 * SW_B + kcOff);
            ldm_x4(w3, wbL + 48 * SW_B + kcOff);
            ldm_x2(wp, wbL + 64 * SW_B + kcOff);
            mma_f16(y[0], a, w0[0], w0[1]);
            mma_f16(y[1], a, w0[2], w0[3]);
            mma_f16(y[2], a, w1[0], w1[1]);
            mma_f16(y[3], a, w1[2], w1[3]);
            mma_f16(y[4], a, w2[0], w2[1]);
            mma_f16(y[5], a, w2[2], w2[3]);
            mma_f16(y[6], a, w3[0], w3[1]);
            mma_f16(y[7], a, w3[2], w3[3]);
            mma_f16(yp,   a, wp[0], wp[1]);
        }
        __syncthreads();
    }

    // ---- p1'/p2' live in yp of t4==0 lanes (cols 64,65); broadcast ----
    int src = lane & 28;
    float P1a = __shfl_sync(0xffffffffu, yp[0], src);
    float P2a = __shfl_sync(0xffffffffu, yp[1], src);
    float P1b = __shfl_sync(0xffffffffu, yp[2], src);
    float P2b = __shfl_sync(0xffffffffu, yp[3], src);

    // deflate to unscaled sums, replicate reference clamps exactly in fp32
    float p1a = esca * P1a, p2a = esca * P2a;
    float p1b = escb * P1b, p2b = escb * P2b;
    float cc0 = rsqrtf(fmaxf(p1a, EPS_C));
    float cc1 = rsqrtf(fmaxf(p1b, EPS_C));
    float f0  = cc0 / fmaxf(cc0 * p2a, EPS_C) * esca;   // applies to y' (scaled)
    float f1  = cc1 / fmaxf(cc1 * p2b, EPS_C) * escb;

    // ---- write y as single fp16 ----
    size_t o0 = (size_t)(row0 + r0) * DOUT + h * DIM + 2 * t4;
    size_t o1 = (size_t)(row0 + r1) * DOUT + h * DIM + 2 * t4;
    #pragma unroll
    for (int nt = 0; nt < 8; nt++) {
        *reinterpret_cast<uint32_t*>(g_Y + o0 + nt * 8) =
            pack_h2(y[nt][0] * f0, y[nt][1] * f0);
        *reinterpret_cast<uint32_t*>(g_Y + o1 + nt * 8) =
            pack_h2(y[nt][2] * f1, y[nt][3] * f1);
    }
}

// ---------------------------------------------------------------------------
// out = y @ W_O + b_O : fp16, A single, B hi/lo 2-pass. 128x128 tiles.
// ---------------------------------------------------------------------------
#define OB_STRIDE 144u
#define OB_A      0u
#define OB_BH     18432u
#define OB_BL     36864u
#define OB_BUF    55296u
#define OUT_SMEM  (2u * OB_BUF)          // 110592

__device__ __forceinline__ void issue_out_loads(char* smem, int buf, int row0,
                                                int col0, int k0, int tid)
{
    uint32_t sb = smem_u32(smem) + (uint32_t)buf * OB_BUF;
    #pragma unroll
    for (int i = tid; i < 1024; i += 256) {
        int row = i >> 3, u = i & 7;
        cp16(sb + OB_A  + row * OB_STRIDE + u * 16,
             g_Y + (size_t)(row0 + row) * DOUT + k0 + u * 8);
        size_t gb = (size_t)(col0 + row) * DOUT + k0 + u * 8;
        cp16(sb + OB_BH + row * OB_STRIDE + u * 16, g_WOH + gb);
        cp16(sb + OB_BL + row * OB_STRIDE + u * 16, g_WOL + gb);
    }
}

__global__ void __launch_bounds__(256, 1)
out_tc(const float* __restrict__ bO, float* __restrict__ out)
{
    extern __shared__ __align__(16) char smem[];
    const int tid  = threadIdx.x;
    const int warp = tid >> 5;
    const int lane = tid & 31;
    const int row0 = blockIdx.x * 128;
    const int col0 = blockIdx.y * 128;
    const int g    = lane >> 2;
    const int t4   = lane & 3;
    const int wrow = warp * 16;
    const uint32_t sbase = smem_u32(smem);

    const int n_add = ((lane >> 4) & 1) * 8 + (lane & 7);
    const int k_add = ((lane >> 3) & 1) * 8;
    const uint32_t laneO = (uint32_t)(n_add * OB_STRIDE + k_add * 2);

    issue_out_loads(smem, 0, row0, col0, 0, tid);
    CP_COMMIT();

    float y[16][4];
    #pragma unroll
    for (int nt = 0; nt < 16; nt++)
        #pragma unroll
        for (int e = 0; e < 4; e++) y[nt][e] = 0.f;

    for (int kb = 0; kb < 8; kb++) {
        const int cur = kb & 1;
        if (kb < 7) {
            issue_out_loads(smem, cur ^ 1, row0, col0, (kb + 1) * 64, tid);
            CP_COMMIT();
            CP_WAIT1();
        } else {
            CP_WAIT0();
        }
        __syncthreads();

        const uint32_t sb = sbase + (uint32_t)cur * OB_BUF;
        const uint32_t aA = sb + OB_A  + (uint32_t)wrow * OB_STRIDE + laneO;
        const uint32_t bH = sb + OB_BH + laneO;
        const uint32_t bL = sb + OB_BL + laneO;

        #pragma unroll
        for (int kc = 0; kc < 4; kc++) {
            uint32_t ta[4];
            ldm_x4(ta, aA + kc * 32);
            uint32_t a[4] = {ta[0], ta[2], ta[1], ta[3]};   // validated permute

            #pragma unroll
            for (int np = 0; np < 4; np++) {
                uint32_t oA = (uint32_t)((2 * np) * 16) * OB_STRIDE + (uint32_t)kc * 32;
                uint32_t oB = (uint32_t)((2 * np + 1) * 16) * OB_STRIDE + (uint32_t)kc * 32;
                uint32_t whA[4], wlA[4], whB[4], wlB[4];
                ldm_x4(whA, bH + oA);
                ldm_x4(wlA, bL + oA);
                ldm_x4(whB, bH + oB);
                ldm_x4(wlB, bL + oB);
                float* y0 = y[4 * np + 0];
                float* y1 = y[4 * np + 1];
                float* y2 = y[4 * np + 2];
                float* y3 = y[4 * np + 3];
                mma_f16(y0, a, whA[0], whA[1]);
                mma_f16(y1, a, whA[2], whA[3]);
                mma_f16(y2, a, whB[0], whB[1]);
                mma_f16(y3, a, whB[2], whB[3]);
                mma_f16(y0, a, wlA[0], wlA[1]);
                mma_f16(y1, a, wlA[2], wlA[3]);
                mma_f16(y2, a, wlB[0], wlB[1]);
                mma_f16(y3, a, wlB[2], wlB[3]);
            }
        }
        __syncthreads();
    }

    const int r0 = row0 + wrow + g, r1 = r0 + 8;
    #pragma unroll
    for (int nt = 0; nt < 16; nt++) {
        int col = col0 + nt * 8 + 2 * t4;
        float b0 = bO[col], b1 = bO[col + 1];
        *reinterpret_cast<float2*>(out + (size_t)r0 * DOUT + col) =
            make_float2(y[nt][0] + b0, y[nt][1] + b1);
        *reinterpret_cast<float2*>(out + (size_t)r1 * DOUT + col) =
            make_float2(y[nt][2] + b0, y[nt][3] + b1);
    }
}

// ---------------------------------------------------------------------------
extern "C" void kernel_launch(void* const* d_in, const int* in_sizes, int n_in,
                              void* d_out, int out_size)
{
    const float* z  = (const float*)d_in[0];   // (4,1024,8,64)
    const float* R  = (const float*)d_in[1];   // (8,2048,64)
    const float* q  = (const float*)d_in[2];   // (8,2048)
    const float* W  = (const float*)d_in[3];   // (8,2048,64)
    const float* WO = (const float*)d_in[4];   // (512,512)
    const float* bO = (const float*)d_in[5];   // (512)
    float* out = (float*)d_out;                // (4,1024,512)
    (void)in_sizes; (void)n_in; (void)out_size;

    cudaFuncSetAttribute(fused_mma, cudaFuncAttributeMaxDynamicSharedMemorySize,
                         SMEM_BYTES);
    cudaFuncSetAttribute(out_tc, cudaFuncAttributeMaxDynamicSharedMemorySize,
                         OUT_SMEM);

    prep_land<<<NHEAD * NLAND / 8, 256>>>(R, q);
    prep_wp<<<NHEAD * (NLAND / 64), 256>>>(W);   // after prep_land (reads g_qa)
    prep_wo<<<64, 256>>>(WO);

    dim3 gridF(BS_ROWS / 128, NHEAD);          // (32, 8)
    fused_mma<<<gridF, 256, SMEM_BYTES>>>(z);

    dim3 gridO(BS_ROWS / 128, DOUT / 128);     // (32, 4)
    out_tc<<<gridO, 256, OUT_SMEM>>>(bO, out);
}

// round 11
// speedup vs baseline: 1.7910x; 1.1721x over previous
#include <cuda_runtime.h>
#include <cuda_fp16.h>
#include <cstdint>

// ---------------------------------------------------------------------------
// Problem constants
// ---------------------------------------------------------------------------
#define BS_ROWS 4096      // B*S
#define NHEAD   8
#define DIM     64        // d == D_head
#define NLAND   2048      // landmarks per head
#define DOUT    512
#define EPS_C   1e-12f
#define C2EXP   (-0.72134752044448f)    // -0.5 * log2(e)
#define LOG2E   (1.44269504088896f)

// ---------------------------------------------------------------------------
// Device-global scratch
// K' = K * e^{+z^2/2} row-shift keeps the GEMM2 operand fp16-legal; the shift
// cancels analytically and is undone in fp32 with the reference's clamps.
// ---------------------------------------------------------------------------
__device__ float  g_cR2[NHEAD * NLAND];                 // C2EXP * ||R_n||^2
__device__ float  g_qa [NHEAD * NLAND];                 // (relu(q)+eps)^(-1/2)
__device__ __half g_RH[NHEAD * NLAND * DIM];            // R fp16 [h][n][d] (single)
__device__ __half g_WPH[NHEAD * 72 * NLAND];            // W' hi [h][72][n] fp16
__device__ __half g_WPL[NHEAD * 72 * NLAND];            // rows 0-63: qa*W^T; 64: 1; 65: qa; 66-71: 0
__device__ __half g_Y [BS_ROWS * DOUT];                 // y fp16 [row][col]
__device__ __half g_WOH[DOUT * DOUT];                   // W_O^T hi [col][k] fp16
__device__ __half g_WOL[DOUT * DOUT];                   // W_O^T lo fp16

// ---------------------------------------------------------------------------
// PTX helpers
// ---------------------------------------------------------------------------
__device__ __forceinline__ uint32_t smem_u32(const void* p) {
    return (uint32_t)__cvta_generic_to_shared(p);
}
__device__ __forceinline__ void cp16(uint32_t s, const void* g) {
    asm volatile("cp.async.cg.shared.global [%0], [%1], 16;" :: "r"(s), "l"(g));
}
#define CP_COMMIT() asm volatile("cp.async.commit_group;" ::: "memory")
#define CP_WAIT1()  asm volatile("cp.async.wait_group 1;" ::: "memory")
#define CP_WAIT0()  asm volatile("cp.async.wait_group 0;" ::: "memory")

__device__ __forceinline__ void ldm_x4(uint32_t* f, uint32_t addr) {
    asm volatile("ldmatrix.sync.aligned.m8n8.x4.shared.b16 {%0,%1,%2,%3}, [%4];"
        : "=r"(f[0]), "=r"(f[1]), "=r"(f[2]), "=r"(f[3]) : "r"(addr));
}
__device__ __forceinline__ void ldm_x2(uint32_t* f, uint32_t addr) {
    asm volatile("ldmatrix.sync.aligned.m8n8.x2.shared.b16 {%0,%1}, [%2];"
        : "=r"(f[0]), "=r"(f[1]) : "r"(addr));
}
__device__ __forceinline__ void mma_f16(float* c, const uint32_t* a,
                                        uint32_t b0, uint32_t b1) {
    asm volatile(
        "mma.sync.aligned.m16n8k16.row.col.f32.f16.f16.f32 "
        "{%0,%1,%2,%3}, {%4,%5,%6,%7}, {%8,%9}, {%0,%1,%2,%3};"
        : "+f"(c[0]), "+f"(c[1]), "+f"(c[2]), "+f"(c[3])
        : "r"(a[0]), "r"(a[1]), "r"(a[2]), "r"(a[3]), "r"(b0), "r"(b1));
}
__device__ __forceinline__ uint32_t pack_h2(float a, float b) {
    __half2 h = __float22half2_rn(make_float2(a, b));
    return *reinterpret_cast<uint32_t*>(&h);
}
__device__ __forceinline__ float ex2f(float x) {
    float r; asm("ex2.approx.ftz.f32 %0, %1;" : "=f"(r) : "f"(x)); return r;
}

// ---------------------------------------------------------------------------
// Fused SMEM layout (per buffer) — RL region removed vs R9
// ---------------------------------------------------------------------------
#define SR_B     144u     // R tile [128 n][64 k] fp16
#define SW_B     272u     // W' tile [72 dh][128 n] fp16
#define OFF_RH   0u       // 18432 B
#define OFF_WH   18432u   // 19584 B
#define OFF_WL   38016u   // 19584 B
#define OFF_CR2  57600u   // float[128]
#define BUF_B    58112u
#define SMEM_BYTES (2u * BUF_B)    // 116224

// ---------------------------------------------------------------------------
// Prep 1: cR2, qa, fp16 R (single-rounded). warp per landmark.
// ---------------------------------------------------------------------------
__global__ void __launch_bounds__(256)
prep_land(const float* __restrict__ R, const float* __restrict__ q)
{
    int wid  = threadIdx.x >> 5, lane = threadIdx.x & 31;
    int idx  = blockIdx.x * 8 + wid;
    const float* r = R + (size_t)idx * DIM;
    float v0 = r[lane], v1 = r[lane + 32];
    g_RH[(size_t)idx * DIM + lane]      = __float2half_rn(v0);
    g_RH[(size_t)idx * DIM + lane + 32] = __float2half_rn(v1);
    float s = v0 * v0 + v1 * v1;
    #pragma unroll
    for (int m = 16; m >= 1; m >>= 1) s += __shfl_xor_sync(0xffffffffu, s, m);
    if (lane == 0) {
        g_cR2[idx] = C2EXP * s;
        float qq = q[idx];
        qq = (qq > 0.f ? qq : 0.f) + EPS_C;
        g_qa[idx] = rsqrtf(qq);
    }
}

// ---------------------------------------------------------------------------
// Prep 2: W' = [qa*W^T ; ones ; qa ; zeros] fp16 hi/lo [h][72][n]
// Must run AFTER prep_land (reads g_qa).
// ---------------------------------------------------------------------------
__global__ void __launch_bounds__(256)
prep_wp(const float* __restrict__ W)
{
    __shared__ float sm[64][65];
    __shared__ float sqa[64];
    int h  = blockIdx.x >> 5;
    int n0 = (blockIdx.x & 31) * 64;
    for (int t = threadIdx.x; t < 4096; t += 256) {
        int i = t >> 6, d = t & 63;
        sm[i][d] = W[((size_t)(h * NLAND + n0 + i)) * DIM + d];
    }
    if (threadIdx.x < 64) sqa[threadIdx.x] = g_qa[h * NLAND + n0 + threadIdx.x];
    __syncthreads();
    for (int t = threadIdx.x; t < 4096; t += 256) {
        int d = t >> 6, i = t & 63;
        float v = sm[i][d] * sqa[i];
        __half hh = __float2half_rn(v);
        size_t o = ((size_t)h * 72 + d) * NLAND + n0 + i;
        g_WPH[o] = hh;
        g_WPL[o] = __float2half_rn(v - __half2float(hh));
    }
    for (int t = threadIdx.x; t < 64 * 8; t += 256) {
        int rr = 64 + (t >> 6), i = t & 63;
        float v = (rr == 64) ? 1.0f : (rr == 65 ? sqa[i] : 0.0f);
        __half hh = __float2half_rn(v);
        size_t o = ((size_t)h * 72 + rr) * NLAND + n0 + i;
        g_WPH[o] = hh;
        g_WPL[o] = __float2half_rn(v - __half2float(hh));
    }
}

// ---------------------------------------------------------------------------
// Prep 3: W_O^T fp16 hi/lo [col][k]
// ---------------------------------------------------------------------------
__global__ void __launch_bounds__(256)
prep_wo(const float* __restrict__ WO)
{
    __shared__ float sm[64][65];
    int kb = blockIdx.x >> 3, cb = blockIdx.x & 7;
    int k0 = kb * 64, c0 = cb * 64;
    for (int t = threadIdx.x; t < 4096; t += 256) {
        int i = t >> 6, d = t & 63;
        sm[i][d] = WO[(size_t)(k0 + i) * DOUT + c0 + d];
    }
    __syncthreads();
    for (int t = threadIdx.x; t < 4096; t += 256) {
        int d = t >> 6, i = t & 63;
        float v = sm[i][d];
        __half hh = __float2half_rn(v);
        size_t o = (size_t)(c0 + d) * DOUT + k0 + i;
        g_WOH[o] = hh;
        g_WOL[o] = __float2half_rn(v - __half2float(hh));
    }
}

// ---------------------------------------------------------------------------
// Fused kernel: one CTA per (head, 128-row block), 256 threads (R4 schedule).
// ---------------------------------------------------------------------------
__device__ __forceinline__ void issue_tile_loads(char* smem, int buf, int h, int n0,
                                                 int tid)
{
    uint32_t sb = smem_u32(smem) + (uint32_t)buf * BUF_B;
    const __half* rh = g_RH + ((size_t)h * NLAND + n0) * DIM;
    #pragma unroll
    for (int i = tid; i < 1024; i += 256) {
        int row = i >> 3, u = i & 7;
        cp16(sb + OFF_RH + row * SR_B + u * 16, rh + row * DIM + u * 8);
    }
    const __half* wh = g_WPH + (size_t)h * 72 * NLAND + n0;
    const __half* wl = g_WPL + (size_t)h * 72 * NLAND + n0;
    for (int i = tid; i < 1152; i += 256) {
        int row = i >> 4, u = i & 15;
        cp16(sb + OFF_WH + row * SW_B + u * 16, wh + (size_t)row * NLAND + u * 8);
        cp16(sb + OFF_WL + row * SW_B + u * 16, wl + (size_t)row * NLAND + u * 8);
    }
    if (tid < 32)
        cp16(sb + OFF_CR2 + tid * 16, g_cR2 + h * NLAND + n0 + tid * 4);
}

__global__ void __launch_bounds__(256, 1)
fused_mma(const float* __restrict__ z)
{
    extern __shared__ __align__(16) char smem[];
    const int tid  = threadIdx.x;
    const int warp = tid >> 5;
    const int lane = tid & 31;
    const int h    = blockIdx.y;
    const int row0 = blockIdx.x * 128;
    const int g    = lane >> 2;
    const int t4   = lane & 3;
    const int wrow = warp * 16;
    const uint32_t sbase = smem_u32(smem);

    const int n_add = ((lane >> 4) & 1) * 8 + (lane & 7);
    const int k_add = ((lane >> 3) & 1) * 8;
    const uint32_t laneR = (uint32_t)(n_add * SR_B + k_add * 2);
    const uint32_t laneW = (uint32_t)(n_add * SW_B + k_add * 2);

    issue_tile_loads(smem, 0, h, 0, tid);
    CP_COMMIT();

    // ---- stage z fp32 into buf1 region; build fp16 A-frags (single) ----
    float* zstage = (float*)(smem + BUF_B);     // [128][68] = 34816 B < BUF_B
    {
        const float4* zsrc = reinterpret_cast<const float4*>(z);
        #pragma unroll
        for (int i = tid; i < 2048; i += 256) {
            int r = i >> 4, c4 = i & 15;
            float4 v = zsrc[(((size_t)(row0 + r) * NHEAD + h) * DIM >> 2) + c4];
            *reinterpret_cast<float4*>(zstage + r * 68 + c4 * 4) = v;
        }
    }
    __syncthreads();

    const int r0 = wrow + g, r1 = r0 + 8;
    float z2a = 0.f, z2b = 0.f;
    #pragma unroll
    for (int k = 0; k < DIM; k++) {
        float va = zstage[r0 * 68 + k];
        float vb = zstage[r1 * 68 + k];
        z2a += va * va; z2b += vb * vb;
    }
    // per-row deflation factor e^{-z^2/2} (fp32)
    const float esca = ex2f(C2EXP * z2a);
    const float escb = ex2f(C2EXP * z2b);

    uint32_t zh[4][4];
    #pragma unroll
    for (int kc = 0; kc < 4; kc++) {
        int k0 = kc * 16 + 2 * t4;
        zh[kc][0] = pack_h2(zstage[r0 * 68 + k0],     zstage[r0 * 68 + k0 + 1]);
        zh[kc][1] = pack_h2(zstage[r1 * 68 + k0],     zstage[r1 * 68 + k0 + 1]);
        zh[kc][2] = pack_h2(zstage[r0 * 68 + k0 + 8], zstage[r0 * 68 + k0 + 9]);
        zh[kc][3] = pack_h2(zstage[r1 * 68 + k0 + 8], zstage[r1 * 68 + k0 + 9]);
    }
    __syncthreads();   // buf1 free before tile-1 cp.async

    float y[8][4];     // y accumulators (64 dh)
    float yp[4];       // p-columns accumulator (cols 64-71 block)
    #pragma unroll
    for (int nt = 0; nt < 8; nt++)
        #pragma unroll
        for (int e = 0; e < 4; e++) y[nt][e] = 0.f;
    #pragma unroll
    for (int e = 0; e < 4; e++) yp[e] = 0.f;

    for (int t = 0; t < 16; t++) {
        const int cur = t & 1;
        if (t < 15) {
            issue_tile_loads(smem, cur ^ 1, h, (t + 1) * 128, tid);
            CP_COMMIT();
            CP_WAIT1();
        } else {
            CP_WAIT0();
        }
        __syncthreads();

        const uint32_t sb  = sbase + (uint32_t)cur * BUF_B;
        const uint32_t rbH = sb + OFF_RH + laneR;
        const float* crp = (const float*)(smem + cur * BUF_B + OFF_CR2);

        // ---- GEMM1: fp16 single-pass z x R ----
        float c[16][4];
        #pragma unroll
        for (int nt = 0; nt < 16; nt++)
            #pragma unroll
            for (int e = 0; e < 4; e++) c[nt][e] = 0.f;

        #pragma unroll
        for (int kc = 0; kc < 4; kc++) {
            #pragma unroll
            for (int ntp = 0; ntp < 8; ntp++) {
                uint32_t off = (uint32_t)(ntp * 16) * SR_B + (uint32_t)kc * 32;
                uint32_t rh[4];
                ldm_x4(rh, rbH + off);
                mma_f16(c[2 * ntp],     zh[kc], rh[0], rh[1]);
                mma_f16(c[2 * ntp + 1], zh[kc], rh[2], rh[3]);
            }
        }

        // ---- epilogue: K' = 2^min(s*log2e + cR2, 15)  (row-shifted kernel) ----
        const uint32_t wbH = sb + OFF_WH + laneW;
        const uint32_t wbL = sb + OFF_WL + laneW;
        #pragma unroll
        for (int kch = 0; kch < 8; kch++) {
            const int ct0 = 2 * kch, ct1 = 2 * kch + 1;
            const int col0 = ct0 * 8 + 2 * t4;
            const int col1 = ct1 * 8 + 2 * t4;
            float cr0 = crp[col0], cr1 = crp[col0 + 1];
            float cr2 = crp[col1], cr3 = crp[col1 + 1];

            float K00 = ex2f(fminf(fmaf(c[ct0][0], LOG2E, cr0), 15.f));
            float K01 = ex2f(fminf(fmaf(c[ct0][1], LOG2E, cr1), 15.f));
            float K02 = ex2f(fminf(fmaf(c[ct0][2], LOG2E, cr0), 15.f));
            float K03 = ex2f(fminf(fmaf(c[ct0][3], LOG2E, cr1), 15.f));
            float K10 = ex2f(fminf(fmaf(c[ct1][0], LOG2E, cr2), 15.f));
            float K11 = ex2f(fminf(fmaf(c[ct1][1], LOG2E, cr3), 15.f));
            float K12 = ex2f(fminf(fmaf(c[ct1][2], LOG2E, cr2), 15.f));
            float K13 = ex2f(fminf(fmaf(c[ct1][3], LOG2E, cr3), 15.f));

            uint32_t a[4];
            a[0] = pack_h2(K00, K01);
            a[1] = pack_h2(K02, K03);
            a[2] = pack_h2(K10, K11);
            a[3] = pack_h2(K12, K13);

            uint32_t kcOff = (uint32_t)kch * 32;
            uint32_t w0[4], w1[4], w2[4], w3[4], wp[2];
            // hi pass
            ldm_x4(w0, wbH + kcOff);
            ldm_x4(w1, wbH + 16 * SW_B + kcOff);
            ldm_x4(w2, wbH + 32 * SW_B + kcOff);
            ldm_x4(w3, wbH + 48 * SW_B + kcOff);
            ldm_x2(wp, wbH + 64 * SW_B + kcOff);
            mma_f16(y[0], a, w0[0], w0[1]);
            mma_f16(y[1], a, w0[2], w0[3]);
            mma_f16(y[2], a, w1[0], w1[1]);
            mma_f16(y[3], a, w1[2], w1[3]);
            mma_f16(y[4], a, w2[0], w2[1]);
            mma_f16(y[5], a, w2[2], w2[3]);
            mma_f16(y[6], a, w3[0], w3[1]);
            mma_f16(y[7], a, w3[2], w3[3]);
            mma_f16(yp,   a, wp[0], wp[1]);
            // lo pass
            ldm_x4(w0, wbL + kcOff);
            ldm_x4(w1, wbL + 16 * SW_B + kcOff);
            ldm_x4(w2, wbL + 32 * SW_B + kcOff);
            ldm_x4(w3, wbL + 48 * SW_B + kcOff);
            ldm_x2(wp, wbL + 64 * SW_B + kcOff);
            mma_f16(y[0], a, w0[0], w0[1]);
            mma_f16(y[1], a, w0[2], w0[3]);
            mma_f16(y[2], a, w1[0], w1[1]);
            mma_f16(y[3], a, w1[2], w1[3]);
            mma_f16(y[4], a, w2[0], w2[1]);
            mma_f16(y[5], a, w2[2], w2[3]);
            mma_f16(y[6], a, w3[0], w3[1]);
            mma_f16(y[7], a, w3[2], w3[3]);
            mma_f16(yp,   a, wp[0], wp[1]);
        }
        __syncthreads();
    }

    // ---- p1'/p2' live in yp of t4==0 lanes (cols 64,65); broadcast ----
    int src = lane & 28;
    float P1a = __shfl_sync(0xffffffffu, yp[0], src);
    float P2a = __shfl_sync(0xffffffffu, yp[1], src);
    float P1b = __shfl_sync(0xffffffffu, yp[2], src);
    float P2b = __shfl_sync(0xffffffffu, yp[3], src);

    // deflate to unscaled sums, replicate reference clamps exactly in fp32
    float p1a = esca * P1a, p2a = esca * P2a;
    float p1b = escb * P1b, p2b = escb * P2b;
    float cc0 = rsqrtf(fmaxf(p1a, EPS_C));
    float cc1 = rsqrtf(fmaxf(p1b, EPS_C));
    float f0  = cc0 / fmaxf(cc0 * p2a, EPS_C) * esca;   // applies to y' (scaled)
    float f1  = cc1 / fmaxf(cc1 * p2b, EPS_C) * escb;

    // ---- write y as single fp16 ----
    size_t o0 = (size_t)(row0 + r0) * DOUT + h * DIM + 2 * t4;
    size_t o1 = (size_t)(row0 + r1) * DOUT + h * DIM + 2 * t4;
    #pragma unroll
    for (int nt = 0; nt < 8; nt++) {
        *reinterpret_cast<uint32_t*>(g_Y + o0 + nt * 8) =
            pack_h2(y[nt][0] * f0, y[nt][1] * f0);
        *reinterpret_cast<uint32_t*>(g_Y + o1 + nt * 8) =
            pack_h2(y[nt][2] * f1, y[nt][3] * f1);
    }
}

// ---------------------------------------------------------------------------
// out = y @ W_O + b_O : fp16, A single, B hi/lo 2-pass. 128x128 tiles.
// ---------------------------------------------------------------------------
#define OB_STRIDE 144u
#define OB_A      0u
#define OB_BH     18432u
#define OB_BL     36864u
#define OB_BUF    55296u
#define OUT_SMEM  (2u * OB_BUF)          // 110592

__device__ __forceinline__ void issue_out_loads(char* smem, int buf, int row0,
                                                int col0, int k0, int tid)
{
    uint32_t sb = smem_u32(smem) + (uint32_t)buf * OB_BUF;
    #pragma unroll
    for (int i = tid; i < 1024; i += 256) {
        int row = i >> 3, u = i & 7;
        cp16(sb + OB_A  + row * OB_STRIDE + u * 16,
             g_Y + (size_t)(row0 + row) * DOUT + k0 + u * 8);
        size_t gb = (size_t)(col0 + row) * DOUT + k0 + u * 8;
        cp16(sb + OB_BH + row * OB_STRIDE + u * 16, g_WOH + gb);
        cp16(sb + OB_BL + row * OB_STRIDE + u * 16, g_WOL + gb);
    }
}

__global__ void __launch_bounds__(256, 1)
out_tc(const float* __restrict__ bO, float* __restrict__ out)
{
    extern __shared__ __align__(16) char smem[];
    const int tid  = threadIdx.x;
    const int warp = tid >> 5;
    const int lane = tid & 31;
    const int row0 = blockIdx.x * 128;
    const int col0 = blockIdx.y * 128;
    const int g    = lane >> 2;
    const int t4   = lane & 3;
    const int wrow = warp * 16;
    const uint32_t sbase = smem_u32(smem);

    const int n_add = ((lane >> 4) & 1) * 8 + (lane & 7);
    const int k_add = ((lane >> 3) & 1) * 8;
    const uint32_t laneO = (uint32_t)(n_add * OB_STRIDE + k_add * 2);

    issue_out_loads(smem, 0, row0, col0, 0, tid);
    CP_COMMIT();

    float y[16][4];
    #pragma unroll
    for (int nt = 0; nt < 16; nt++)
        #pragma unroll
        for (int e = 0; e < 4; e++) y[nt][e] = 0.f;

    for (int kb = 0; kb < 8; kb++) {
        const int cur = kb & 1;
        if (kb < 7) {
            issue_out_loads(smem, cur ^ 1, row0, col0, (kb + 1) * 64, tid);
            CP_COMMIT();
            CP_WAIT1();
        } else {
            CP_WAIT0();
        }
        __syncthreads();

        const uint32_t sb = sbase + (uint32_t)cur * OB_BUF;
        const uint32_t aA = sb + OB_A  + (uint32_t)wrow * OB_STRIDE + laneO;
        const uint32_t bH = sb + OB_BH + laneO;
        const uint32_t bL = sb + OB_BL + laneO;

        #pragma unroll
        for (int kc = 0; kc < 4; kc++) {
            uint32_t ta[4];
            ldm_x4(ta, aA + kc * 32);
            uint32_t a[4] = {ta[0], ta[2], ta[1], ta[3]};   // validated permute

            #pragma unroll
            for (int np = 0; np < 4; np++) {
                uint32_t oA = (uint32_t)((2 * np) * 16) * OB_STRIDE + (uint32_t)kc * 32;
                uint32_t oB = (uint32_t)((2 * np + 1) * 16) * OB_STRIDE + (uint32_t)kc * 32;
                uint32_t whA[4], wlA[4], whB[4], wlB[4];
                ldm_x4(whA, bH + oA);
                ldm_x4(wlA, bL + oA);
                ldm_x4(whB, bH + oB);
                ldm_x4(wlB, bL + oB);
                float* y0 = y[4 * np + 0];
                float* y1 = y[4 * np + 1];
                float* y2 = y[4 * np + 2];
                float* y3 = y[4 * np + 3];
                mma_f16(y0, a, whA[0], whA[1]);
                mma_f16(y1, a, whA[2], whA[3]);
                mma_f16(y2, a, whB[0], whB[1]);
                mma_f16(y3, a, whB[2], whB[3]);
                mma_f16(y0, a, wlA[0], wlA[1]);
                mma_f16(y1, a, wlA[2], wlA[3]);
                mma_f16(y2, a, wlB[0], wlB[1]);
                mma_f16(y3, a, wlB[2], wlB[3]);
            }
        }
        __syncthreads();
    }

    const int r0 = row0 + wrow + g, r1 = r0 + 8;
    #pragma unroll
    for (int nt = 0; nt < 16; nt++) {
        int col = col0 + nt * 8 + 2 * t4;
        float b0 = bO[col], b1 = bO[col + 1];
        *reinterpret_cast<float2*>(out + (size_t)r0 * DOUT + col) =
            make_float2(y[nt][0] + b0, y[nt][1] + b1);
        *reinterpret_cast<float2*>(out + (size_t)r1 * DOUT + col) =
            make_float2(y[nt][2] + b0, y[nt][3] + b1);
    }
}

// ---------------------------------------------------------------------------
extern "C" void kernel_launch(void* const* d_in, const int* in_sizes, int n_in,
                              void* d_out, int out_size)
{
    const float* z  = (const float*)d_in[0];   // (4,1024,8,64)
    const float* R  = (const float*)d_in[1];   // (8,2048,64)
    const float* q  = (const float*)d_in[2];   // (8,2048)
    const float* W  = (const float*)d_in[3];   // (8,2048,64)
    const float* WO = (const float*)d_in[4];   // (512,512)
    const float* bO = (const float*)d_in[5];   // (512)
    float* out = (float*)d_out;                // (4,1024,512)
    (void)in_sizes; (void)n_in; (void)out_size;

    cudaFuncSetAttribute(fused_mma, cudaFuncAttributeMaxDynamicSharedMemorySize,
                         SMEM_BYTES);
    cudaFuncSetAttribute(out_tc, cudaFuncAttributeMaxDynamicSharedMemorySize,
                         OUT_SMEM);

    prep_land<<<NHEAD * NLAND / 8, 256>>>(R, q);
    prep_wp<<<NHEAD * (NLAND / 64), 256>>>(W);   // after prep_land (reads g_qa)
    prep_wo<<<64, 256>>>(WO);

    dim3 gridF(BS_ROWS / 128, NHEAD);          // (32, 8)
    fused_mma<<<gridF, 256, SMEM_BYTES>>>(z);

    dim3 gridO(BS_ROWS / 128, DOUT / 128);     // (32, 4)
    out_tc<<<gridO, 256, OUT_SMEM>>>(bO, out);
}

// round 12
// speedup vs baseline: 2.3049x; 1.2869x over previous
#include <cuda_runtime.h>
#include <cuda_fp16.h>
#include <cstdint>

// ---------------------------------------------------------------------------
// Problem constants
// ---------------------------------------------------------------------------
#define BS_ROWS 4096      // B*S
#define NHEAD   8
#define DIM     64        // d == D_head
#define NLAND   2048      // landmarks per head
#define DOUT    512
#define EPS_C   1e-12f
#define C2EXP   (-0.72134752044448f)    // -0.5 * log2(e)
#define LOG2E   (1.44269504088896f)

// ---------------------------------------------------------------------------
// Device-global scratch
// K' = K * e^{+z^2/2} row-shift keeps the GEMM2 operand fp16-legal; the shift
// cancels analytically and is undone in fp32 with the reference's clamps.
// ---------------------------------------------------------------------------
__device__ float  g_cR2[NHEAD * NLAND];                 // C2EXP * ||R_n||^2
__device__ float  g_qa [NHEAD * NLAND];                 // (relu(q)+eps)^(-1/2)
__device__ __half g_RH[NHEAD * NLAND * DIM];            // R fp16 [h][n][d] (single)
__device__ __half g_WPH[NHEAD * 72 * NLAND];            // W' fp16 [h][72][n] (single)
                                                        // rows 0-63: qa*W^T; 64: 1; 65: qa; 66-71: 0
__device__ __half g_Y [BS_ROWS * DOUT];                 // y fp16 [row][col]
__device__ __half g_WOH[DOUT * DOUT];                   // W_O^T hi [col][k] fp16
__device__ __half g_WOL[DOUT * DOUT];                   // W_O^T lo fp16

// ---------------------------------------------------------------------------
// PTX helpers
// ---------------------------------------------------------------------------
__device__ __forceinline__ uint32_t smem_u32(const void* p) {
    return (uint32_t)__cvta_generic_to_shared(p);
}
__device__ __forceinline__ void cp16(uint32_t s, const void* g) {
    asm volatile("cp.async.cg.shared.global [%0], [%1], 16;" :: "r"(s), "l"(g));
}
#define CP_COMMIT() asm volatile("cp.async.commit_group;" ::: "memory")
#define CP_WAIT1()  asm volatile("cp.async.wait_group 1;" ::: "memory")
#define CP_WAIT0()  asm volatile("cp.async.wait_group 0;" ::: "memory")

__device__ __forceinline__ void ldm_x4(uint32_t* f, uint32_t addr) {
    asm volatile("ldmatrix.sync.aligned.m8n8.x4.shared.b16 {%0,%1,%2,%3}, [%4];"
        : "=r"(f[0]), "=r"(f[1]), "=r"(f[2]), "=r"(f[3]) : "r"(addr));
}
__device__ __forceinline__ void ldm_x2(uint32_t* f, uint32_t addr) {
    asm volatile("ldmatrix.sync.aligned.m8n8.x2.shared.b16 {%0,%1}, [%2];"
        : "=r"(f[0]), "=r"(f[1]) : "r"(addr));
}
__device__ __forceinline__ void mma_f16(float* c, const uint32_t* a,
                                        uint32_t b0, uint32_t b1) {
    asm volatile(
        "mma.sync.aligned.m16n8k16.row.col.f32.f16.f16.f32 "
        "{%0,%1,%2,%3}, {%4,%5,%6,%7}, {%8,%9}, {%0,%1,%2,%3};"
        : "+f"(c[0]), "+f"(c[1]), "+f"(c[2]), "+f"(c[3])
        : "r"(a[0]), "r"(a[1]), "r"(a[2]), "r"(a[3]), "r"(b0), "r"(b1));
}
__device__ __forceinline__ uint32_t pack_h2(float a, float b) {
    __half2 h = __float22half2_rn(make_float2(a, b));
    return *reinterpret_cast<uint32_t*>(&h);
}
__device__ __forceinline__ float ex2f(float x) {
    float r; asm("ex2.approx.ftz.f32 %0, %1;" : "=f"(r) : "f"(x)); return r;
}

// ---------------------------------------------------------------------------
// Fused SMEM layout (per buffer) — W' lo region removed vs R10
// ---------------------------------------------------------------------------
#define SR_B     144u     // R tile [128 n][64 k] fp16
#define SW_B     272u     // W' tile [72 dh][128 n] fp16
#define OFF_RH   0u       // 18432 B
#define OFF_WH   18432u   // 19584 B
#define OFF_CR2  38016u   // float[128]
#define BUF_B    38528u
#define SMEM_BYTES (2u * BUF_B)    // 77056

// ---------------------------------------------------------------------------
// Prep 1: cR2, qa, fp16 R (single-rounded). warp per landmark.
// ---------------------------------------------------------------------------
__global__ void __launch_bounds__(256)
prep_land(const float* __restrict__ R, const float* __restrict__ q)
{
    int wid  = threadIdx.x >> 5, lane = threadIdx.x & 31;
    int idx  = blockIdx.x * 8 + wid;
    const float* r = R + (size_t)idx * DIM;
    float v0 = r[lane], v1 = r[lane + 32];
    g_RH[(size_t)idx * DIM + lane]      = __float2half_rn(v0);
    g_RH[(size_t)idx * DIM + lane + 32] = __float2half_rn(v1);
    float s = v0 * v0 + v1 * v1;
    #pragma unroll
    for (int m = 16; m >= 1; m >>= 1) s += __shfl_xor_sync(0xffffffffu, s, m);
    if (lane == 0) {
        g_cR2[idx] = C2EXP * s;
        float qq = q[idx];
        qq = (qq > 0.f ? qq : 0.f) + EPS_C;
        g_qa[idx] = rsqrtf(qq);
    }
}

// ---------------------------------------------------------------------------
// Prep 2: W' = [qa*W^T ; ones ; qa ; zeros] fp16 (single) [h][72][n]
// Must run AFTER prep_land (reads g_qa).
// ---------------------------------------------------------------------------
__global__ void __launch_bounds__(256)
prep_wp(const float* __restrict__ W)
{
    __shared__ float sm[64][65];
    __shared__ float sqa[64];
    int h  = blockIdx.x >> 5;
    int n0 = (blockIdx.x & 31) * 64;
    for (int t = threadIdx.x; t < 4096; t += 256) {
        int i = t >> 6, d = t & 63;
        sm[i][d] = W[((size_t)(h * NLAND + n0 + i)) * DIM + d];
    }
    if (threadIdx.x < 64) sqa[threadIdx.x] = g_qa[h * NLAND + n0 + threadIdx.x];
    __syncthreads();
    for (int t = threadIdx.x; t < 4096; t += 256) {
        int d = t >> 6, i = t & 63;
        float v = sm[i][d] * sqa[i];
        g_WPH[((size_t)h * 72 + d) * NLAND + n0 + i] = __float2half_rn(v);
    }
    for (int t = threadIdx.x; t < 64 * 8; t += 256) {
        int rr = 64 + (t >> 6), i = t & 63;
        float v = (rr == 64) ? 1.0f : (rr == 65 ? sqa[i] : 0.0f);
        g_WPH[((size_t)h * 72 + rr) * NLAND + n0 + i] = __float2half_rn(v);
    }
}

// ---------------------------------------------------------------------------
// Prep 3: W_O^T fp16 hi/lo [col][k]
// ---------------------------------------------------------------------------
__global__ void __launch_bounds__(256)
prep_wo(const float* __restrict__ WO)
{
    __shared__ float sm[64][65];
    int kb = blockIdx.x >> 3, cb = blockIdx.x & 7;
    int k0 = kb * 64, c0 = cb * 64;
    for (int t = threadIdx.x; t < 4096; t += 256) {
        int i = t >> 6, d = t & 63;
        sm[i][d] = WO[(size_t)(k0 + i) * DOUT + c0 + d];
    }
    __syncthreads();
    for (int t = threadIdx.x; t < 4096; t += 256) {
        int d = t >> 6, i = t & 63;
        float v = sm[i][d];
        __half hh = __float2half_rn(v);
        size_t o = (size_t)(c0 + d) * DOUT + k0 + i;
        g_WOH[o] = hh;
        g_WOL[o] = __float2half_rn(v - __half2float(hh));
    }
}

// ---------------------------------------------------------------------------
// Fused kernel: one CTA per (head, 128-row block), 256 threads (R4 schedule).
// ---------------------------------------------------------------------------
__device__ __forceinline__ void issue_tile_loads(char* smem, int buf, int h, int n0,
                                                 int tid)
{
    uint32_t sb = smem_u32(smem) + (uint32_t)buf * BUF_B;
    const __half* rh = g_RH + ((size_t)h * NLAND + n0) * DIM;
    #pragma unroll
    for (int i = tid; i < 1024; i += 256) {
        int row = i >> 3, u = i & 7;
        cp16(sb + OFF_RH + row * SR_B + u * 16, rh + row * DIM + u * 8);
    }
    const __half* wh = g_WPH + (size_t)h * 72 * NLAND + n0;
    for (int i = tid; i < 1152; i += 256) {
        int row = i >> 4, u = i & 15;
        cp16(sb + OFF_WH + row * SW_B + u * 16, wh + (size_t)row * NLAND + u * 8);
    }
    if (tid < 32)
        cp16(sb + OFF_CR2 + tid * 16, g_cR2 + h * NLAND + n0 + tid * 4);
}

__global__ void __launch_bounds__(256, 1)
fused_mma(const float* __restrict__ z)
{
    extern __shared__ __align__(16) char smem[];
    const int tid  = threadIdx.x;
    const int warp = tid >> 5;
    const int lane = tid & 31;
    const int h    = blockIdx.y;
    const int row0 = blockIdx.x * 128;
    const int g    = lane >> 2;
    const int t4   = lane & 3;
    const int wrow = warp * 16;
    const uint32_t sbase = smem_u32(smem);

    const int n_add = ((lane >> 4) & 1) * 8 + (lane & 7);
    const int k_add = ((lane >> 3) & 1) * 8;
    const uint32_t laneR = (uint32_t)(n_add * SR_B + k_add * 2);
    const uint32_t laneW = (uint32_t)(n_add * SW_B + k_add * 2);

    issue_tile_loads(smem, 0, h, 0, tid);
    CP_COMMIT();

    // ---- stage z fp32 into buf1 region; build fp16 A-frags (single) ----
    float* zstage = (float*)(smem + BUF_B);     // [128][68] = 34816 B < BUF_B
    {
        const float4* zsrc = reinterpret_cast<const float4*>(z);
        #pragma unroll
        for (int i = tid; i < 2048; i += 256) {
            int r = i >> 4, c4 = i & 15;
            float4 v = zsrc[(((size_t)(row0 + r) * NHEAD + h) * DIM >> 2) + c4];
            *reinterpret_cast<float4*>(zstage + r * 68 + c4 * 4) = v;
        }
    }
    __syncthreads();

    const int r0 = wrow + g, r1 = r0 + 8;
    float z2a = 0.f, z2b = 0.f;
    #pragma unroll
    for (int k = 0; k < DIM; k++) {
        float va = zstage[r0 * 68 + k];
        float vb = zstage[r1 * 68 + k];
        z2a += va * va; z2b += vb * vb;
    }
    // per-row deflation factor e^{-z^2/2} (fp32)
    const float esca = ex2f(C2EXP * z2a);
    const float escb = ex2f(C2EXP * z2b);

    uint32_t zh[4][4];
    #pragma unroll
    for (int kc = 0; kc < 4; kc++) {
        int k0 = kc * 16 + 2 * t4;
        zh[kc][0] = pack_h2(zstage[r0 * 68 + k0],     zstage[r0 * 68 + k0 + 1]);
        zh[kc][1] = pack_h2(zstage[r1 * 68 + k0],     zstage[r1 * 68 + k0 + 1]);
        zh[kc][2] = pack_h2(zstage[r0 * 68 + k0 + 8], zstage[r0 * 68 + k0 + 9]);
        zh[kc][3] = pack_h2(zstage[r1 * 68 + k0 + 8], zstage[r1 * 68 + k0 + 9]);
    }
    __syncthreads();   // buf1 free before tile-1 cp.async

    float y[8][4];     // y accumulators (64 dh)
    float yp[4];       // p-columns accumulator (cols 64-71 block)
    #pragma unroll
    for (int nt = 0; nt < 8; nt++)
        #pragma unroll
        for (int e = 0; e < 4; e++) y[nt][e] = 0.f;
    #pragma unroll
    for (int e = 0; e < 4; e++) yp[e] = 0.f;

    for (int t = 0; t < 16; t++) {
        const int cur = t & 1;
        if (t < 15) {
            issue_tile_loads(smem, cur ^ 1, h, (t + 1) * 128, tid);
            CP_COMMIT();
            CP_WAIT1();
        } else {
            CP_WAIT0();
        }
        __syncthreads();

        const uint32_t sb  = sbase + (uint32_t)cur * BUF_B;
        const uint32_t rbH = sb + OFF_RH + laneR;
        const float* crp = (const float*)(smem + cur * BUF_B + OFF_CR2);

        // ---- GEMM1: fp16 single-pass z x R ----
        float c[16][4];
        #pragma unroll
        for (int nt = 0; nt < 16; nt++)
            #pragma unroll
            for (int e = 0; e < 4; e++) c[nt][e] = 0.f;

        #pragma unroll
        for (int kc = 0; kc < 4; kc++) {
            #pragma unroll
            for (int ntp = 0; ntp < 8; ntp++) {
                uint32_t off = (uint32_t)(ntp * 16) * SR_B + (uint32_t)kc * 32;
                uint32_t rh[4];
                ldm_x4(rh, rbH + off);
                mma_f16(c[2 * ntp],     zh[kc], rh[0], rh[1]);
                mma_f16(c[2 * ntp + 1], zh[kc], rh[2], rh[3]);
            }
        }

        // ---- epilogue: K' = 2^min(s*log2e + cR2, 15); GEMM2 single pass ----
        const uint32_t wbH = sb + OFF_WH + laneW;
        #pragma unroll
        for (int kch = 0; kch < 8; kch++) {
            const int ct0 = 2 * kch, ct1 = 2 * kch + 1;
            const int col0 = ct0 * 8 + 2 * t4;
            const int col1 = ct1 * 8 + 2 * t4;
            float cr0 = crp[col0], cr1 = crp[col0 + 1];
            float cr2 = crp[col1], cr3 = crp[col1 + 1];

            float K00 = ex2f(fminf(fmaf(c[ct0][0], LOG2E, cr0), 15.f));
            float K01 = ex2f(fminf(fmaf(c[ct0][1], LOG2E, cr1), 15.f));
            float K02 = ex2f(fminf(fmaf(c[ct0][2], LOG2E, cr0), 15.f));
            float K03 = ex2f(fminf(fmaf(c[ct0][3], LOG2E, cr1), 15.f));
            float K10 = ex2f(fminf(fmaf(c[ct1][0], LOG2E, cr2), 15.f));
            float K11 = ex2f(fminf(fmaf(c[ct1][1], LOG2E, cr3), 15.f));
            float K12 = ex2f(fminf(fmaf(c[ct1][2], LOG2E, cr2), 15.f));
            float K13 = ex2f(fminf(fmaf(c[ct1][3], LOG2E, cr3), 15.f));

            uint32_t a[4];
            a[0] = pack_h2(K00, K01);
            a[1] = pack_h2(K02, K03);
            a[2] = pack_h2(K10, K11);
            a[3] = pack_h2(K12, K13);

            uint32_t kcOff = (uint32_t)kch * 32;
            uint32_t w0[4], w1[4], w2[4], w3[4], wp[2];
            ldm_x4(w0, wbH + kcOff);
            ldm_x4(w1, wbH + 16 * SW_B + kcOff);
            ldm_x4(w2, wbH + 32 * SW_B + kcOff);
            ldm_x4(w3, wbH + 48 * SW_B + kcOff);
            ldm_x2(wp, wbH + 64 * SW_B + kcOff);
            mma_f16(y[0], a, w0[0], w0[1]);
            mma_f16(y[1], a, w0[2], w0[3]);
            mma_f16(y[2], a, w1[0], w1[1]);
            mma_f16(y[3], a, w1[2], w1[3]);
            mma_f16(y[4], a, w2[0], w2[1]);
            mma_f16(y[5], a, w2[2], w2[3]);
            mma_f16(y[6], a, w3[0], w3[1]);
            mma_f16(y[7], a, w3[2], w3[3]);
            mma_f16(yp,   a, wp[0], wp[1]);
        }
        __syncthreads();
    }

    // ---- p1'/p2' live in yp of t4==0 lanes (cols 64,65); broadcast ----
    int src = lane & 28;
    float P1a = __shfl_sync(0xffffffffu, yp[0], src);
    float P2a = __shfl_sync(0xffffffffu, yp[1], src);
    float P1b = __shfl_sync(0xffffffffu, yp[2], src);
    float P2b = __shfl_sync(0xffffffffu, yp[3], src);

    // deflate to unscaled sums, replicate reference clamps exactly in fp32
    float p1a = esca * P1a, p2a = esca * P2a;
    float p1b = escb * P1b, p2b = escb * P2b;
    float cc0 = rsqrtf(fmaxf(p1a, EPS_C));
    float cc1 = rsqrtf(fmaxf(p1b, EPS_C));
    float f0  = cc0 / fmaxf(cc0 * p2a, EPS_C) * esca;   // applies to y' (scaled)
    float f1  = cc1 / fmaxf(cc1 * p2b, EPS_C) * escb;

    // ---- write y as single fp16 ----
    size_t o0 = (size_t)(row0 + r0) * DOUT + h * DIM + 2 * t4;
    size_t o1 = (size_t)(row0 + r1) * DOUT + h * DIM + 2 * t4;
    #pragma unroll
    for (int nt = 0; nt < 8; nt++) {
        *reinterpret_cast<uint32_t*>(g_Y + o0 + nt * 8) =
            pack_h2(y[nt][0] * f0, y[nt][1] * f0);
        *reinterpret_cast<uint32_t*>(g_Y + o1 + nt * 8) =
            pack_h2(y[nt][2] * f1, y[nt][3] * f1);
    }
}

// ---------------------------------------------------------------------------
// out = y @ W_O + b_O : fp16, A single, B hi/lo 2-pass. 128x128 tiles.
// ---------------------------------------------------------------------------
#define OB_STRIDE 144u
#define OB_A      0u
#define OB_BH     18432u
#define OB_BL     36864u
#define OB_BUF    55296u
#define OUT_SMEM  (2u * OB_BUF)          // 110592

__device__ __forceinline__ void issue_out_loads(char* smem, int buf, int row0,
                                                int col0, int k0, int tid)
{
    uint32_t sb = smem_u32(smem) + (uint32_t)buf * OB_BUF;
    #pragma unroll
    for (int i = tid; i < 1024; i += 256) {
        int row = i >> 3, u = i & 7;
        cp16(sb + OB_A  + row * OB_STRIDE + u * 16,
             g_Y + (size_t)(row0 + row) * DOUT + k0 + u * 8);
        size_t gb = (size_t)(col0 + row) * DOUT + k0 + u * 8;
        cp16(sb + OB_BH + row * OB_STRIDE + u * 16, g_WOH + gb);
        cp16(sb + OB_BL + row * OB_STRIDE + u * 16, g_WOL + gb);
    }
}

__global__ void __launch_bounds__(256, 1)
out_tc(const float* __restrict__ bO, float* __restrict__ out)
{
    extern __shared__ __align__(16) char smem[];
    const int tid  = threadIdx.x;
    const int warp = tid >> 5;
    const int lane = tid & 31;
    const int row0 = blockIdx.x * 128;
    const int col0 = blockIdx.y * 128;
    const int g    = lane >> 2;
    const int t4   = lane & 3;
    const int wrow = warp * 16;
    const uint32_t sbase = smem_u32(smem);

    const int n_add = ((lane >> 4) & 1) * 8 + (lane & 7);
    const int k_add = ((lane >> 3) & 1) * 8;
    const uint32_t laneO = (uint32_t)(n_add * OB_STRIDE + k_add * 2);

    issue_out_loads(smem, 0, row0, col0, 0, tid);
    CP_COMMIT();

    float y[16][4];
    #pragma unroll
    for (int nt = 0; nt < 16; nt++)
        #pragma unroll
        for (int e = 0; e < 4; e++) y[nt][e] = 0.f;

    for (int kb = 0; kb < 8; kb++) {
        const int cur = kb & 1;
        if (kb < 7) {
            issue_out_loads(smem, cur ^ 1, row0, col0, (kb + 1) * 64, tid);
            CP_COMMIT();
            CP_WAIT1();
        } else {
            CP_WAIT0();
        }
        __syncthreads();

        const uint32_t sb = sbase + (uint32_t)cur * OB_BUF;
        const uint32_t aA = sb + OB_A  + (uint32_t)wrow * OB_STRIDE + laneO;
        const uint32_t bH = sb + OB_BH + laneO;
        const uint32_t bL = sb + OB_BL + laneO;

        #pragma unroll
        for (int kc = 0; kc < 4; kc++) {
            uint32_t ta[4];
            ldm_x4(ta, aA + kc * 32);
            uint32_t a[4] = {ta[0], ta[2], ta[1], ta[3]};   // validated permute

            #pragma unroll
            for (int np = 0; np < 4; np++) {
                uint32_t oA = (uint32_t)((2 * np) * 16) * OB_STRIDE + (uint32_t)kc * 32;
                uint32_t oB = (uint32_t)((2 * np + 1) * 16) * OB_STRIDE + (uint32_t)kc * 32;
                uint32_t whA[4], wlA[4], whB[4], wlB[4];
                ldm_x4(whA, bH + oA);
                ldm_x4(wlA, bL + oA);
                ldm_x4(whB, bH + oB);
                ldm_x4(wlB, bL + oB);
                float* y0 = y[4 * np + 0];
                float* y1 = y[4 * np + 1];
                float* y2 = y[4 * np + 2];
                float* y3 = y[4 * np + 3];
                mma_f16(y0, a, whA[0], whA[1]);
                mma_f16(y1, a, whA[2], whA[3]);
                mma_f16(y2, a, whB[0], whB[1]);
                mma_f16(y3, a, whB[2], whB[3]);
                mma_f16(y0, a, wlA[0], wlA[1]);
                mma_f16(y1, a, wlA[2], wlA[3]);
                mma_f16(y2, a, wlB[0], wlB[1]);
                mma_f16(y3, a, wlB[2], wlB[3]);
            }
        }
        __syncthreads();
    }

    const int r0 = row0 + wrow + g, r1 = r0 + 8;
    #pragma unroll
    for (int nt = 0; nt < 16; nt++) {
        int col = col0 + nt * 8 + 2 * t4;
        float b0 = bO[col], b1 = bO[col + 1];
        *reinterpret_cast<float2*>(out + (size_t)r0 * DOUT + col) =
            make_float2(y[nt][0] + b0, y[nt][1] + b1);
        *reinterpret_cast<float2*>(out + (size_t)r1 * DOUT + col) =
            make_float2(y[nt][2] + b0, y[nt][3] + b1);
    }
}

// ---------------------------------------------------------------------------
extern "C" void kernel_launch(void* const* d_in, const int* in_sizes, int n_in,
                              void* d_out, int out_size)
{
    const float* z  = (const float*)d_in[0];   // (4,1024,8,64)
    const float* R  = (const float*)d_in[1];   // (8,2048,64)
    const float* q  = (const float*)d_in[2];   // (8,2048)
    const float* W  = (const float*)d_in[3];   // (8,2048,64)
    const float* WO = (const float*)d_in[4];   // (512,512)
    const float* bO = (const float*)d_in[5];   // (512)
    float* out = (float*)d_out;                // (4,1024,512)
    (void)in_sizes; (void)n_in; (void)out_size;

    cudaFuncSetAttribute(fused_mma, cudaFuncAttributeMaxDynamicSharedMemorySize,
                         SMEM_BYTES);
    cudaFuncSetAttribute(out_tc, cudaFuncAttributeMaxDynamicSharedMemorySize,
                         OUT_SMEM);

    prep_land<<<NHEAD * NLAND / 8, 256>>>(R, q);
    prep_wp<<<NHEAD * (NLAND / 64), 256>>>(W);   // after prep_land (reads g_qa)
    prep_wo<<<64, 256>>>(WO);

    dim3 gridF(BS_ROWS / 128, NHEAD);          // (32, 8)
    fused_mma<<<gridF, 256, SMEM_BYTES>>>(z);

    dim3 gridO(BS_ROWS / 128, DOUT / 128);     // (32, 4)
    out_tc<<<gridO, 256, OUT_SMEM>>>(bO, out);
}

// round 13
// speedup vs baseline: 2.6667x; 1.1569x over previous
#include <cuda_runtime.h>
#include <cuda_fp16.h>
#include <cstdint>

// ---------------------------------------------------------------------------
// Problem constants
// ---------------------------------------------------------------------------
#define BS_ROWS 4096      // B*S
#define NHEAD   8
#define DIM     64        // d == D_head
#define NLAND   2048      // landmarks per head
#define DOUT    512
#define EPS_C   1e-12f
#define C2EXP   (-0.72134752044448f)    // -0.5 * log2(e)
#define LOG2E   (1.44269504088896f)

// ---------------------------------------------------------------------------
// Device-global scratch
// K' = K * e^{+z^2/2} row-shift keeps the GEMM2 operand fp16-legal; the shift
// cancels analytically and is undone in fp32 with the reference's clamps.
// ---------------------------------------------------------------------------
__device__ float  g_cR2[NHEAD * NLAND];                 // C2EXP * ||R_n||^2
__device__ float  g_qa [NHEAD * NLAND];                 // (relu(q)+eps)^(-1/2)
__device__ __half g_RH[NHEAD * NLAND * DIM];            // R fp16 [h][n][d] (single)
__device__ __half g_WPH[NHEAD * 72 * NLAND];            // W' fp16 [h][72][n] (single)
                                                        // rows 0-63: qa*W^T; 64: 1; 65: qa; 66-71: 0
__device__ __half g_Y [BS_ROWS * DOUT];                 // y fp16 [row][col]
__device__ __half g_WOH[DOUT * DOUT];                   // W_O^T fp16 [col][k] (single)

// ---------------------------------------------------------------------------
// PTX helpers
// ---------------------------------------------------------------------------
__device__ __forceinline__ uint32_t smem_u32(const void* p) {
    return (uint32_t)__cvta_generic_to_shared(p);
}
__device__ __forceinline__ void cp16(uint32_t s, const void* g) {
    asm volatile("cp.async.cg.shared.global [%0], [%1], 16;" :: "r"(s), "l"(g));
}
#define CP_COMMIT() asm volatile("cp.async.commit_group;" ::: "memory")
#define CP_WAIT1()  asm volatile("cp.async.wait_group 1;" ::: "memory")
#define CP_WAIT0()  asm volatile("cp.async.wait_group 0;" ::: "memory")

__device__ __forceinline__ void ldm_x4(uint32_t* f, uint32_t addr) {
    asm volatile("ldmatrix.sync.aligned.m8n8.x4.shared.b16 {%0,%1,%2,%3}, [%4];"
        : "=r"(f[0]), "=r"(f[1]), "=r"(f[2]), "=r"(f[3]) : "r"(addr));
}
__device__ __forceinline__ void ldm_x2(uint32_t* f, uint32_t addr) {
    asm volatile("ldmatrix.sync.aligned.m8n8.x2.shared.b16 {%0,%1}, [%2];"
        : "=r"(f[0]), "=r"(f[1]) : "r"(addr));
}
__device__ __forceinline__ void mma_f16(float* c, const uint32_t* a,
                                        uint32_t b0, uint32_t b1) {
    asm volatile(
        "mma.sync.aligned.m16n8k16.row.col.f32.f16.f16.f32 "
        "{%0,%1,%2,%3}, {%4,%5,%6,%7}, {%8,%9}, {%0,%1,%2,%3};"
        : "+f"(c[0]), "+f"(c[1]), "+f"(c[2]), "+f"(c[3])
        : "r"(a[0]), "r"(a[1]), "r"(a[2]), "r"(a[3]), "r"(b0), "r"(b1));
}
__device__ __forceinline__ uint32_t pack_h2(float a, float b) {
    __half2 h = __float22half2_rn(make_float2(a, b));
    return *reinterpret_cast<uint32_t*>(&h);
}
__device__ __forceinline__ float ex2f(float x) {
    float r; asm("ex2.approx.ftz.f32 %0, %1;" : "=f"(r) : "f"(x)); return r;
}

// ---------------------------------------------------------------------------
// Fused SMEM layout (per buffer) — identical traffic/tiling to R11
// ---------------------------------------------------------------------------
#define SR_B     144u     // R tile [128 n][64 k] fp16
#define SW_B     272u     // W' tile [72 dh][128 n] fp16
#define OFF_RH   0u       // 18432 B
#define OFF_WH   18432u   // 19584 B
#define OFF_CR2  38016u   // float[128]
#define BUF_B    38528u
#define SMEM_BYTES (2u * BUF_B)    // 77056  (x2 CTAs = 154112 < 228KB)

// ---------------------------------------------------------------------------
// Prep 1: cR2, qa, fp16 R (single-rounded). warp per landmark.
// ---------------------------------------------------------------------------
__global__ void __launch_bounds__(256)
prep_land(const float* __restrict__ R, const float* __restrict__ q)
{
    int wid  = threadIdx.x >> 5, lane = threadIdx.x & 31;
    int idx  = blockIdx.x * 8 + wid;
    const float* r = R + (size_t)idx * DIM;
    float v0 = r[lane], v1 = r[lane + 32];
    g_RH[(size_t)idx * DIM + lane]      = __float2half_rn(v0);
    g_RH[(size_t)idx * DIM + lane + 32] = __float2half_rn(v1);
    float s = v0 * v0 + v1 * v1;
    #pragma unroll
    for (int m = 16; m >= 1; m >>= 1) s += __shfl_xor_sync(0xffffffffu, s, m);
    if (lane == 0) {
        g_cR2[idx] = C2EXP * s;
        float qq = q[idx];
        qq = (qq > 0.f ? qq : 0.f) + EPS_C;
        g_qa[idx] = rsqrtf(qq);
    }
}

// ---------------------------------------------------------------------------
// Prep 2: W' = [qa*W^T ; ones ; qa ; zeros] fp16 (single) [h][72][n]
// Must run AFTER prep_land (reads g_qa).
// ---------------------------------------------------------------------------
__global__ void __launch_bounds__(256)
prep_wp(const float* __restrict__ W)
{
    __shared__ float sm[64][65];
    __shared__ float sqa[64];
    int h  = blockIdx.x >> 5;
    int n0 = (blockIdx.x & 31) * 64;
    for (int t = threadIdx.x; t < 4096; t += 256) {
        int i = t >> 6, d = t & 63;
        sm[i][d] = W[((size_t)(h * NLAND + n0 + i)) * DIM + d];
    }
    if (threadIdx.x < 64) sqa[threadIdx.x] = g_qa[h * NLAND + n0 + threadIdx.x];
    __syncthreads();
    for (int t = threadIdx.x; t < 4096; t += 256) {
        int d = t >> 6, i = t & 63;
        float v = sm[i][d] * sqa[i];
        g_WPH[((size_t)h * 72 + d) * NLAND + n0 + i] = __float2half_rn(v);
    }
    for (int t = threadIdx.x; t < 64 * 8; t += 256) {
        int rr = 64 + (t >> 6), i = t & 63;
        float v = (rr == 64) ? 1.0f : (rr == 65 ? sqa[i] : 0.0f);
        g_WPH[((size_t)h * 72 + rr) * NLAND + n0 + i] = __float2half_rn(v);
    }
}

// ---------------------------------------------------------------------------
// Prep 3: W_O^T fp16 (single) [col][k]
// ---------------------------------------------------------------------------
__global__ void __launch_bounds__(256)
prep_wo(const float* __restrict__ WO)
{
    __shared__ float sm[64][65];
    int kb = blockIdx.x >> 3, cb = blockIdx.x & 7;
    int k0 = kb * 64, c0 = cb * 64;
    for (int t = threadIdx.x; t < 4096; t += 256) {
        int i = t >> 6, d = t & 63;
        sm[i][d] = WO[(size_t)(k0 + i) * DOUT + c0 + d];
    }
    __syncthreads();
    for (int t = threadIdx.x; t < 4096; t += 256) {
        int d = t >> 6, i = t & 63;
        g_WOH[(size_t)(c0 + d) * DOUT + k0 + i] = __float2half_rn(sm[i][d]);
    }
}

// ---------------------------------------------------------------------------
// Fused kernel: one CTA per (head, 128-row block), 256 threads, 2 CTAs/SM.
// Interleaved schedule: per 16-landmark group, GEMM1 chunk -> exp -> GEMM2
// chunk, so the GEMM1 accumulator is only 8 registers.
// ---------------------------------------------------------------------------
__device__ __forceinline__ void issue_tile_loads(char* smem, int buf, int h, int n0,
                                                 int tid)
{
    uint32_t sb = smem_u32(smem) + (uint32_t)buf * BUF_B;
    const __half* rh = g_RH + ((size_t)h * NLAND + n0) * DIM;
    #pragma unroll
    for (int i = tid; i < 1024; i += 256) {
        int row = i >> 3, u = i & 7;
        cp16(sb + OFF_RH + row * SR_B + u * 16, rh + row * DIM + u * 8);
    }
    const __half* wh = g_WPH + (size_t)h * 72 * NLAND + n0;
    for (int i = tid; i < 1152; i += 256) {
        int row = i >> 4, u = i & 15;
        cp16(sb + OFF_WH + row * SW_B + u * 16, wh + (size_t)row * NLAND + u * 8);
    }
    if (tid < 32)
        cp16(sb + OFF_CR2 + tid * 16, g_cR2 + h * NLAND + n0 + tid * 4);
}

__global__ void __launch_bounds__(256, 2)
fused_mma(const float* __restrict__ z)
{
    extern __shared__ __align__(16) char smem[];
    const int tid  = threadIdx.x;
    const int warp = tid >> 5;
    const int lane = tid & 31;
    const int h    = blockIdx.y;
    const int row0 = blockIdx.x * 128;
    const int g    = lane >> 2;
    const int t4   = lane & 3;
    const int wrow = warp * 16;
    const uint32_t sbase = smem_u32(smem);

    const int n_add = ((lane >> 4) & 1) * 8 + (lane & 7);
    const int k_add = ((lane >> 3) & 1) * 8;
    const uint32_t laneR = (uint32_t)(n_add * SR_B + k_add * 2);
    const uint32_t laneW = (uint32_t)(n_add * SW_B + k_add * 2);

    issue_tile_loads(smem, 0, h, 0, tid);
    CP_COMMIT();

    // ---- stage z fp32 into buf1 region; build fp16 A-frags (single) ----
    float* zstage = (float*)(smem + BUF_B);     // [128][68] = 34816 B < BUF_B
    {
        const float4* zsrc = reinterpret_cast<const float4*>(z);
        #pragma unroll
        for (int i = tid; i < 2048; i += 256) {
            int r = i >> 4, c4 = i & 15;
            float4 v = zsrc[(((size_t)(row0 + r) * NHEAD + h) * DIM >> 2) + c4];
            *reinterpret_cast<float4*>(zstage + r * 68 + c4 * 4) = v;
        }
    }
    __syncthreads();

    const int r0 = wrow + g, r1 = r0 + 8;
    float z2a = 0.f, z2b = 0.f;
    #pragma unroll
    for (int k = 0; k < DIM; k++) {
        float va = zstage[r0 * 68 + k];
        float vb = zstage[r1 * 68 + k];
        z2a += va * va; z2b += vb * vb;
    }
    // per-row deflation factor e^{-z^2/2} (fp32)
    const float esca = ex2f(C2EXP * z2a);
    const float escb = ex2f(C2EXP * z2b);

    uint32_t zh[4][4];
    #pragma unroll
    for (int kc = 0; kc < 4; kc++) {
        int k0 = kc * 16 + 2 * t4;
        zh[kc][0] = pack_h2(zstage[r0 * 68 + k0],     zstage[r0 * 68 + k0 + 1]);
        zh[kc][1] = pack_h2(zstage[r1 * 68 + k0],     zstage[r1 * 68 + k0 + 1]);
        zh[kc][2] = pack_h2(zstage[r0 * 68 + k0 + 8], zstage[r0 * 68 + k0 + 9]);
        zh[kc][3] = pack_h2(zstage[r1 * 68 + k0 + 8], zstage[r1 * 68 + k0 + 9]);
    }
    __syncthreads();   // buf1 free before tile-1 cp.async

    float y[8][4];     // y accumulators (64 dh)
    float yp[4];       // p-columns accumulator (cols 64-71 block)
    #pragma unroll
    for (int nt = 0; nt < 8; nt++)
        #pragma unroll
        for (int e = 0; e < 4; e++) y[nt][e] = 0.f;
    #pragma unroll
    for (int e = 0; e < 4; e++) yp[e] = 0.f;

    for (int t = 0; t < 16; t++) {
        const int cur = t & 1;
        if (t < 15) {
            issue_tile_loads(smem, cur ^ 1, h, (t + 1) * 128, tid);
            CP_COMMIT();
            CP_WAIT1();
        } else {
            CP_WAIT0();
        }
        __syncthreads();

        const uint32_t sb  = sbase + (uint32_t)cur * BUF_B;
        const uint32_t rbH = sb + OFF_RH + laneR;
        const uint32_t wbH = sb + OFF_WH + laneW;
        const float* crp = (const float*)(smem + cur * BUF_B + OFF_CR2);

        // ---- per 16-landmark group: GEMM1 chunk -> exp -> GEMM2 chunk ----
        #pragma unroll
        for (int ntp = 0; ntp < 8; ntp++) {
            float c0[4] = {0.f, 0.f, 0.f, 0.f};
            float c1[4] = {0.f, 0.f, 0.f, 0.f};
            #pragma unroll
            for (int kc = 0; kc < 4; kc++) {
                uint32_t rh[4];
                ldm_x4(rh, rbH + (uint32_t)(ntp * 16) * SR_B + (uint32_t)kc * 32);
                mma_f16(c0, zh[kc], rh[0], rh[1]);
                mma_f16(c1, zh[kc], rh[2], rh[3]);
            }

            const int col0 = (2 * ntp) * 8 + 2 * t4;
            const int col1 = col0 + 8;
            float cr0 = crp[col0], cr1 = crp[col0 + 1];
            float cr2 = crp[col1], cr3 = crp[col1 + 1];

            float K00 = ex2f(fminf(fmaf(c0[0], LOG2E, cr0), 15.f));
            float K01 = ex2f(fminf(fmaf(c0[1], LOG2E, cr1), 15.f));
            float K02 = ex2f(fminf(fmaf(c0[2], LOG2E, cr0), 15.f));
            float K03 = ex2f(fminf(fmaf(c0[3], LOG2E, cr1), 15.f));
            float K10 = ex2f(fminf(fmaf(c1[0], LOG2E, cr2), 15.f));
            float K11 = ex2f(fminf(fmaf(c1[1], LOG2E, cr3), 15.f));
            float K12 = ex2f(fminf(fmaf(c1[2], LOG2E, cr2), 15.f));
            float K13 = ex2f(fminf(fmaf(c1[3], LOG2E, cr3), 15.f));

            uint32_t a[4];
            a[0] = pack_h2(K00, K01);
            a[1] = pack_h2(K02, K03);
            a[2] = pack_h2(K10, K11);
            a[3] = pack_h2(K12, K13);

            uint32_t kcOff = (uint32_t)ntp * 32;
            uint32_t w0[4], w1[4], w2[4], w3[4], wp[2];
            ldm_x4(w0, wbH + kcOff);
            ldm_x4(w1, wbH + 16 * SW_B + kcOff);
            ldm_x4(w2, wbH + 32 * SW_B + kcOff);
            ldm_x4(w3, wbH + 48 * SW_B + kcOff);
            ldm_x2(wp, wbH + 64 * SW_B + kcOff);
            mma_f16(y[0], a, w0[0], w0[1]);
            mma_f16(y[1], a, w0[2], w0[3]);
            mma_f16(y[2], a, w1[0], w1[1]);
            mma_f16(y[3], a, w1[2], w1[3]);
            mma_f16(y[4], a, w2[0], w2[1]);
            mma_f16(y[5], a, w2[2], w2[3]);
            mma_f16(y[6], a, w3[0], w3[1]);
            mma_f16(y[7], a, w3[2], w3[3]);
            mma_f16(yp,   a, wp[0], wp[1]);
        }
        __syncthreads();
    }

    // ---- p1'/p2' live in yp of t4==0 lanes (cols 64,65); broadcast ----
    int src = lane & 28;
    float P1a = __shfl_sync(0xffffffffu, yp[0], src);
    float P2a = __shfl_sync(0xffffffffu, yp[1], src);
    float P1b = __shfl_sync(0xffffffffu, yp[2], src);
    float P2b = __shfl_sync(0xffffffffu, yp[3], src);

    // deflate to unscaled sums, replicate reference clamps exactly in fp32
    float p1a = esca * P1a, p2a = esca * P2a;
    float p1b = escb * P1b, p2b = escb * P2b;
    float cc0 = rsqrtf(fmaxf(p1a, EPS_C));
    float cc1 = rsqrtf(fmaxf(p1b, EPS_C));
    float f0  = cc0 / fmaxf(cc0 * p2a, EPS_C) * esca;   // applies to y' (scaled)
    float f1  = cc1 / fmaxf(cc1 * p2b, EPS_C) * escb;

    // ---- write y as single fp16 ----
    size_t o0 = (size_t)(row0 + r0) * DOUT + h * DIM + 2 * t4;
    size_t o1 = (size_t)(row0 + r1) * DOUT + h * DIM + 2 * t4;
    #pragma unroll
    for (int nt = 0; nt < 8; nt++) {
        *reinterpret_cast<uint32_t*>(g_Y + o0 + nt * 8) =
            pack_h2(y[nt][0] * f0, y[nt][1] * f0);
        *reinterpret_cast<uint32_t*>(g_Y + o1 + nt * 8) =
            pack_h2(y[nt][2] * f1, y[nt][3] * f1);
    }
}

// ---------------------------------------------------------------------------
// out = y @ W_O + b_O : fp16 single-pass both operands. 128x128 tiles.
// ---------------------------------------------------------------------------
#define OB_STRIDE 144u
#define OB_A      0u
#define OB_BH     18432u
#define OB_BUF    36864u
#define OUT_SMEM  (2u * OB_BUF)          // 73728

__device__ __forceinline__ void issue_out_loads(char* smem, int buf, int row0,
                                                int col0, int k0, int tid)
{
    uint32_t sb = smem_u32(smem) + (uint32_t)buf * OB_BUF;
    #pragma unroll
    for (int i = tid; i < 1024; i += 256) {
        int row = i >> 3, u = i & 7;
        cp16(sb + OB_A  + row * OB_STRIDE + u * 16,
             g_Y + (size_t)(row0 + row) * DOUT + k0 + u * 8);
        cp16(sb + OB_BH + row * OB_STRIDE + u * 16,
             g_WOH + (size_t)(col0 + row) * DOUT + k0 + u * 8);
    }
}

__global__ void __launch_bounds__(256, 1)
out_tc(const float* __restrict__ bO, float* __restrict__ out)
{
    extern __shared__ __align__(16) char smem[];
    const int tid  = threadIdx.x;
    const int warp = tid >> 5;
    const int lane = tid & 31;
    const int row0 = blockIdx.x * 128;
    const int col0 = blockIdx.y * 128;
    const int g    = lane >> 2;
    const int t4   = lane & 3;
    const int wrow = warp * 16;
    const uint32_t sbase = smem_u32(smem);

    const int n_add = ((lane >> 4) & 1) * 8 + (lane & 7);
    const int k_add = ((lane >> 3) & 1) * 8;
    const uint32_t laneO = (uint32_t)(n_add * OB_STRIDE + k_add * 2);

    issue_out_loads(smem, 0, row0, col0, 0, tid);
    CP_COMMIT();

    float y[16][4];
    #pragma unroll
    for (int nt = 0; nt < 16; nt++)
        #pragma unroll
        for (int e = 0; e < 4; e++) y[nt][e] = 0.f;

    for (int kb = 0; kb < 8; kb++) {
        const int cur = kb & 1;
        if (kb < 7) {
            issue_out_loads(smem, cur ^ 1, row0, col0, (kb + 1) * 64, tid);
            CP_COMMIT();
            CP_WAIT1();
        } else {
            CP_WAIT0();
        }
        __syncthreads();

        const uint32_t sb = sbase + (uint32_t)cur * OB_BUF;
        const uint32_t aA = sb + OB_A  + (uint32_t)wrow * OB_STRIDE + laneO;
        const uint32_t bH = sb + OB_BH + laneO;

        #pragma unroll
        for (int kc = 0; kc < 4; kc++) {
            uint32_t ta[4];
            ldm_x4(ta, aA + kc * 32);
            uint32_t a[4] = {ta[0], ta[2], ta[1], ta[3]};   // validated permute

            #pragma unroll
            for (int np = 0; np < 4; np++) {
                uint32_t oA = (uint32_t)((2 * np) * 16) * OB_STRIDE + (uint32_t)kc * 32;
                uint32_t oB = (uint32_t)((2 * np + 1) * 16) * OB_STRIDE + (uint32_t)kc * 32;
                uint32_t whA[4], whB[4];
                ldm_x4(whA, bH + oA);
                ldm_x4(whB, bH + oB);
                mma_f16(y[4 * np + 0], a, whA[0], whA[1]);
                mma_f16(y[4 * np + 1], a, whA[2], whA[3]);
                mma_f16(y[4 * np + 2], a, whB[0], whB[1]);
                mma_f16(y[4 * np + 3], a, whB[2], whB[3]);
            }
        }
        __syncthreads();
    }

    const int r0 = row0 + wrow + g, r1 = r0 + 8;
    #pragma unroll
    for (int nt = 0; nt < 16; nt++) {
        int col = col0 + nt * 8 + 2 * t4;
        float b0 = bO[col], b1 = bO[col + 1];
        *reinterpret_cast<float2*>(out + (size_t)r0 * DOUT + col) =
            make_float2(y[nt][0] + b0, y[nt][1] + b1);
        *reinterpret_cast<float2*>(out + (size_t)r1 * DOUT + col) =
            make_float2(y[nt][2] + b0, y[nt][3] + b1);
    }
}

// ---------------------------------------------------------------------------
extern "C" void kernel_launch(void* const* d_in, const int* in_sizes, int n_in,
                              void* d_out, int out_size)
{
    const float* z  = (const float*)d_in[0];   // (4,1024,8,64)
    const float* R  = (const float*)d_in[1];   // (8,2048,64)
    const float* q  = (const float*)d_in[2];   // (8,2048)
    const float* W  = (const float*)d_in[3];   // (8,2048,64)
    const float* WO = (const float*)d_in[4];   // (512,512)
    const float* bO = (const float*)d_in[5];   // (512)
    float* out = (float*)d_out;                // (4,1024,512)
    (void)in_sizes; (void)n_in; (void)out_size;

    cudaFuncSetAttribute(fused_mma, cudaFuncAttributeMaxDynamicSharedMemorySize,
                         SMEM_BYTES);
    cudaFuncSetAttribute(out_tc, cudaFuncAttributeMaxDynamicSharedMemorySize,
                         OUT_SMEM);

    prep_land<<<NHEAD * NLAND / 8, 256>>>(R, q);
    prep_wp<<<NHEAD * (NLAND / 64), 256>>>(W);   // after prep_land (reads g_qa)
    prep_wo<<<64, 256>>>(WO);

    dim3 gridF(BS_ROWS / 128, NHEAD);          // (32, 8)
    fused_mma<<<gridF, 256, SMEM_BYTES>>>(z);

    dim3 gridO(BS_ROWS / 128, DOUT / 128);     // (32, 4)
    out_tc<<<gridO, 256, OUT_SMEM>>>(bO, out);
}

// round 14
// speedup vs baseline: 2.8571x; 1.0714x over previous
#include <cuda_runtime.h>
#include <cuda_fp16.h>
#include <cstdint>

// ---------------------------------------------------------------------------
// Problem constants
// ---------------------------------------------------------------------------
#define BS_ROWS 4096      // B*S
#define NHEAD   8
#define DIM     64        // d == D_head
#define NLAND   2048      // landmarks per head
#define DOUT    512
#define EPS_C   1e-12f
#define C2EXP   (-0.72134752044448f)    // -0.5 * log2(e)
#define LOG2E   (1.44269504088896f)
#define BM      256       // rows per CTA (32 per warp)

// ---------------------------------------------------------------------------
// Device-global scratch
// K' = K * e^{+z^2/2} row-shift keeps the GEMM2 operand fp16-legal; the shift
// cancels analytically and is undone in fp32 with the reference's clamps.
// ---------------------------------------------------------------------------
__device__ float  g_cR2[NHEAD * NLAND];                 // C2EXP * ||R_n||^2
__device__ float  g_qa [NHEAD * NLAND];                 // (relu(q)+eps)^(-1/2)
__device__ __half g_RH[NHEAD * NLAND * DIM];            // R fp16 [h][n][d] (single)
__device__ __half g_WPH[NHEAD * 72 * NLAND];            // W' fp16 [h][72][n] (single)
                                                        // rows 0-63: qa*W^T; 64: 1; 65: qa; 66-71: 0
__device__ __half g_Y [BS_ROWS * DOUT];                 // y fp16 [row][col]
__device__ __half g_WOH[DOUT * DOUT];                   // W_O^T fp16 [col][k] (single)

// ---------------------------------------------------------------------------
// PTX helpers
// ---------------------------------------------------------------------------
__device__ __forceinline__ uint32_t smem_u32(const void* p) {
    return (uint32_t)__cvta_generic_to_shared(p);
}
__device__ __forceinline__ void cp16(uint32_t s, const void* g) {
    asm volatile("cp.async.cg.shared.global [%0], [%1], 16;" :: "r"(s), "l"(g));
}
#define CP_COMMIT() asm volatile("cp.async.commit_group;" ::: "memory")
#define CP_WAIT1()  asm volatile("cp.async.wait_group 1;" ::: "memory")
#define CP_WAIT0()  asm volatile("cp.async.wait_group 0;" ::: "memory")

__device__ __forceinline__ void ldm_x4(uint32_t* f, uint32_t addr) {
    asm volatile("ldmatrix.sync.aligned.m8n8.x4.shared.b16 {%0,%1,%2,%3}, [%4];"
        : "=r"(f[0]), "=r"(f[1]), "=r"(f[2]), "=r"(f[3]) : "r"(addr));
}
__device__ __forceinline__ void ldm_x2(uint32_t* f, uint32_t addr) {
    asm volatile("ldmatrix.sync.aligned.m8n8.x2.shared.b16 {%0,%1}, [%2];"
        : "=r"(f[0]), "=r"(f[1]) : "r"(addr));
}
__device__ __forceinline__ void mma_f16(float* c, const uint32_t* a,
                                        uint32_t b0, uint32_t b1) {
    asm volatile(
        "mma.sync.aligned.m16n8k16.row.col.f32.f16.f16.f32 "
        "{%0,%1,%2,%3}, {%4,%5,%6,%7}, {%8,%9}, {%0,%1,%2,%3};"
        : "+f"(c[0]), "+f"(c[1]), "+f"(c[2]), "+f"(c[3])
        : "r"(a[0]), "r"(a[1]), "r"(a[2]), "r"(a[3]), "r"(b0), "r"(b1));
}
__device__ __forceinline__ uint32_t pack_h2(float a, float b) {
    __half2 h = __float22half2_rn(make_float2(a, b));
    return *reinterpret_cast<uint32_t*>(&h);
}
__device__ __forceinline__ float ex2f(float x) {
    float r; asm("ex2.approx.ftz.f32 %0, %1;" : "=f"(r) : "f"(x)); return r;
}

// ---------------------------------------------------------------------------
// Fused SMEM layout (per buffer) — tiling identical to R11/R12
// ---------------------------------------------------------------------------
#define SR_B     144u     // R tile [128 n][64 k] fp16
#define SW_B     272u     // W' tile [72 dh][128 n] fp16
#define OFF_RH   0u       // 18432 B
#define OFF_WH   18432u   // 19584 B
#define OFF_CR2  38016u   // float[128]
#define BUF_B    38528u
#define SMEM_BYTES (2u * BUF_B)    // 77056 (zstage [256][68] f32 = 69632 fits)

// ---------------------------------------------------------------------------
// Prep 1: cR2, qa, fp16 R (single-rounded). warp per landmark.
// ---------------------------------------------------------------------------
__global__ void __launch_bounds__(256)
prep_land(const float* __restrict__ R, const float* __restrict__ q)
{
    int wid  = threadIdx.x >> 5, lane = threadIdx.x & 31;
    int idx  = blockIdx.x * 8 + wid;
    const float* r = R + (size_t)idx * DIM;
    float v0 = r[lane], v1 = r[lane + 32];
    g_RH[(size_t)idx * DIM + lane]      = __float2half_rn(v0);
    g_RH[(size_t)idx * DIM + lane + 32] = __float2half_rn(v1);
    float s = v0 * v0 + v1 * v1;
    #pragma unroll
    for (int m = 16; m >= 1; m >>= 1) s += __shfl_xor_sync(0xffffffffu, s, m);
    if (lane == 0) {
        g_cR2[idx] = C2EXP * s;
        float qq = q[idx];
        qq = (qq > 0.f ? qq : 0.f) + EPS_C;
        g_qa[idx] = rsqrtf(qq);
    }
}

// ---------------------------------------------------------------------------
// Prep 2: W' = [qa*W^T ; ones ; qa ; zeros] fp16 (single) [h][72][n]
// Must run AFTER prep_land (reads g_qa).
// ---------------------------------------------------------------------------
__global__ void __launch_bounds__(256)
prep_wp(const float* __restrict__ W)
{
    __shared__ float sm[64][65];
    __shared__ float sqa[64];
    int h  = blockIdx.x >> 5;
    int n0 = (blockIdx.x & 31) * 64;
    for (int t = threadIdx.x; t < 4096; t += 256) {
        int i = t >> 6, d = t & 63;
        sm[i][d] = W[((size_t)(h * NLAND + n0 + i)) * DIM + d];
    }
    if (threadIdx.x < 64) sqa[threadIdx.x] = g_qa[h * NLAND + n0 + threadIdx.x];
    __syncthreads();
    for (int t = threadIdx.x; t < 4096; t += 256) {
        int d = t >> 6, i = t & 63;
        float v = sm[i][d] * sqa[i];
        g_WPH[((size_t)h * 72 + d) * NLAND + n0 + i] = __float2half_rn(v);
    }
    for (int t = threadIdx.x; t < 64 * 8; t += 256) {
        int rr = 64 + (t >> 6), i = t & 63;
        float v = (rr == 64) ? 1.0f : (rr == 65 ? sqa[i] : 0.0f);
        g_WPH[((size_t)h * 72 + rr) * NLAND + n0 + i] = __float2half_rn(v);
    }
}

// ---------------------------------------------------------------------------
// Prep 3: W_O^T fp16 (single) [col][k]
// ---------------------------------------------------------------------------
__global__ void __launch_bounds__(256)
prep_wo(const float* __restrict__ WO)
{
    __shared__ float sm[64][65];
    int kb = blockIdx.x >> 3, cb = blockIdx.x & 7;
    int k0 = kb * 64, c0 = cb * 64;
    for (int t = threadIdx.x; t < 4096; t += 256) {
        int i = t >> 6, d = t & 63;
        sm[i][d] = WO[(size_t)(k0 + i) * DOUT + c0 + d];
    }
    __syncthreads();
    for (int t = threadIdx.x; t < 4096; t += 256) {
        int d = t >> 6, i = t & 63;
        g_WOH[(size_t)(c0 + d) * DOUT + k0 + i] = __float2half_rn(sm[i][d]);
    }
}

// ---------------------------------------------------------------------------
// Fused kernel: one CTA per (head, 256-row block), 256 threads, 32 rows/warp.
// Each B-fragment (ldmatrix) now feeds TWO 16-row A groups -> ldm/HMMA halved.
// ---------------------------------------------------------------------------
__device__ __forceinline__ void issue_tile_loads(char* smem, int buf, int h, int n0,
                                                 int tid)
{
    uint32_t sb = smem_u32(smem) + (uint32_t)buf * BUF_B;
    const __half* rh = g_RH + ((size_t)h * NLAND + n0) * DIM;
    #pragma unroll
    for (int i = tid; i < 1024; i += 256) {
        int row = i >> 3, u = i & 7;
        cp16(sb + OFF_RH + row * SR_B + u * 16, rh + row * DIM + u * 8);
    }
    const __half* wh = g_WPH + (size_t)h * 72 * NLAND + n0;
    for (int i = tid; i < 1152; i += 256) {
        int row = i >> 4, u = i & 15;
        cp16(sb + OFF_WH + row * SW_B + u * 16, wh + (size_t)row * NLAND + u * 8);
    }
    if (tid < 32)
        cp16(sb + OFF_CR2 + tid * 16, g_cR2 + h * NLAND + n0 + tid * 4);
}

__global__ void __launch_bounds__(256, 1)
fused_mma(const float* __restrict__ z)
{
    extern __shared__ __align__(16) char smem[];
    const int tid  = threadIdx.x;
    const int warp = tid >> 5;
    const int lane = tid & 31;
    const int h    = blockIdx.y;
    const int row0 = blockIdx.x * BM;
    const int g    = lane >> 2;
    const int t4   = lane & 3;
    const int wrow = warp * 32;
    const uint32_t sbase = smem_u32(smem);

    const int n_add = ((lane >> 4) & 1) * 8 + (lane & 7);
    const int k_add = ((lane >> 3) & 1) * 8;
    const uint32_t laneR = (uint32_t)(n_add * SR_B + k_add * 2);
    const uint32_t laneW = (uint32_t)(n_add * SW_B + k_add * 2);

    // ---- stage z fp32 into smem FIRST (uses both tile buffers transiently) ----
    float* zstage = (float*)smem;               // [256][68] = 69632 B
    {
        const float4* zsrc = reinterpret_cast<const float4*>(z);
        #pragma unroll
        for (int i = tid; i < BM * 16; i += 256) {
            int r = i >> 4, c4 = i & 15;
            float4 v = zsrc[(((size_t)(row0 + r) * NHEAD + h) * DIM >> 2) + c4];
            *reinterpret_cast<float4*>(zstage + r * 68 + c4 * 4) = v;
        }
    }
    __syncthreads();

    // this thread's 4 rows (two 16-row A groups)
    const int ra0 = wrow + g, ra1 = ra0 + 8;
    const int rb0 = wrow + 16 + g, rb1 = rb0 + 8;

    float z2[4] = {0.f, 0.f, 0.f, 0.f};
    #pragma unroll
    for (int k = 0; k < DIM; k++) {
        float v0 = zstage[ra0 * 68 + k];
        float v1 = zstage[ra1 * 68 + k];
        float v2 = zstage[rb0 * 68 + k];
        float v3 = zstage[rb1 * 68 + k];
        z2[0] += v0 * v0; z2[1] += v1 * v1;
        z2[2] += v2 * v2; z2[3] += v3 * v3;
    }
    float esc[4];
    #pragma unroll
    for (int e = 0; e < 4; e++) esc[e] = ex2f(C2EXP * z2[e]);

    uint32_t zh[4][8];
    #pragma unroll
    for (int kc = 0; kc < 4; kc++) {
        int k0 = kc * 16 + 2 * t4;
        zh[kc][0] = pack_h2(zstage[ra0 * 68 + k0],     zstage[ra0 * 68 + k0 + 1]);
        zh[kc][1] = pack_h2(zstage[ra1 * 68 + k0],     zstage[ra1 * 68 + k0 + 1]);
        zh[kc][2] = pack_h2(zstage[ra0 * 68 + k0 + 8], zstage[ra0 * 68 + k0 + 9]);
        zh[kc][3] = pack_h2(zstage[ra1 * 68 + k0 + 8], zstage[ra1 * 68 + k0 + 9]);
        zh[kc][4] = pack_h2(zstage[rb0 * 68 + k0],     zstage[rb0 * 68 + k0 + 1]);
        zh[kc][5] = pack_h2(zstage[rb1 * 68 + k0],     zstage[rb1 * 68 + k0 + 1]);
        zh[kc][6] = pack_h2(zstage[rb0 * 68 + k0 + 8], zstage[rb0 * 68 + k0 + 9]);
        zh[kc][7] = pack_h2(zstage[rb1 * 68 + k0 + 8], zstage[rb1 * 68 + k0 + 9]);
    }
    __syncthreads();   // zstage region free -> start cp.async pipeline

    issue_tile_loads(smem, 0, h, 0, tid);
    CP_COMMIT();

    float y[16][4];    // y: [0..7] group A rows, [8..15] group B rows
    float yp0[4], yp1[4];
    #pragma unroll
    for (int nt = 0; nt < 16; nt++)
        #pragma unroll
        for (int e = 0; e < 4; e++) y[nt][e] = 0.f;
    #pragma unroll
    for (int e = 0; e < 4; e++) { yp0[e] = 0.f; yp1[e] = 0.f; }

    for (int t = 0; t < 16; t++) {
        const int cur = t & 1;
        if (t < 15) {
            issue_tile_loads(smem, cur ^ 1, h, (t + 1) * 128, tid);
            CP_COMMIT();
            CP_WAIT1();
        } else {
            CP_WAIT0();
        }
        __syncthreads();

        const uint32_t sb  = sbase + (uint32_t)cur * BUF_B;
        const uint32_t rbH = sb + OFF_RH + laneR;
        const uint32_t wbH = sb + OFF_WH + laneW;
        const float* crp = (const float*)(smem + cur * BUF_B + OFF_CR2);

        // ---- per 16-landmark group: GEMM1 chunk -> exp -> GEMM2 chunk ----
        #pragma unroll
        for (int ntp = 0; ntp < 8; ntp++) {
            float cA0[4] = {0.f, 0.f, 0.f, 0.f};
            float cA1[4] = {0.f, 0.f, 0.f, 0.f};
            float cB0[4] = {0.f, 0.f, 0.f, 0.f};
            float cB1[4] = {0.f, 0.f, 0.f, 0.f};
            #pragma unroll
            for (int kc = 0; kc < 4; kc++) {
                uint32_t rh[4];
                ldm_x4(rh, rbH + (uint32_t)(ntp * 16) * SR_B + (uint32_t)kc * 32);
                mma_f16(cA0, &zh[kc][0], rh[0], rh[1]);
                mma_f16(cA1, &zh[kc][0], rh[2], rh[3]);
                mma_f16(cB0, &zh[kc][4], rh[0], rh[1]);
                mma_f16(cB1, &zh[kc][4], rh[2], rh[3]);
            }

            const int col0 = (2 * ntp) * 8 + 2 * t4;
            const int col1 = col0 + 8;
            float cr0 = crp[col0], cr1 = crp[col0 + 1];
            float cr2 = crp[col1], cr3 = crp[col1 + 1];

            uint32_t a0[4], a1[4];
            a0[0] = pack_h2(ex2f(fminf(fmaf(cA0[0], LOG2E, cr0), 15.f)),
                            ex2f(fminf(fmaf(cA0[1], LOG2E, cr1), 15.f)));
            a0[1] = pack_h2(ex2f(fminf(fmaf(cA0[2], LOG2E, cr0), 15.f)),
                            ex2f(fminf(fmaf(cA0[3], LOG2E, cr1), 15.f)));
            a0[2] = pack_h2(ex2f(fminf(fmaf(cA1[0], LOG2E, cr2), 15.f)),
                            ex2f(fminf(fmaf(cA1[1], LOG2E, cr3), 15.f)));
            a0[3] = pack_h2(ex2f(fminf(fmaf(cA1[2], LOG2E, cr2), 15.f)),
                            ex2f(fminf(fmaf(cA1[3], LOG2E, cr3), 15.f)));
            a1[0] = pack_h2(ex2f(fminf(fmaf(cB0[0], LOG2E, cr0), 15.f)),
                            ex2f(fminf(fmaf(cB0[1], LOG2E, cr1), 15.f)));
            a1[1] = pack_h2(ex2f(fminf(fmaf(cB0[2], LOG2E, cr0), 15.f)),
                            ex2f(fminf(fmaf(cB0[3], LOG2E, cr1), 15.f)));
            a1[2] = pack_h2(ex2f(fminf(fmaf(cB1[0], LOG2E, cr2), 15.f)),
                            ex2f(fminf(fmaf(cB1[1], LOG2E, cr3), 15.f)));
            a1[3] = pack_h2(ex2f(fminf(fmaf(cB1[2], LOG2E, cr2), 15.f)),
                            ex2f(fminf(fmaf(cB1[3], LOG2E, cr3), 15.f)));

            uint32_t kcOff = (uint32_t)ntp * 32;
            uint32_t w0[4], w1[4], w2[4], w3[4], wp[2];
            ldm_x4(w0, wbH + kcOff);
            ldm_x4(w1, wbH + 16 * SW_B + kcOff);
            ldm_x4(w2, wbH + 32 * SW_B + kcOff);
            ldm_x4(w3, wbH + 48 * SW_B + kcOff);
            ldm_x2(wp, wbH + 64 * SW_B + kcOff);
            // group A
            mma_f16(y[0], a0, w0[0], w0[1]);
            mma_f16(y[1], a0, w0[2], w0[3]);
            mma_f16(y[2], a0, w1[0], w1[1]);
            mma_f16(y[3], a0, w1[2], w1[3]);
            mma_f16(y[4], a0, w2[0], w2[1]);
            mma_f16(y[5], a0, w2[2], w2[3]);
            mma_f16(y[6], a0, w3[0], w3[1]);
            mma_f16(y[7], a0, w3[2], w3[3]);
            mma_f16(yp0,  a0, wp[0], wp[1]);
            // group B
            mma_f16(y[8],  a1, w0[0], w0[1]);
            mma_f16(y[9],  a1, w0[2], w0[3]);
            mma_f16(y[10], a1, w1[0], w1[1]);
            mma_f16(y[11], a1, w1[2], w1[3]);
            mma_f16(y[12], a1, w2[0], w2[1]);
            mma_f16(y[13], a1, w2[2], w2[3]);
            mma_f16(y[14], a1, w3[0], w3[1]);
            mma_f16(y[15], a1, w3[2], w3[3]);
            mma_f16(yp1,  a1, wp[0], wp[1]);
        }
        __syncthreads();
    }

    // ---- p1'/p2' live in yp of t4==0 lanes (cols 64,65); broadcast ----
    int src = lane & 28;
    float P1[4], P2[4];
    P1[0] = __shfl_sync(0xffffffffu, yp0[0], src);
    P2[0] = __shfl_sync(0xffffffffu, yp0[1], src);
    P1[1] = __shfl_sync(0xffffffffu, yp0[2], src);
    P2[1] = __shfl_sync(0xffffffffu, yp0[3], src);
    P1[2] = __shfl_sync(0xffffffffu, yp1[0], src);
    P2[2] = __shfl_sync(0xffffffffu, yp1[1], src);
    P1[3] = __shfl_sync(0xffffffffu, yp1[2], src);
    P2[3] = __shfl_sync(0xffffffffu, yp1[3], src);

    float f[4];
    #pragma unroll
    for (int e = 0; e < 4; e++) {
        float p1 = esc[e] * P1[e], p2 = esc[e] * P2[e];
        float cc = rsqrtf(fmaxf(p1, EPS_C));
        f[e] = cc / fmaxf(cc * p2, EPS_C) * esc[e];
    }

    // ---- write y as single fp16 (4 rows) ----
    const int rows[4] = {ra0, ra1, rb0, rb1};
    #pragma unroll
    for (int e = 0; e < 4; e++) {
        size_t o = (size_t)(row0 + rows[e]) * DOUT + h * DIM + 2 * t4;
        int base = (e >> 1) * 8;              // 0 for group A, 8 for group B
        int lohi = e & 1;                     // 0 -> elems 0,1 ; 1 -> elems 2,3
        #pragma unroll
        for (int nt = 0; nt < 8; nt++) {
            *reinterpret_cast<uint32_t*>(g_Y + o + nt * 8) =
                pack_h2(y[base + nt][2 * lohi] * f[e],
                        y[base + nt][2 * lohi + 1] * f[e]);
        }
    }
}

// ---------------------------------------------------------------------------
// out = y @ W_O + b_O : fp16 single-pass both operands. 128x128 tiles.
// ---------------------------------------------------------------------------
#define OB_STRIDE 144u
#define OB_A      0u
#define OB_BH     18432u
#define OB_BUF    36864u
#define OUT_SMEM  (2u * OB_BUF)          // 73728

__device__ __forceinline__ void issue_out_loads(char* smem, int buf, int row0,
                                                int col0, int k0, int tid)
{
    uint32_t sb = smem_u32(smem) + (uint32_t)buf * OB_BUF;
    #pragma unroll
    for (int i = tid; i < 1024; i += 256) {
        int row = i >> 3, u = i & 7;
        cp16(sb + OB_A  + row * OB_STRIDE + u * 16,
             g_Y + (size_t)(row0 + row) * DOUT + k0 + u * 8);
        cp16(sb + OB_BH + row * OB_STRIDE + u * 16,
             g_WOH + (size_t)(col0 + row) * DOUT + k0 + u * 8);
    }
}

__global__ void __launch_bounds__(256, 1)
out_tc(const float* __restrict__ bO, float* __restrict__ out)
{
    extern __shared__ __align__(16) char smem[];
    const int tid  = threadIdx.x;
    const int warp = tid >> 5;
    const int lane = tid & 31;
    const int row0 = blockIdx.x * 128;
    const int col0 = blockIdx.y * 128;
    const int g    = lane >> 2;
    const int t4   = lane & 3;
    const int wrow = warp * 16;
    const uint32_t sbase = smem_u32(smem);

    const int n_add = ((lane >> 4) & 1) * 8 + (lane & 7);
    const int k_add = ((lane >> 3) & 1) * 8;
    const uint32_t laneO = (uint32_t)(n_add * OB_STRIDE + k_add * 2);

    issue_out_loads(smem, 0, row0, col0, 0, tid);
    CP_COMMIT();

    float y[16][4];
    #pragma unroll
    for (int nt = 0; nt < 16; nt++)
        #pragma unroll
        for (int e = 0; e < 4; e++) y[nt][e] = 0.f;

    for (int kb = 0; kb < 8; kb++) {
        const int cur = kb & 1;
        if (kb < 7) {
            issue_out_loads(smem, cur ^ 1, row0, col0, (kb + 1) * 64, tid);
            CP_COMMIT();
            CP_WAIT1();
        } else {
            CP_WAIT0();
        }
        __syncthreads();

        const uint32_t sb = sbase + (uint32_t)cur * OB_BUF;
        const uint32_t aA = sb + OB_A  + (uint32_t)wrow * OB_STRIDE + laneO;
        const uint32_t bH = sb + OB_BH + laneO;

        #pragma unroll
        for (int kc = 0; kc < 4; kc++) {
            uint32_t ta[4];
            ldm_x4(ta, aA + kc * 32);
            uint32_t a[4] = {ta[0], ta[2], ta[1], ta[3]};   // validated permute

            #pragma unroll
            for (int np = 0; np < 4; np++) {
                uint32_t oA = (uint32_t)((2 * np) * 16) * OB_STRIDE + (uint32_t)kc * 32;
                uint32_t oB = (uint32_t)((2 * np + 1) * 16) * OB_STRIDE + (uint32_t)kc * 32;
                uint32_t whA[4], whB[4];
                ldm_x4(whA, bH + oA);
                ldm_x4(whB, bH + oB);
                mma_f16(y[4 * np + 0], a, whA[0], whA[1]);
                mma_f16(y[4 * np + 1], a, whA[2], whA[3]);
                mma_f16(y[4 * np + 2], a, whB[0], whB[1]);
                mma_f16(y[4 * np + 3], a, whB[2], whB[3]);
            }
        }
        __syncthreads();
    }

    const int r0 = row0 + wrow + g, r1 = r0 + 8;
    #pragma unroll
    for (int nt = 0; nt < 16; nt++) {
        int col = col0 + nt * 8 + 2 * t4;
        float b0 = bO[col], b1 = bO[col + 1];
        *reinterpret_cast<float2*>(out + (size_t)r0 * DOUT + col) =
            make_float2(y[nt][0] + b0, y[nt][1] + b1);
        *reinterpret_cast<float2*>(out + (size_t)r1 * DOUT + col) =
            make_float2(y[nt][2] + b0, y[nt][3] + b1);
    }
}

// ---------------------------------------------------------------------------
extern "C" void kernel_launch(void* const* d_in, const int* in_sizes, int n_in,
                              void* d_out, int out_size)
{
    const float* z  = (const float*)d_in[0];   // (4,1024,8,64)
    const float* R  = (const float*)d_in[1];   // (8,2048,64)
    const float* q  = (const float*)d_in[2];   // (8,2048)
    const float* W  = (const float*)d_in[3];   // (8,2048,64)
    const float* WO = (const float*)d_in[4];   // (512,512)
    const float* bO = (const float*)d_in[5];   // (512)
    float* out = (float*)d_out;                // (4,1024,512)
    (void)in_sizes; (void)n_in; (void)out_size;

    cudaFuncSetAttribute(fused_mma, cudaFuncAttributeMaxDynamicSharedMemorySize,
                         SMEM_BYTES);
    cudaFuncSetAttribute(out_tc, cudaFuncAttributeMaxDynamicSharedMemorySize,
                         OUT_SMEM);

    prep_land<<<NHEAD * NLAND / 8, 256>>>(R, q);
    prep_wp<<<NHEAD * (NLAND / 64), 256>>>(W);   // after prep_land (reads g_qa)
    prep_wo<<<64, 256>>>(WO);

    dim3 gridF(BS_ROWS / BM, NHEAD);           // (16, 8) = 128 CTAs, one wave
    fused_mma<<<gridF, 256, SMEM_BYTES>>>(z);

    dim3 gridO(BS_ROWS / 128, DOUT / 128);     // (32, 4)
    out_tc<<<gridO, 256, OUT_SMEM>>>(bO, out);
}

// round 15
// speedup vs baseline: 3.0000x; 1.0500x over previous
#include <cuda_runtime.h>
#include <cuda_fp16.h>
#include <cstdint>

// ---------------------------------------------------------------------------
// Problem constants
// ---------------------------------------------------------------------------
#define BS_ROWS 4096      // B*S
#define NHEAD   8
#define DIM     64        // d == D_head
#define NLAND   2048      // landmarks per head
#define DOUT    512
#define EPS_C   1e-12f
#define C2EXP   (-0.72134752044448f)    // -0.5 * log2(e)
#define LOG2E   (1.44269504088896f)
#define BM      256       // rows per CTA (32 per warp)
#define NCTAS   128       // fused grid size (16 x 8) -- all resident (<=148 SMs)

// ---------------------------------------------------------------------------
// Device-global scratch
// ---------------------------------------------------------------------------
__device__ float  g_cR2[NHEAD * NLAND];                 // C2EXP * ||R_n||^2
__device__ __half g_RH[NHEAD * NLAND * DIM];            // R fp16 [h][n][d] (single)
__device__ __half g_WPH[NHEAD * 72 * NLAND];            // W' fp16 [h][72][n] (single)
                                                        // rows 0-63: qa*W^T; 64: 1; 65: qa; 66-71: 0
__device__ __half g_Y [BS_ROWS * DOUT];                 // y fp16 [row][col]
__device__ __half g_WOH[DOUT * DOUT];                   // W_O^T fp16 [col][k] (single)
__device__ int    g_bar;                                // device barrier (reset by prep)

// ---------------------------------------------------------------------------
// PTX helpers
// ---------------------------------------------------------------------------
__device__ __forceinline__ uint32_t smem_u32(const void* p) {
    return (uint32_t)__cvta_generic_to_shared(p);
}
__device__ __forceinline__ void cp16(uint32_t s, const void* g) {
    asm volatile("cp.async.cg.shared.global [%0], [%1], 16;" :: "r"(s), "l"(g));
}
#define CP_COMMIT() asm volatile("cp.async.commit_group;" ::: "memory")
#define CP_WAIT1()  asm volatile("cp.async.wait_group 1;" ::: "memory")
#define CP_WAIT0()  asm volatile("cp.async.wait_group 0;" ::: "memory")

__device__ __forceinline__ void ldm_x4(uint32_t* f, uint32_t addr) {
    asm volatile("ldmatrix.sync.aligned.m8n8.x4.shared.b16 {%0,%1,%2,%3}, [%4];"
        : "=r"(f[0]), "=r"(f[1]), "=r"(f[2]), "=r"(f[3]) : "r"(addr));
}
__device__ __forceinline__ void ldm_x2(uint32_t* f, uint32_t addr) {
    asm volatile("ldmatrix.sync.aligned.m8n8.x2.shared.b16 {%0,%1}, [%2];"
        : "=r"(f[0]), "=r"(f[1]) : "r"(addr));
}
__device__ __forceinline__ void mma_f16(float* c, const uint32_t* a,
                                        uint32_t b0, uint32_t b1) {
    asm volatile(
        "mma.sync.aligned.m16n8k16.row.col.f32.f16.f16.f32 "
        "{%0,%1,%2,%3}, {%4,%5,%6,%7}, {%8,%9}, {%0,%1,%2,%3};"
        : "+f"(c[0]), "+f"(c[1]), "+f"(c[2]), "+f"(c[3])
        : "r"(a[0]), "r"(a[1]), "r"(a[2]), "r"(a[3]), "r"(b0), "r"(b1));
}
__device__ __forceinline__ uint32_t pack_h2(float a, float b) {
    __half2 h = __float22half2_rn(make_float2(a, b));
    return *reinterpret_cast<uint32_t*>(&h);
}
__device__ __forceinline__ float ex2f(float x) {
    float r; asm("ex2.approx.ftz.f32 %0, %1;" : "=f"(r) : "f"(x)); return r;
}

// ---------------------------------------------------------------------------
// Fused SMEM layout (per buffer)
// ---------------------------------------------------------------------------
#define SR_B     144u     // R tile [128 n][64 k] fp16
#define SW_B     272u     // W' tile [72 dh][128 n] fp16
#define OFF_RH   0u       // 18432 B
#define OFF_WH   18432u   // 19584 B
#define OFF_CR2  38016u   // float[128]
#define BUF_B    38528u
#define SMEM_BYTES (2u * BUF_B)    // 77056 (zstage [256][68] f32 = 69632 fits)

// out-phase SMEM layout (reuses the same dynamic smem; 73728 <= 77056)
#define OB_STRIDE 144u
#define OB_A      0u
#define OB_BH     18432u
#define OB_BUF    36864u

// ---------------------------------------------------------------------------
// Unified prep kernel. Block ranges:
//   [0, 2048)        : cR2 + fp16 R split (warp per landmark)
//   [2048, 2304)     : W' build (qa computed inline from q)
//   [2304, 2368)     : W_O^T fp16
// Block 0 also resets the device barrier for this graph replay.
// ---------------------------------------------------------------------------
__global__ void __launch_bounds__(256)
prep_all(const float* __restrict__ R, const float* __restrict__ q,
         const float* __restrict__ W, const float* __restrict__ WO)
{
    const int bid = blockIdx.x;
    if (bid == 0 && threadIdx.x == 0) g_bar = 0;

    if (bid < 2048) {
        int wid  = threadIdx.x >> 5, lane = threadIdx.x & 31;
        int idx  = bid * 8 + wid;
        const float* r = R + (size_t)idx * DIM;
        float v0 = r[lane], v1 = r[lane + 32];
        g_RH[(size_t)idx * DIM + lane]      = __float2half_rn(v0);
        g_RH[(size_t)idx * DIM + lane + 32] = __float2half_rn(v1);
        float s = v0 * v0 + v1 * v1;
        #pragma unroll
        for (int m = 16; m >= 1; m >>= 1) s += __shfl_xor_sync(0xffffffffu, s, m);
        if (lane == 0) g_cR2[idx] = C2EXP * s;
    } else if (bid < 2304) {
        __shared__ float sm[64][65];
        __shared__ float sqa[64];
        int b2 = bid - 2048;
        int h  = b2 >> 5;
        int n0 = (b2 & 31) * 64;
        for (int t = threadIdx.x; t < 4096; t += 256) {
            int i = t >> 6, d = t & 63;
            sm[i][d] = W[((size_t)(h * NLAND + n0 + i)) * DIM + d];
        }
        if (threadIdx.x < 64) {
            float qq = q[h * NLAND + n0 + threadIdx.x];
            qq = (qq > 0.f ? qq : 0.f) + EPS_C;
            sqa[threadIdx.x] = rsqrtf(qq);
        }
        __syncthreads();
        for (int t = threadIdx.x; t < 4096; t += 256) {
            int d = t >> 6, i = t & 63;
            float v = sm[i][d] * sqa[i];
            g_WPH[((size_t)h * 72 + d) * NLAND + n0 + i] = __float2half_rn(v);
        }
        for (int t = threadIdx.x; t < 64 * 8; t += 256) {
            int rr = 64 + (t >> 6), i = t & 63;
            float v = (rr == 64) ? 1.0f : (rr == 65 ? sqa[i] : 0.0f);
            g_WPH[((size_t)h * 72 + rr) * NLAND + n0 + i] = __float2half_rn(v);
        }
    } else {
        __shared__ float sm[64][65];
        int b3 = bid - 2304;
        int kb = b3 >> 3, cb = b3 & 7;
        int k0 = kb * 64, c0 = cb * 64;
        for (int t = threadIdx.x; t < 4096; t += 256) {
            int i = t >> 6, d = t & 63;
            sm[i][d] = WO[(size_t)(k0 + i) * DOUT + c0 + d];
        }
        __syncthreads();
        for (int t = threadIdx.x; t < 4096; t += 256) {
            int d = t >> 6, i = t & 63;
            g_WOH[(size_t)(c0 + d) * DOUT + k0 + i] = __float2half_rn(sm[i][d]);
        }
    }
}

// ---------------------------------------------------------------------------
// Fused kernel: phase 1 = landmark attention (R13 exact), device barrier,
// phase 2 = out = y @ W_O + b_O  (ex-out_tc, remapped onto the same grid).
// ---------------------------------------------------------------------------
__device__ __forceinline__ void issue_tile_loads(char* smem, int buf, int h, int n0,
                                                 int tid)
{
    uint32_t sb = smem_u32(smem) + (uint32_t)buf * BUF_B;
    const __half* rh = g_RH + ((size_t)h * NLAND + n0) * DIM;
    #pragma unroll
    for (int i = tid; i < 1024; i += 256) {
        int row = i >> 3, u = i & 7;
        cp16(sb + OFF_RH + row * SR_B + u * 16, rh + row * DIM + u * 8);
    }
    const __half* wh = g_WPH + (size_t)h * 72 * NLAND + n0;
    for (int i = tid; i < 1152; i += 256) {
        int row = i >> 4, u = i & 15;
        cp16(sb + OFF_WH + row * SW_B + u * 16, wh + (size_t)row * NLAND + u * 8);
    }
    if (tid < 32)
        cp16(sb + OFF_CR2 + tid * 16, g_cR2 + h * NLAND + n0 + tid * 4);
}

__device__ __forceinline__ void issue_out_loads(char* smem, int buf, int row0,
                                                int col0, int k0, int tid)
{
    uint32_t sb = smem_u32(smem) + (uint32_t)buf * OB_BUF;
    #pragma unroll
    for (int i = tid; i < 1024; i += 256) {
        int row = i >> 3, u = i & 7;
        cp16(sb + OB_A  + row * OB_STRIDE + u * 16,
             g_Y + (size_t)(row0 + row) * DOUT + k0 + u * 8);
        cp16(sb + OB_BH + row * OB_STRIDE + u * 16,
             g_WOH + (size_t)(col0 + row) * DOUT + k0 + u * 8);
    }
}

__global__ void __launch_bounds__(256, 1)
fused_mma(const float* __restrict__ z, const float* __restrict__ bO,
          float* __restrict__ out)
{
    extern __shared__ __align__(16) char smem[];
    const int tid  = threadIdx.x;
    const int warp = tid >> 5;
    const int lane = tid & 31;
    const int h    = blockIdx.y;
    const int row0 = blockIdx.x * BM;
    const int g    = lane >> 2;
    const int t4   = lane & 3;
    const int wrow = warp * 32;
    const uint32_t sbase = smem_u32(smem);

    const int n_add = ((lane >> 4) & 1) * 8 + (lane & 7);
    const int k_add = ((lane >> 3) & 1) * 8;
    const uint32_t laneR = (uint32_t)(n_add * SR_B + k_add * 2);
    const uint32_t laneW = (uint32_t)(n_add * SW_B + k_add * 2);

    // ---- stage z fp32 into smem FIRST (uses both tile buffers transiently) ----
    float* zstage = (float*)smem;               // [256][68] = 69632 B
    {
        const float4* zsrc = reinterpret_cast<const float4*>(z);
        #pragma unroll
        for (int i = tid; i < BM * 16; i += 256) {
            int r = i >> 4, c4 = i & 15;
            float4 v = zsrc[(((size_t)(row0 + r) * NHEAD + h) * DIM >> 2) + c4];
            *reinterpret_cast<float4*>(zstage + r * 68 + c4 * 4) = v;
        }
    }
    __syncthreads();

    // this thread's 4 rows (two 16-row A groups)
    const int ra0 = wrow + g, ra1 = ra0 + 8;
    const int rb0 = wrow + 16 + g, rb1 = rb0 + 8;

    float z2[4] = {0.f, 0.f, 0.f, 0.f};
    #pragma unroll
    for (int k = 0; k < DIM; k++) {
        float v0 = zstage[ra0 * 68 + k];
        float v1 = zstage[ra1 * 68 + k];
        float v2 = zstage[rb0 * 68 + k];
        float v3 = zstage[rb1 * 68 + k];
        z2[0] += v0 * v0; z2[1] += v1 * v1;
        z2[2] += v2 * v2; z2[3] += v3 * v3;
    }
    float esc[4];
    #pragma unroll
    for (int e = 0; e < 4; e++) esc[e] = ex2f(C2EXP * z2[e]);

    uint32_t zh[4][8];
    #pragma unroll
    for (int kc = 0; kc < 4; kc++) {
        int k0 = kc * 16 + 2 * t4;
        zh[kc][0] = pack_h2(zstage[ra0 * 68 + k0],     zstage[ra0 * 68 + k0 + 1]);
        zh[kc][1] = pack_h2(zstage[ra1 * 68 + k0],     zstage[ra1 * 68 + k0 + 1]);
        zh[kc][2] = pack_h2(zstage[ra0 * 68 + k0 + 8], zstage[ra0 * 68 + k0 + 9]);
        zh[kc][3] = pack_h2(zstage[ra1 * 68 + k0 + 8], zstage[ra1 * 68 + k0 + 9]);
        zh[kc][4] = pack_h2(zstage[rb0 * 68 + k0],     zstage[rb0 * 68 + k0 + 1]);
        zh[kc][5] = pack_h2(zstage[rb1 * 68 + k0],     zstage[rb1 * 68 + k0 + 1]);
        zh[kc][6] = pack_h2(zstage[rb0 * 68 + k0 + 8], zstage[rb0 * 68 + k0 + 9]);
        zh[kc][7] = pack_h2(zstage[rb1 * 68 + k0 + 8], zstage[rb1 * 68 + k0 + 9]);
    }
    __syncthreads();   // zstage region free -> start cp.async pipeline

    issue_tile_loads(smem, 0, h, 0, tid);
    CP_COMMIT();

    float y[16][4];    // y: [0..7] group A rows, [8..15] group B rows
    float yp0[4], yp1[4];
    #pragma unroll
    for (int nt = 0; nt < 16; nt++)
        #pragma unroll
        for (int e = 0; e < 4; e++) y[nt][e] = 0.f;
    #pragma unroll
    for (int e = 0; e < 4; e++) { yp0[e] = 0.f; yp1[e] = 0.f; }

    for (int t = 0; t < 16; t++) {
        const int cur = t & 1;
        if (t < 15) {
            issue_tile_loads(smem, cur ^ 1, h, (t + 1) * 128, tid);
            CP_COMMIT();
            CP_WAIT1();
        } else {
            CP_WAIT0();
        }
        __syncthreads();

        const uint32_t sb  = sbase + (uint32_t)cur * BUF_B;
        const uint32_t rbH = sb + OFF_RH + laneR;
        const uint32_t wbH = sb + OFF_WH + laneW;
        const float* crp = (const float*)(smem + cur * BUF_B + OFF_CR2);

        // ---- per 16-landmark group: GEMM1 chunk -> exp -> GEMM2 chunk ----
        #pragma unroll
        for (int ntp = 0; ntp < 8; ntp++) {
            float cA0[4] = {0.f, 0.f, 0.f, 0.f};
            float cA1[4] = {0.f, 0.f, 0.f, 0.f};
            float cB0[4] = {0.f, 0.f, 0.f, 0.f};
            float cB1[4] = {0.f, 0.f, 0.f, 0.f};
            #pragma unroll
            for (int kc = 0; kc < 4; kc++) {
                uint32_t rh[4];
                ldm_x4(rh, rbH + (uint32_t)(ntp * 16) * SR_B + (uint32_t)kc * 32);
                mma_f16(cA0, &zh[kc][0], rh[0], rh[1]);
                mma_f16(cA1, &zh[kc][0], rh[2], rh[3]);
                mma_f16(cB0, &zh[kc][4], rh[0], rh[1]);
                mma_f16(cB1, &zh[kc][4], rh[2], rh[3]);
            }

            const int col0 = (2 * ntp) * 8 + 2 * t4;
            const int col1 = col0 + 8;
            float cr0 = crp[col0], cr1 = crp[col0 + 1];
            float cr2 = crp[col1], cr3 = crp[col1 + 1];

            uint32_t a0[4], a1[4];
            a0[0] = pack_h2(ex2f(fminf(fmaf(cA0[0], LOG2E, cr0), 15.f)),
                            ex2f(fminf(fmaf(cA0[1], LOG2E, cr1), 15.f)));
            a0[1] = pack_h2(ex2f(fminf(fmaf(cA0[2], LOG2E, cr0), 15.f)),
                            ex2f(fminf(fmaf(cA0[3], LOG2E, cr1), 15.f)));
            a0[2] = pack_h2(ex2f(fminf(fmaf(cA1[0], LOG2E, cr2), 15.f)),
                            ex2f(fminf(fmaf(cA1[1], LOG2E, cr3), 15.f)));
            a0[3] = pack_h2(ex2f(fminf(fmaf(cA1[2], LOG2E, cr2), 15.f)),
                            ex2f(fminf(fmaf(cA1[3], LOG2E, cr3), 15.f)));
            a1[0] = pack_h2(ex2f(fminf(fmaf(cB0[0], LOG2E, cr0), 15.f)),
                            ex2f(fminf(fmaf(cB0[1], LOG2E, cr1), 15.f)));
            a1[1] = pack_h2(ex2f(fminf(fmaf(cB0[2], LOG2E, cr0), 15.f)),
                            ex2f(fminf(fmaf(cB0[3], LOG2E, cr1), 15.f)));
            a1[2] = pack_h2(ex2f(fminf(fmaf(cB1[0], LOG2E, cr2), 15.f)),
                            ex2f(fminf(fmaf(cB1[1], LOG2E, cr3), 15.f)));
            a1[3] = pack_h2(ex2f(fminf(fmaf(cB1[2], LOG2E, cr2), 15.f)),
                            ex2f(fminf(fmaf(cB1[3], LOG2E, cr3), 15.f)));

            uint32_t kcOff = (uint32_t)ntp * 32;
            uint32_t w0[4], w1[4], w2[4], w3[4], wp[2];
            ldm_x4(w0, wbH + kcOff);
            ldm_x4(w1, wbH + 16 * SW_B + kcOff);
            ldm_x4(w2, wbH + 32 * SW_B + kcOff);
            ldm_x4(w3, wbH + 48 * SW_B + kcOff);
            ldm_x2(wp, wbH + 64 * SW_B + kcOff);
            // group A
            mma_f16(y[0], a0, w0[0], w0[1]);
            mma_f16(y[1], a0, w0[2], w0[3]);
            mma_f16(y[2], a0, w1[0], w1[1]);
            mma_f16(y[3], a0, w1[2], w1[3]);
            mma_f16(y[4], a0, w2[0], w2[1]);
            mma_f16(y[5], a0, w2[2], w2[3]);
            mma_f16(y[6], a0, w3[0], w3[1]);
            mma_f16(y[7], a0, w3[2], w3[3]);
            mma_f16(yp0,  a0, wp[0], wp[1]);
            // group B
            mma_f16(y[8],  a1, w0[0], w0[1]);
            mma_f16(y[9],  a1, w0[2], w0[3]);
            mma_f16(y[10], a1, w1[0], w1[1]);
            mma_f16(y[11], a1, w1[2], w1[3]);
            mma_f16(y[12], a1, w2[0], w2[1]);
            mma_f16(y[13], a1, w2[2], w2[3]);
            mma_f16(y[14], a1, w3[0], w3[1]);
            mma_f16(y[15], a1, w3[2], w3[3]);
            mma_f16(yp1,  a1, wp[0], wp[1]);
        }
        __syncthreads();
    }

    // ---- p1'/p2' live in yp of t4==0 lanes (cols 64,65); broadcast ----
    int src = lane & 28;
    float P1[4], P2[4];
    P1[0] = __shfl_sync(0xffffffffu, yp0[0], src);
    P2[0] = __shfl_sync(0xffffffffu, yp0[1], src);
    P1[1] = __shfl_sync(0xffffffffu, yp0[2], src);
    P2[1] = __shfl_sync(0xffffffffu, yp0[3], src);
    P1[2] = __shfl_sync(0xffffffffu, yp1[0], src);
    P2[2] = __shfl_sync(0xffffffffu, yp1[1], src);
    P1[3] = __shfl_sync(0xffffffffu, yp1[2], src);
    P2[3] = __shfl_sync(0xffffffffu, yp1[3], src);

    float f[4];
    #pragma unroll
    for (int e = 0; e < 4; e++) {
        float p1 = esc[e] * P1[e], p2 = esc[e] * P2[e];
        float cc = rsqrtf(fmaxf(p1, EPS_C));
        f[e] = cc / fmaxf(cc * p2, EPS_C) * esc[e];
    }

    // ---- write y as single fp16 (4 rows) ----
    const int rows[4] = {ra0, ra1, rb0, rb1};
    #pragma unroll
    for (int e = 0; e < 4; e++) {
        size_t o = (size_t)(row0 + rows[e]) * DOUT + h * DIM + 2 * t4;
        int base = (e >> 1) * 8;              // 0 for group A, 8 for group B
        int lohi = e & 1;                     // 0 -> elems 0,1 ; 1 -> elems 2,3
        #pragma unroll
        for (int nt = 0; nt < 8; nt++) {
            *reinterpret_cast<uint32_t*>(g_Y + o + nt * 8) =
                pack_h2(y[base + nt][2 * lohi] * f[e],
                        y[base + nt][2 * lohi + 1] * f[e]);
        }
    }

    // =======================================================================
    // Device-wide barrier: all 128 CTAs resident (grid 128 <= 148 SMs).
    // g_bar was reset to 0 by prep_all earlier in this graph replay.
    // =======================================================================
    __threadfence();
    __syncthreads();
    if (tid == 0) {
        atomicAdd(&g_bar, 1);
        while (atomicAdd(&g_bar, 0) < NCTAS) __nanosleep(64);
    }
    __syncthreads();

    // =======================================================================
    // Phase 2: out = y @ W_O + b_O. Remap grid (16,8) -> (row32, col4) tiles.
    // =======================================================================
    const int id    = blockIdx.x * 8 + blockIdx.y;   // 0..127
    const int row0o = (id >> 2) * 128;
    const int col0o = (id & 3) * 128;
    const int wrow2 = warp * 16;
    const uint32_t laneO = (uint32_t)(n_add * OB_STRIDE + k_add * 2);

    issue_out_loads(smem, 0, row0o, col0o, 0, tid);
    CP_COMMIT();

    float yo[16][4];
    #pragma unroll
    for (int nt = 0; nt < 16; nt++)
        #pragma unroll
        for (int e = 0; e < 4; e++) yo[nt][e] = 0.f;

    for (int kb = 0; kb < 8; kb++) {
        const int cur = kb & 1;
        if (kb < 7) {
            issue_out_loads(smem, cur ^ 1, row0o, col0o, (kb + 1) * 64, tid);
            CP_COMMIT();
            CP_WAIT1();
        } else {
            CP_WAIT0();
        }
        __syncthreads();

        const uint32_t sb = sbase + (uint32_t)cur * OB_BUF;
        const uint32_t aA = sb + OB_A  + (uint32_t)wrow2 * OB_STRIDE + laneO;
        const uint32_t bH = sb + OB_BH + laneO;

        #pragma unroll
        for (int kc = 0; kc < 4; kc++) {
            uint32_t ta[4];
            ldm_x4(ta, aA + kc * 32);
            uint32_t a[4] = {ta[0], ta[2], ta[1], ta[3]};   // validated permute

            #pragma unroll
            for (int np = 0; np < 4; np++) {
                uint32_t oA = (uint32_t)((2 * np) * 16) * OB_STRIDE + (uint32_t)kc * 32;
                uint32_t oB = (uint32_t)((2 * np + 1) * 16) * OB_STRIDE + (uint32_t)kc * 32;
                uint32_t whA[4], whB[4];
                ldm_x4(whA, bH + oA);
                ldm_x4(whB, bH + oB);
                mma_f16(yo[4 * np + 0], a, whA[0], whA[1]);
                mma_f16(yo[4 * np + 1], a, whA[2], whA[3]);
                mma_f16(yo[4 * np + 2], a, whB[0], whB[1]);
                mma_f16(yo[4 * np + 3], a, whB[2], whB[3]);
            }
        }
        __syncthreads();
    }

    const int r0o = row0o + wrow2 + g, r1o = r0o + 8;
    #pragma unroll
    for (int nt = 0; nt < 16; nt++) {
        int col = col0o + nt * 8 + 2 * t4;
        float b0 = bO[col], b1 = bO[col + 1];
        *reinterpret_cast<float2*>(out + (size_t)r0o * DOUT + col) =
            make_float2(yo[nt][0] + b0, yo[nt][1] + b1);
        *reinterpret_cast<float2*>(out + (size_t)r1o * DOUT + col) =
            make_float2(yo[nt][2] + b0, yo[nt][3] + b1);
    }
}

// ---------------------------------------------------------------------------
extern "C" void kernel_launch(void* const* d_in, const int* in_sizes, int n_in,
                              void* d_out, int out_size)
{
    const float* z  = (const float*)d_in[0];   // (4,1024,8,64)
    const float* R  = (const float*)d_in[1];   // (8,2048,64)
    const float* q  = (const float*)d_in[2];   // (8,2048)
    const float* W  = (const float*)d_in[3];   // (8,2048,64)
    const float* WO = (const float*)d_in[4];   // (512,512)
    const float* bO = (const float*)d_in[5];   // (512)
    float* out = (float*)d_out;                // (4,1024,512)
    (void)in_sizes; (void)n_in; (void)out_size;

    cudaFuncSetAttribute(fused_mma, cudaFuncAttributeMaxDynamicSharedMemorySize,
                         SMEM_BYTES);

    prep_all<<<2368, 256>>>(R, q, W, WO);      // also resets g_bar

    dim3 gridF(BS_ROWS / BM, NHEAD);           // (16, 8) = 128 CTAs, one wave
    fused_mma<<<gridF, 256, SMEM_BYTES>>>(z, bO, out);
}